// round 6
// baseline (speedup 1.0000x reference)
#include <cuda_runtime.h>
#include <cuda_bf16.h>
#include <math.h>
#include <stdint.h>

#define BATCH 2
#define SEQ 1024
#define FEAT 80
#define DMODEL 512
#define DSTATE 16
#define DCONV 7
#define HEADDIM 64
#define DINNER 1024
#define NHEADS 16
#define CONVDIM 1056
#define DINPROJ 2096
#define NTOK (BATCH*SEQ)
#define EPSF 1e-5f
#define KPI 128
#define CH 16            // scan chunks
#define CL 64            // steps per chunk

// ---------------- scratch ----------------
__device__ float g_h[NTOK*DMODEL];
__device__ float g_zx[2][NTOK*DINPROJ];
__device__ float g_xbc[2][NTOK*CONVDIM];
__device__ float g_dt[2][NTOK*NHEADS];
__device__ float g_dA[2][NTOK*NHEADS];
__device__ float g_y[2][NTOK*DINNER];
__device__ float g_hfin[NTOK*DMODEL];

__device__ float g_S[2*2*16*CH*64*16];
__device__ float g_Hc[2*2*16*CH*64*16];
__device__ float g_cA[2][NTOK*NHEADS];

__device__ __nv_bfloat16 g_hnh[NTOK*DMODEL],  g_hnl[NTOK*DMODEL];
__device__ __nv_bfloat16 g_xh[NTOK*KPI],      g_xl[NTOK*KPI];
__device__ __nv_bfloat16 g_ych[NTOK*2*DINNER],g_ycl[NTOK*2*DINNER];   // concat [tok][dir*1024+i]
__device__ __nv_bfloat16 g_hfh[NTOK*DMODEL],  g_hfl[NTOK*DMODEL];

__device__ __nv_bfloat16 g_winh[4L*DMODEL*DINPROJ], g_winl[4L*DMODEL*DINPROJ];
__device__ __nv_bfloat16 g_wouth[4L*DINNER*DMODEL], g_woutl[4L*DINNER*DMODEL];
__device__ __nv_bfloat16 g_wpih[KPI*DMODEL],        g_wpil[KPI*DMODEL];
__device__ __nv_bfloat16 g_wpoh[DMODEL*FEAT],       g_wpol[DMODEL*FEAT];

// ---------------- helpers ----------------
__device__ __forceinline__ void cvt_hl(float v, __nv_bfloat16& h, __nv_bfloat16& l) {
    h = __float2bfloat16_rn(v);
    l = __float2bfloat16_rn(v - __bfloat162float(h));
}
__device__ __forceinline__ uint32_t smem_u32(const void* p) {
    uint32_t a;
    asm("{ .reg .u64 t; cvta.to.shared.u64 t, %1; cvt.u32.u64 %0, t; }" : "=r"(a) : "l"(p));
    return a;
}
__device__ __forceinline__ void cpa16(uint32_t dst, const void* src) {
    asm volatile("cp.async.cg.shared.global [%0], [%1], 16;" :: "r"(dst), "l"(src));
}
__device__ __forceinline__ void ldsm_x4(unsigned r[4], uint32_t addr) {
    asm volatile("ldmatrix.sync.aligned.m8n8.x4.shared.b16 {%0,%1,%2,%3}, [%4];"
        : "=r"(r[0]), "=r"(r[1]), "=r"(r[2]), "=r"(r[3]) : "r"(addr));
}
__device__ __forceinline__ void ldsm_x2t(unsigned r[2], uint32_t addr) {
    asm volatile("ldmatrix.sync.aligned.m8n8.x2.trans.shared.b16 {%0,%1}, [%2];"
        : "=r"(r[0]), "=r"(r[1]) : "r"(addr));
}
__device__ __forceinline__ void mma16816(float d[4], const unsigned a[4], const unsigned b[2]) {
    asm volatile("mma.sync.aligned.m16n8k16.row.col.f32.bf16.bf16.f32 "
        "{%0,%1,%2,%3}, {%4,%5,%6,%7}, {%8,%9}, {%0,%1,%2,%3};"
        : "+f"(d[0]), "+f"(d[1]), "+f"(d[2]), "+f"(d[3])
        : "r"(a[0]), "r"(a[1]), "r"(a[2]), "r"(a[3]), "r"(b[0]), "r"(b[1]));
}

// ---------------- GEMM template (BN = 128 or 64) ----------------
// C[M,N](+)= A[M,K]@B[K,N] (+bias), bf16 hi/lo 3-pass. BM=128, BK=32, 256 thr.
#define ASTR 80
#define OFF_AL 10240
#define OFF_BH 20480

template<int BN>
__device__ __forceinline__ void g5_stage(
    uint32_t sb, const __nv_bfloat16* Ah, const __nv_bfloat16* Al,
    const __nv_bfloat16* Bh, const __nv_bfloat16* Bl,
    int m0, int n0, int k0, int N, int K, int tid)
{
    constexpr int BSTR = BN*2 + 16;
    constexpr int BBLK = 32*BSTR;
    constexpr int SEGS = BN/8;
    #pragma unroll
    for (int q = 0; q < 2; q++) {
        int idx = q * 256 + tid, row = idx >> 2, seg = idx & 3;
        uint32_t d = sb + row * ASTR + seg * 16;
        const __nv_bfloat16* s = Ah + (size_t)(m0 + row) * K + k0 + seg * 8;
        cpa16(d, s);
        cpa16(d + OFF_AL, Al + (s - Ah));
    }
    #pragma unroll
    for (int q = 0; q < (32*SEGS)/256; q++) {
        int idx = q * 256 + tid, row = idx / SEGS, seg = idx % SEGS;
        uint32_t d = sb + OFF_BH + row * BSTR + seg * 16;
        if (n0 + seg * 8 < N) {
            const __nv_bfloat16* s = Bh + (size_t)(k0 + row) * N + n0 + seg * 8;
            cpa16(d, s);
            cpa16(d + BBLK, Bl + (s - Bh));
        } else {
            asm volatile("st.shared.v4.b32 [%0], {%1,%1,%1,%1};" :: "r"(d), "r"(0) : "memory");
            asm volatile("st.shared.v4.b32 [%0], {%1,%1,%1,%1};" :: "r"(d + BBLK), "r"(0) : "memory");
        }
    }
    asm volatile("cp.async.commit_group;" ::: "memory");
}

template<bool ACCUM, bool BIAS, int BN>
__global__ void __launch_bounds__(256) gemm5(
    const __nv_bfloat16* __restrict__ Ah, const __nv_bfloat16* __restrict__ Al,
    const __nv_bfloat16* __restrict__ Bh, const __nv_bfloat16* __restrict__ Bl,
    const float* __restrict__ bias, float* __restrict__ C,
    int N, int K, long az, long bz, long cz)
{
    constexpr int BSTR = BN*2 + 16;
    constexpr int BBLK = 32*BSTR;
    constexpr int STAGE = OFF_BH + 2*BBLK;
    constexpr int NW_M = (BN == 128) ? 2 : 4;     // warps along M
    constexpr int FW = 8 / NW_M;                  // 16-row frags per warp

    extern __shared__ char dsm[];
    Ah += (long)blockIdx.z * az;  Al += (long)blockIdx.z * az;
    Bh += (long)blockIdx.z * bz;  Bl += (long)blockIdx.z * bz;
    C  += (long)blockIdx.z * cz;
    const int m0 = blockIdx.y * 128, n0 = blockIdx.x * BN;
    const int tid = threadIdx.x, warp = tid >> 5, lane = tid & 31;
    const int wm = (warp % NW_M) * (FW * 16);
    const int wn = (warp / NW_M) * 32;
    const uint32_t raw = smem_u32(dsm);

    float acc[FW][4][4];
    #pragma unroll
    for (int f = 0; f < FW; f++)
        #pragma unroll
        for (int g = 0; g < 4; g++)
            #pragma unroll
            for (int i = 0; i < 4; i++) acc[f][g][i] = 0.f;

    const int nch = K >> 5;
    g5_stage<BN>(raw, Ah, Al, Bh, Bl, m0, n0, 0, N, K, tid);

    for (int c = 0; c < nch; c++) {
        if (c + 1 < nch) {
            g5_stage<BN>(raw + (uint32_t)((c + 1) & 1) * STAGE,
                         Ah, Al, Bh, Bl, m0, n0, (c + 1) << 5, N, K, tid);
            asm volatile("cp.async.wait_group 1;" ::: "memory");
        } else {
            asm volatile("cp.async.wait_group 0;" ::: "memory");
        }
        __syncthreads();

        const uint32_t sb = raw + (uint32_t)(c & 1) * STAGE;
        #pragma unroll
        for (int ks = 0; ks < 2; ks++) {
            const int kk = ks * 16;
            unsigned ah[FW][4], al[FW][4], bh[4][2], bl[4][2];
            #pragma unroll
            for (int f = 0; f < FW; f++) {
                int row = wm + f * 16 + (lane & 15);
                int col = kk + ((lane >> 4) << 3);
                uint32_t a = sb + row * ASTR + col * 2;
                ldsm_x4(ah[f], a);
                ldsm_x4(al[f], a + OFF_AL);
            }
            #pragma unroll
            for (int g = 0; g < 4; g++) {
                int row = kk + (lane & 15);
                int col = wn + g * 8;
                uint32_t a = sb + OFF_BH + row * BSTR + col * 2;
                ldsm_x2t(bh[g], a);
                ldsm_x2t(bl[g], a + BBLK);
            }
            #pragma unroll
            for (int f = 0; f < FW; f++)
                #pragma unroll
                for (int g = 0; g < 4; g++) {
                    mma16816(acc[f][g], ah[f], bh[g]);
                    mma16816(acc[f][g], al[f], bh[g]);
                    mma16816(acc[f][g], ah[f], bl[g]);
                }
        }
        __syncthreads();
    }

    const int cr = lane >> 2, cc = (lane & 3) * 2;
    #pragma unroll
    for (int f = 0; f < FW; f++) {
        #pragma unroll
        for (int g = 0; g < 4; g++) {
            int mmb = m0 + wm + f * 16 + cr;
            int nn = n0 + wn + g * 8 + cc;
            #pragma unroll
            for (int half = 0; half < 2; half++) {
                int m = mmb + half * 8;
                #pragma unroll
                for (int j = 0; j < 2; j++) {
                    if (nn + j < N) {
                        float v = acc[f][g][half * 2 + j];
                        long o = (long)m * N + nn + j;
                        if (BIAS) v += bias[nn + j];
                        if (ACCUM) v += C[o];
                        C[o] = v;
                    }
                }
            }
        }
    }
}

#define GS128 (2*(OFF_BH + 2*(32*(128*2+16))))
#define GS64  (2*(OFF_BH + 2*(32*(64*2+16))))

// ---------------- weight convert: W[K][N] -> bf16 hi/lo, K padded ----------
__global__ void __launch_bounds__(256) cvt_w_k(
    const float* __restrict__ W, __nv_bfloat16* __restrict__ Wh,
    __nv_bfloat16* __restrict__ Wl, int K, int N, int Kpad, long wz, long oz)
{
    long idx = (long)blockIdx.x * 256 + threadIdx.x;
    if (idx >= (long)Kpad * N) return;
    W  += (long)blockIdx.z * wz;
    Wh += (long)blockIdx.z * oz;
    Wl += (long)blockIdx.z * oz;
    int k = (int)(idx / N);
    int n = (int)(idx - (long)k * N);
    float v = (k < K) ? W[(long)k * N + n] : 0.f;
    __nv_bfloat16 h, l;
    cvt_hl(v, h, l);
    Wh[idx] = h; Wl[idx] = l;
}

// ---------------- x -> bf16 hi/lo, K padded 80->128 ----------------
__global__ void __launch_bounds__(256) cvt_x_k(const float* __restrict__ x)
{
    int idx = blockIdx.x * 256 + threadIdx.x;
    if (idx >= NTOK * KPI) return;
    int mrow = idx >> 7, c = idx & (KPI - 1);
    float v = (c < FEAT) ? x[mrow * FEAT + c] : 0.f;
    __nv_bfloat16 h, l;
    cvt_hl(v, h, l);
    g_xh[idx] = h; g_xl[idx] = l;
}

// ---------------- reductions ----------------
__device__ __forceinline__ float warpSum(float v) {
    #pragma unroll
    for (int o = 16; o; o >>= 1) v += __shfl_down_sync(0xffffffffu, v, o);
    return v;
}

// ---------------- layernorm (512) -> bf16 hi/lo (+opt fp32) ----------------
__global__ void __launch_bounds__(256) layernorm_hl_k(
    const float* __restrict__ in, const float* __restrict__ w,
    const float* __restrict__ b, __nv_bfloat16* __restrict__ oh,
    __nv_bfloat16* __restrict__ ol, float* __restrict__ of)
{
    __shared__ float sbuf[8];
    int row = blockIdx.x, tid = threadIdx.x;
    const float* v = in + (long)row * DMODEL;
    float x0 = v[tid], x1 = v[tid + 256];
    float s = warpSum(x0 + x1);
    if ((tid & 31) == 0) sbuf[tid >> 5] = s;
    __syncthreads();
    float mean = 0.f;
    #pragma unroll
    for (int i = 0; i < 8; i++) mean += sbuf[i];
    mean *= (1.f / DMODEL);
    __syncthreads();
    float c0 = x0 - mean, c1 = x1 - mean;
    float ss = warpSum(c0 * c0 + c1 * c1);
    if ((tid & 31) == 0) sbuf[tid >> 5] = ss;
    __syncthreads();
    float var = 0.f;
    #pragma unroll
    for (int i = 0; i < 8; i++) var += sbuf[i];
    var *= (1.f / DMODEL);
    float rs = rsqrtf(var + EPSF);
    float r0 = c0 * rs * w[tid] + b[tid];
    float r1 = c1 * rs * w[tid + 256] + b[tid + 256];
    __nv_bfloat16 h, l;
    long o0 = (long)row * DMODEL + tid, o1 = o0 + 256;
    cvt_hl(r0, h, l); oh[o0] = h; ol[o0] = l;
    cvt_hl(r1, h, l); oh[o1] = h; ol[o1] = l;
    if (of) { of[o0] = r0; of[o1] = r1; }
}

// ---------------- sliding-window causal conv + SiLU ----------------
// grid: (9 chan-groups, SEQ/64 seq-tiles, 4 = dir*2+b); 128 threads (channel)
__global__ void __launch_bounds__(128) conv2_k(
    const float* __restrict__ convw, const float* __restrict__ convb, int l)
{
    int c = blockIdx.x * 128 + threadIdx.x;
    bool act = (c < CONVDIM);
    int t0 = blockIdx.y * 64;
    int dir = blockIdx.z >> 1;
    int b = blockIdx.z & 1;
    float w[7], bias = 0.f;
    #pragma unroll
    for (int k = 0; k < 7; k++) w[k] = 0.f;
    if (act) {
        const float* wp = convw + ((long)((l * 2 + dir) * CONVDIM) + c) * DCONV;
        #pragma unroll
        for (int k = 0; k < 7; k++) w[k] = wp[k];
        bias = convb[(l * 2 + dir) * CONVDIM + c];
    }
    const float* in = g_zx[dir] + (long)b * SEQ * DINPROJ + DINNER + c;
    float* outp = g_xbc[dir] + (long)b * SEQ * CONVDIM + c;

    float win[7];
    if (dir == 0) {
        // win[j] = in[o-j]; out[o] = bias + sum_j w[6-j]*win[j]
        #pragma unroll
        for (int j = 1; j < 7; j++) {
            int t = t0 - j;
            win[j] = (act && t >= 0) ? in[(long)t * DINPROJ] : 0.f;
        }
        #pragma unroll 4
        for (int i = 0; i < 64; i++) {
            int o = t0 + i;
            win[0] = act ? in[(long)o * DINPROJ] : 0.f;
            float a = bias;
            #pragma unroll
            for (int j = 0; j < 7; j++) a += w[6 - j] * win[j];
            float sv = a / (1.f + expf(-a));
            if (act) outp[(long)o * CONVDIM] = sv;
            #pragma unroll
            for (int j = 6; j > 0; j--) win[j] = win[j - 1];
        }
    } else {
        // win[j] = in[o+j]; out[o] = bias + sum_j w[6-j]*win[j]
        #pragma unroll
        for (int j = 0; j < 6; j++) {
            int t = t0 + j;
            win[j] = (act && t < SEQ) ? in[(long)t * DINPROJ] : 0.f;
        }
        #pragma unroll 4
        for (int i = 0; i < 64; i++) {
            int o = t0 + i;
            int t = o + 6;
            win[6] = (act && t < SEQ) ? in[(long)t * DINPROJ] : 0.f;
            float a = bias;
            #pragma unroll
            for (int j = 0; j < 7; j++) a += w[6 - j] * win[j];
            float sv = a / (1.f + expf(-a));
            if (act) outp[(long)o * CONVDIM] = sv;
            #pragma unroll
            for (int j = 0; j < 6; j++) win[j] = win[j + 1];
        }
    }
}

// ---------------- dt/dA precompute ----------------
__global__ void __launch_bounds__(256) dtprep_k(
    const float* __restrict__ dt_bias, const float* __restrict__ A_log, int l)
{
    int idx = blockIdx.x * 256 + threadIdx.x;
    if (idx >= 2 * NTOK * NHEADS) return;
    int dir = idx / (NTOK * NHEADS);
    int r = idx - dir * (NTOK * NHEADS);
    int h = r & 15;
    int tok = r >> 4;
    float raw = g_zx[dir][(long)tok * DINPROJ + DINNER + CONVDIM + h];
    float xv = raw + dt_bias[(l * 2 + dir) * NHEADS + h];
    float dt = (xv > 20.f) ? xv : log1pf(expf(xv));
    float Av = -expf(A_log[(l * 2 + dir) * NHEADS + h]);
    g_dt[dir][r] = dt;
    g_dA[dir][r] = expf(dt * Av);
}

// ---------------- scan phase A: chunk-local scan (h0=0) --------------------
__global__ void __launch_bounds__(64) scanA_k(const float* __restrict__ Dp, int l)
{
    int bid = blockIdx.x;
    int chunk = bid & 15;
    int h = (bid >> 4) & 15;
    int b = (bid >> 8) & 1;
    int dir = bid >> 9;
    int p = threadIdx.x;
    const float* xbc = g_xbc[dir];
    const float* dtp = g_dt[dir];
    const float* dAp = g_dA[dir];
    float* yo = g_y[dir];
    float* cAo = g_cA[dir];
    const float Dv = Dp[(l * 2 + dir) * NHEADS + h];
    float hs[16];
    #pragma unroll
    for (int n = 0; n < 16; n++) hs[n] = 0.f;
    float cumA = 1.f;
    __shared__ float sB[8][16], sC[8][16], sdt[8], sdA[8];

    for (int t8 = 0; t8 < CL; t8 += 8) {
        int tb = chunk * CL + t8;
        #pragma unroll
        for (int i = p; i < 128; i += 64) {
            int tt = i >> 4, n = i & 15;
            int o = dir ? (SEQ - 1 - (tb + tt)) : (tb + tt);
            long base = (long)(b * SEQ + o) * CONVDIM + DINNER;
            sB[tt][n] = xbc[base + n];
            sC[tt][n] = xbc[base + DSTATE + n];
        }
        if (p < 8) {
            int o = dir ? (SEQ - 1 - (tb + p)) : (tb + p);
            sdt[p] = dtp[(long)(b * SEQ + o) * NHEADS + h];
            sdA[p] = dAp[(long)(b * SEQ + o) * NHEADS + h];
        }
        __syncthreads();

        float xt[8];
        int oidx[8];
        #pragma unroll
        for (int j = 0; j < 8; j++) {
            int o = dir ? (SEQ - 1 - (tb + j)) : (tb + j);
            oidx[j] = o;
            xt[j] = xbc[(long)(b * SEQ + o) * CONVDIM + h * HEADDIM + p];
        }
        #pragma unroll
        for (int j = 0; j < 8; j++) {
            float dt = sdt[j], dA = sdA[j];
            float cdt = dt * xt[j];
            float y = 0.f;
            #pragma unroll
            for (int n = 0; n < 16; n++) {
                hs[n] = hs[n] * dA + cdt * sB[j][n];
                y += hs[n] * sC[j][n];
            }
            y += Dv * xt[j];
            yo[(long)(b * SEQ + oidx[j]) * DINNER + h * HEADDIM + p] = y;  // pre-gate
            cumA *= dA;
            if (p == 0) cAo[((long)(b * SEQ) + tb + j) * NHEADS + h] = cumA;
        }
        __syncthreads();
    }
    long sbase = ((((long)(dir * 2 + b) * 16 + h) * CH + chunk) * 64 + p) * 16;
    #pragma unroll
    for (int n = 0; n < 16; n++) g_S[sbase + n] = hs[n];
}

// ---------------- scan phase B: sequential chunk combine -------------------
__global__ void __launch_bounds__(64) scanB_k()
{
    int bid = blockIdx.x;
    int h = bid & 15;
    int b = (bid >> 4) & 1;
    int dir = bid >> 5;
    int p = threadIdx.x;
    const float* cAo = g_cA[dir];
    float H[16];
    #pragma unroll
    for (int n = 0; n < 16; n++) H[n] = 0.f;
    for (int c = 0; c < CH; c++) {
        long base = ((((long)(dir * 2 + b) * 16 + h) * CH + c) * 64 + p) * 16;
        #pragma unroll
        for (int n = 0; n < 16; n++) g_Hc[base + n] = H[n];
        float P = cAo[((long)(b * SEQ) + c * CL + CL - 1) * NHEADS + h];
        #pragma unroll
        for (int n = 0; n < 16; n++) H[n] = P * H[n] + g_S[base + n];
    }
}

// ---------------- scan phase C: fixup + gate ----------------
__global__ void __launch_bounds__(64) scanC_k(int l)
{
    int bid = blockIdx.x;
    int chunk = bid & 15;
    int h = (bid >> 4) & 15;
    int b = (bid >> 8) & 1;
    int dir = bid >> 9;
    int p = threadIdx.x;
    const float* xbc = g_xbc[dir];
    const float* zx = g_zx[dir];
    const float* cAo = g_cA[dir];
    float* yo = g_y[dir];
    float H[16];
    long hbase = ((((long)(dir * 2 + b) * 16 + h) * CH + chunk) * 64 + p) * 16;
    #pragma unroll
    for (int n = 0; n < 16; n++) H[n] = g_Hc[hbase + n];
    __shared__ float sC[8][16], scA[8];

    for (int t8 = 0; t8 < CL; t8 += 8) {
        int tb = chunk * CL + t8;
        #pragma unroll
        for (int i = p; i < 128; i += 64) {
            int tt = i >> 4, n = i & 15;
            int o = dir ? (SEQ - 1 - (tb + tt)) : (tb + tt);
            sC[tt][n] = xbc[(long)(b * SEQ + o) * CONVDIM + DINNER + DSTATE + n];
        }
        if (p < 8)
            scA[p] = cAo[((long)(b * SEQ) + tb + p) * NHEADS + h];
        __syncthreads();

        float yp[8], zt[8];
        int oidx[8];
        #pragma unroll
        for (int j = 0; j < 8; j++) {
            int o = dir ? (SEQ - 1 - (tb + j)) : (tb + j);
            oidx[j] = o;
            yp[j] = yo[(long)(b * SEQ + o) * DINNER + h * HEADDIM + p];
            zt[j] = zx[(long)(b * SEQ + o) * DINPROJ + h * HEADDIM + p];
        }
        #pragma unroll
        for (int j = 0; j < 8; j++) {
            float dot = 0.f;
            #pragma unroll
            for (int n = 0; n < 16; n++) dot += H[n] * sC[j][n];
            float y = yp[j] + scA[j] * dot;
            float z = zt[j];
            float sil = z / (1.f + expf(-z));
            yo[(long)(b * SEQ + oidx[j]) * DINNER + h * HEADDIM + p] = y * sil;
        }
        __syncthreads();
    }
}

// ---------------- RMS norm (1024) -> concatenated bf16 hi/lo ---------------
__global__ void __launch_bounds__(256) rms_hl_k(const float* __restrict__ normw, int l)
{
    __shared__ float sbuf[8];
    int bid = blockIdx.x;
    int dir = bid >> 11;
    int tok = bid & (NTOK - 1);
    int tid = threadIdx.x;
    const float* v = g_y[dir] + (long)tok * DINNER;
    const float* w = normw + (l * 2 + dir) * DINNER;
    float vals[4];
    float ss = 0.f;
    #pragma unroll
    for (int i = 0; i < 4; i++) {
        vals[i] = v[tid + i * 256];
        ss += vals[i] * vals[i];
    }
    ss = warpSum(ss);
    if ((tid & 31) == 0) sbuf[tid >> 5] = ss;
    __syncthreads();
    float tot = 0.f;
    #pragma unroll
    for (int i = 0; i < 8; i++) tot += sbuf[i];
    float rs = rsqrtf(tot * (1.f / DINNER) + EPSF);
    #pragma unroll
    for (int i = 0; i < 4; i++) {
        float sv = vals[i] * rs * w[tid + i * 256];
        __nv_bfloat16 h, l2;
        cvt_hl(sv, h, l2);
        long o = (long)tok * (2 * DINNER) + dir * DINNER + tid + i * 256;
        g_ych[o] = h;
        g_ycl[o] = l2;
    }
}

// ---------------- copy final h into d_out tail ----------------
__global__ void __launch_bounds__(256) copy_hfin_k(float* __restrict__ out)
{
    int i = blockIdx.x * 256 + threadIdx.x;
    if (i < NTOK * DMODEL) out[i] = g_hfin[i];
}

// ---------------- launch ----------------
extern "C" void kernel_launch(void* const* d_in, const int* in_sizes, int n_in,
                              void* d_out, int out_size)
{
    const float* x      = (const float*)d_in[0];
    const float* Wpi    = (const float*)d_in[1];
    const float* bpi    = (const float*)d_in[2];
    const float* ln_w   = (const float*)d_in[3];
    const float* ln_b   = (const float*)d_in[4];
    const float* Win    = (const float*)d_in[5];
    const float* convw  = (const float*)d_in[6];
    const float* convb  = (const float*)d_in[7];
    const float* dt_bias= (const float*)d_in[8];
    const float* A_log  = (const float*)d_in[9];
    const float* Dp     = (const float*)d_in[10];
    const float* normw  = (const float*)d_in[11];
    const float* Wout   = (const float*)d_in[12];
    const float* fn_w   = (const float*)d_in[13];
    const float* fn_b   = (const float*)d_in[14];
    const float* Wpo    = (const float*)d_in[15];
    const float* bpo    = (const float*)d_in[16];
    float* out = (float*)d_out;

    cudaFuncSetAttribute(gemm5<false, true, 64>,   cudaFuncAttributeMaxDynamicSharedMemorySize, GS64);
    cudaFuncSetAttribute(gemm5<true,  false, 64>,  cudaFuncAttributeMaxDynamicSharedMemorySize, GS64);
    cudaFuncSetAttribute(gemm5<false, false, 128>, cudaFuncAttributeMaxDynamicSharedMemorySize, GS128);

    float *ph, *phf, *pzx;
    __nv_bfloat16 *pxh, *pxl, *phnh, *phnl, *pych, *pycl, *phfh, *phfl;
    __nv_bfloat16 *pwinh, *pwinl, *pwouth, *pwoutl, *pwpih, *pwpil, *pwpoh, *pwpol;
    cudaGetSymbolAddress((void**)&ph,     g_h);
    cudaGetSymbolAddress((void**)&phf,    g_hfin);
    cudaGetSymbolAddress((void**)&pzx,    g_zx);
    cudaGetSymbolAddress((void**)&pxh,    g_xh);
    cudaGetSymbolAddress((void**)&pxl,    g_xl);
    cudaGetSymbolAddress((void**)&phnh,   g_hnh);
    cudaGetSymbolAddress((void**)&phnl,   g_hnl);
    cudaGetSymbolAddress((void**)&pych,   g_ych);
    cudaGetSymbolAddress((void**)&pycl,   g_ycl);
    cudaGetSymbolAddress((void**)&phfh,   g_hfh);
    cudaGetSymbolAddress((void**)&phfl,   g_hfl);
    cudaGetSymbolAddress((void**)&pwinh,  g_winh);
    cudaGetSymbolAddress((void**)&pwinl,  g_winl);
    cudaGetSymbolAddress((void**)&pwouth, g_wouth);
    cudaGetSymbolAddress((void**)&pwoutl, g_woutl);
    cudaGetSymbolAddress((void**)&pwpih,  g_wpih);
    cudaGetSymbolAddress((void**)&pwpil,  g_wpil);
    cudaGetSymbolAddress((void**)&pwpoh,  g_wpoh);
    cudaGetSymbolAddress((void**)&pwpol,  g_wpol);

    // ---- weight prep ----
    cvt_w_k<<<dim3((KPI*DMODEL + 255)/256, 1, 1), 256>>>(Wpi, pwpih, pwpil, FEAT, DMODEL, KPI, 0, 0);
    cvt_w_k<<<dim3((DMODEL*DINPROJ + 255)/256, 1, 4), 256>>>(
        Win, pwinh, pwinl, DMODEL, DINPROJ, DMODEL,
        (long)DMODEL * DINPROJ, (long)DMODEL * DINPROJ);
    cvt_w_k<<<dim3((DINNER*DMODEL + 255)/256, 1, 4), 256>>>(
        Wout, pwouth, pwoutl, DINNER, DMODEL, DINNER,
        (long)DINNER * DMODEL, (long)DINNER * DMODEL);
    cvt_w_k<<<dim3((DMODEL*FEAT + 255)/256, 1, 1), 256>>>(Wpo, pwpoh, pwpol, DMODEL, FEAT, DMODEL, 0, 0);

    // ---- input proj: h = x @ Wpi + bpi ----
    cvt_x_k<<<(NTOK*KPI + 255)/256, 256>>>(x);
    gemm5<false, true, 64><<<dim3(8, 16, 1), 256, GS64>>>(
        pxh, pxl, pwpih, pwpil, bpi, ph, DMODEL, KPI, 0, 0, 0);

    for (int l = 0; l < 2; l++) {
        layernorm_hl_k<<<NTOK, 256>>>(ph, ln_w + l*DMODEL, ln_b + l*DMODEL, phnh, phnl, nullptr);
        gemm5<false, false, 128><<<dim3(17, 16, 2), 256, GS128>>>(
            phnh, phnl,
            pwinh + (long)l*2*DMODEL*DINPROJ, pwinl + (long)l*2*DMODEL*DINPROJ,
            nullptr, pzx, DINPROJ, DMODEL,
            0, (long)DMODEL*DINPROJ, (long)NTOK*DINPROJ);
        conv2_k<<<dim3(9, SEQ/64, 4), 128>>>(convw, convb, l);
        dtprep_k<<<(2*NTOK*NHEADS + 255)/256, 256>>>(dt_bias, A_log, l);
        scanA_k<<<1024, 64>>>(Dp, l);
        scanB_k<<<64, 64>>>();
        scanC_k<<<1024, 64>>>(l);
        rms_hl_k<<<2*NTOK, 256>>>(normw, l);
        // h += [y0|y1] @ [Wout0; Wout1]   (K-concat, single ACCUM GEMM)
        gemm5<true, false, 64><<<dim3(8, 16, 1), 256, GS64>>>(
            pych, pycl,
            pwouth + (long)l*2*DINNER*DMODEL, pwoutl + (long)l*2*DINNER*DMODEL,
            nullptr, ph, DMODEL, 2*DINNER, 0, 0, 0);
    }

    layernorm_hl_k<<<NTOK, 256>>>(ph, fn_w, fn_b, phfh, phfl, phf);
    gemm5<false, true, 64><<<dim3(2, 16, 1), 256, GS64>>>(
        phfh, phfl, pwpoh, pwpol, bpo, out, FEAT, DMODEL, 0, 0, 0);
    copy_hfin_k<<<(NTOK*DMODEL + 255)/256, 256>>>(out + (long)NTOK*FEAT);
}

// round 8
// speedup vs baseline: 1.0650x; 1.0650x over previous
#include <cuda_runtime.h>
#include <cuda_bf16.h>
#include <math.h>
#include <stdint.h>

#define BATCH 2
#define SEQ 1024
#define FEAT 80
#define DMODEL 512
#define DSTATE 16
#define DCONV 7
#define HEADDIM 64
#define DINNER 1024
#define NHEADS 16
#define CONVDIM 1056
#define DINPROJ 2096
#define NTOK (BATCH*SEQ)
#define EPSF 1e-5f
#define KPI 128
#define CH 16            // scan chunks
#define CL 64            // steps per chunk

// ---------------- scratch ----------------
__device__ float g_h[NTOK*DMODEL];
__device__ float g_zx[2][NTOK*DINPROJ];
__device__ float g_xbc[2][NTOK*CONVDIM];
__device__ float g_y[2][NTOK*DINNER];
__device__ float g_ytmp[2][NTOK*DMODEL];

__device__ float g_S[2*2*16*CH*64*16];
__device__ float g_Hc[2*2*16*CH*64*16];
__device__ float g_cA[2][NTOK*NHEADS];

__device__ __nv_bfloat16 g_hnh[NTOK*DMODEL],  g_hnl[NTOK*DMODEL];
__device__ __nv_bfloat16 g_xh[NTOK*KPI],      g_xl[NTOK*KPI];
__device__ __nv_bfloat16 g_yh[2][NTOK*DINNER],g_yl[2][NTOK*DINNER];
__device__ __nv_bfloat16 g_hfh[NTOK*DMODEL],  g_hfl[NTOK*DMODEL];

__device__ __nv_bfloat16 g_winh[4L*DMODEL*DINPROJ], g_winl[4L*DMODEL*DINPROJ];
__device__ __nv_bfloat16 g_wouth[4L*DINNER*DMODEL], g_woutl[4L*DINNER*DMODEL];
__device__ __nv_bfloat16 g_wpih[KPI*DMODEL],        g_wpil[KPI*DMODEL];
__device__ __nv_bfloat16 g_wpoh[DMODEL*FEAT],       g_wpol[DMODEL*FEAT];

// ---------------- helpers ----------------
__device__ __forceinline__ void cvt_hl(float v, __nv_bfloat16& h, __nv_bfloat16& l) {
    h = __float2bfloat16_rn(v);
    l = __float2bfloat16_rn(v - __bfloat162float(h));
}
__device__ __forceinline__ uint32_t smem_u32(const void* p) {
    uint32_t a;
    asm("{ .reg .u64 t; cvta.to.shared.u64 t, %1; cvt.u32.u64 %0, t; }" : "=r"(a) : "l"(p));
    return a;
}
__device__ __forceinline__ void cpa16(uint32_t dst, const void* src) {
    asm volatile("cp.async.cg.shared.global [%0], [%1], 16;" :: "r"(dst), "l"(src));
}
__device__ __forceinline__ void ldsm_x4(unsigned r[4], uint32_t addr) {
    asm volatile("ldmatrix.sync.aligned.m8n8.x4.shared.b16 {%0,%1,%2,%3}, [%4];"
        : "=r"(r[0]), "=r"(r[1]), "=r"(r[2]), "=r"(r[3]) : "r"(addr));
}
__device__ __forceinline__ void ldsm_x2t(unsigned r[2], uint32_t addr) {
    asm volatile("ldmatrix.sync.aligned.m8n8.x2.trans.shared.b16 {%0,%1}, [%2];"
        : "=r"(r[0]), "=r"(r[1]) : "r"(addr));
}
__device__ __forceinline__ void mma16816(float d[4], const unsigned a[4], const unsigned b[2]) {
    asm volatile("mma.sync.aligned.m16n8k16.row.col.f32.bf16.bf16.f32 "
        "{%0,%1,%2,%3}, {%4,%5,%6,%7}, {%8,%9}, {%0,%1,%2,%3};"
        : "+f"(d[0]), "+f"(d[1]), "+f"(d[2]), "+f"(d[3])
        : "r"(a[0]), "r"(a[1]), "r"(a[2]), "r"(a[3]), "r"(b[0]), "r"(b[1]));
}

// ---------------- GEMM (R5 config): BM=128, BN=128, BK=32, 256 thr ---------
// C[M,N](+)= A[M,K]@B[K,N] (+bias), bf16 hi/lo 3-pass.
#define ASTR 80
#define BSTR 272
#define OFF_AL 10240
#define OFF_BH 20480
#define OFF_BL 29184
#define STAGE 37888
#define GSMEM (2*STAGE)

__device__ __forceinline__ void g5_stage(
    uint32_t sb, const __nv_bfloat16* Ah, const __nv_bfloat16* Al,
    const __nv_bfloat16* Bh, const __nv_bfloat16* Bl,
    int m0, int n0, int k0, int N, int K, int tid)
{
    #pragma unroll
    for (int q = 0; q < 2; q++) {
        int idx = q * 256 + tid, row = idx >> 2, seg = idx & 3;
        uint32_t d = sb + row * ASTR + seg * 16;
        const __nv_bfloat16* s = Ah + (size_t)(m0 + row) * K + k0 + seg * 8;
        cpa16(d, s);
        cpa16(d + OFF_AL, Al + (s - Ah));
    }
    #pragma unroll
    for (int q = 0; q < 2; q++) {
        int idx = q * 256 + tid, row = idx >> 4, seg = idx & 15;
        uint32_t d = sb + OFF_BH + row * BSTR + seg * 16;
        if (n0 + seg * 8 < N) {
            const __nv_bfloat16* s = Bh + (size_t)(k0 + row) * N + n0 + seg * 8;
            cpa16(d, s);
            cpa16(d + 8704, Bl + (s - Bh));
        } else {
            asm volatile("st.shared.v4.b32 [%0], {%1,%1,%1,%1};" :: "r"(d), "r"(0) : "memory");
            asm volatile("st.shared.v4.b32 [%0], {%1,%1,%1,%1};" :: "r"(d + 8704), "r"(0) : "memory");
        }
    }
    asm volatile("cp.async.commit_group;" ::: "memory");
}

template<bool ACCUM, bool BIAS>
__global__ void __launch_bounds__(256) gemm5(
    const __nv_bfloat16* __restrict__ Ah, const __nv_bfloat16* __restrict__ Al,
    const __nv_bfloat16* __restrict__ Bh, const __nv_bfloat16* __restrict__ Bl,
    const float* __restrict__ bias, float* __restrict__ C,
    int N, int K, long az, long bz, long cz)
{
    extern __shared__ char dsm[];
    Ah += (long)blockIdx.z * az;  Al += (long)blockIdx.z * az;
    Bh += (long)blockIdx.z * bz;  Bl += (long)blockIdx.z * bz;
    C  += (long)blockIdx.z * cz;
    const int m0 = blockIdx.y * 128, n0 = blockIdx.x * 128;
    const int tid = threadIdx.x, warp = tid >> 5, lane = tid & 31;
    const int wm = (warp & 1) * 64, wn = (warp >> 1) * 32;
    const uint32_t raw = smem_u32(dsm);

    float acc[4][4][4];
    #pragma unroll
    for (int f = 0; f < 4; f++)
        #pragma unroll
        for (int g = 0; g < 4; g++)
            #pragma unroll
            for (int i = 0; i < 4; i++) acc[f][g][i] = 0.f;

    const int nch = K >> 5;
    g5_stage(raw, Ah, Al, Bh, Bl, m0, n0, 0, N, K, tid);

    for (int c = 0; c < nch; c++) {
        if (c + 1 < nch) {
            g5_stage(raw + (uint32_t)((c + 1) & 1) * STAGE,
                     Ah, Al, Bh, Bl, m0, n0, (c + 1) << 5, N, K, tid);
            asm volatile("cp.async.wait_group 1;" ::: "memory");
        } else {
            asm volatile("cp.async.wait_group 0;" ::: "memory");
        }
        __syncthreads();

        const uint32_t sb = raw + (uint32_t)(c & 1) * STAGE;
        #pragma unroll
        for (int ks = 0; ks < 2; ks++) {
            const int kk = ks * 16;
            unsigned ah[4][4], al[4][4], bh[4][2], bl[4][2];
            #pragma unroll
            for (int f = 0; f < 4; f++) {
                int row = wm + f * 16 + (lane & 15);
                int col = kk + ((lane >> 4) << 3);
                uint32_t a = sb + row * ASTR + col * 2;
                ldsm_x4(ah[f], a);
                ldsm_x4(al[f], a + OFF_AL);
            }
            #pragma unroll
            for (int g = 0; g < 4; g++) {
                int row = kk + (lane & 15);
                int col = wn + g * 8;
                uint32_t a = sb + OFF_BH + row * BSTR + col * 2;
                ldsm_x2t(bh[g], a);
                ldsm_x2t(bl[g], a + 8704);
            }
            #pragma unroll
            for (int f = 0; f < 4; f++)
                #pragma unroll
                for (int g = 0; g < 4; g++) {
                    mma16816(acc[f][g], ah[f], bh[g]);
                    mma16816(acc[f][g], al[f], bh[g]);
                    mma16816(acc[f][g], ah[f], bl[g]);
                }
        }
        __syncthreads();
    }

    const int cr = lane >> 2, cc = (lane & 3) * 2;
    #pragma unroll
    for (int f = 0; f < 4; f++) {
        #pragma unroll
        for (int g = 0; g < 4; g++) {
            int mmb = m0 + wm + f * 16 + cr;
            int nn = n0 + wn + g * 8 + cc;
            #pragma unroll
            for (int half = 0; half < 2; half++) {
                int m = mmb + half * 8;
                #pragma unroll
                for (int j = 0; j < 2; j++) {
                    if (nn + j < N) {
                        float v = acc[f][g][half * 2 + j];
                        long o = (long)m * N + nn + j;
                        if (BIAS) v += bias[nn + j];
                        if (ACCUM) v += C[o];
                        C[o] = v;
                    }
                }
            }
        }
    }
}

// ---------------- mega convert: all weights + x -> bf16 hi/lo --------------
#define SEG0 ((long)KPI*DMODEL)
#define SEG1 (SEG0 + 4L*DMODEL*DINPROJ)
#define SEG2 (SEG1 + 4L*DINNER*DMODEL)
#define SEG3 (SEG2 + (long)DMODEL*FEAT)
#define SEG4 (SEG3 + (long)NTOK*KPI)

__global__ void __launch_bounds__(256) cvt_all_k(
    const float* __restrict__ Wpi, const float* __restrict__ Win,
    const float* __restrict__ Wout, const float* __restrict__ Wpo,
    const float* __restrict__ x)
{
    long i = (long)blockIdx.x * 256 + threadIdx.x;
    if (i >= SEG4) return;
    float v;
    __nv_bfloat16 *dh, *dl;
    long o;
    if (i < SEG0) {                    // Wpi padded [KPI][DMODEL]
        long k = i / DMODEL, n = i - k * DMODEL;
        v = (k < FEAT) ? Wpi[k * DMODEL + n] : 0.f;
        dh = g_wpih; dl = g_wpil; o = i;
    } else if (i < SEG1) {             // Win flat
        o = i - SEG0; v = Win[o]; dh = g_winh; dl = g_winl;
    } else if (i < SEG2) {             // Wout flat
        o = i - SEG1; v = Wout[o]; dh = g_wouth; dl = g_woutl;
    } else if (i < SEG3) {             // Wpo flat
        o = i - SEG2; v = Wpo[o]; dh = g_wpoh; dl = g_wpol;
    } else {                           // x padded [NTOK][KPI]
        o = i - SEG3;
        long r = o >> 7, c = o & (KPI - 1);
        v = (c < FEAT) ? x[r * FEAT + c] : 0.f;
        dh = g_xh; dl = g_xl;
    }
    __nv_bfloat16 h, l;
    cvt_hl(v, h, l);
    dh[o] = h; dl[o] = l;
}

// ---------------- reductions ----------------
__device__ __forceinline__ float warpSum(float v) {
    #pragma unroll
    for (int o = 16; o; o >>= 1) v += __shfl_down_sync(0xffffffffu, v, o);
    return v;
}

// ---------------- layernorm (+optional residual add) -> bf16 hi/lo ---------
// RES: x = h + yt0 + yt1, writes summed value back to h (next residual).
template<bool RES>
__global__ void __launch_bounds__(256) layernorm_hl_k(
    float* __restrict__ hio, const float* __restrict__ yt0,
    const float* __restrict__ yt1, const float* __restrict__ w,
    const float* __restrict__ b, __nv_bfloat16* __restrict__ oh,
    __nv_bfloat16* __restrict__ ol, float* __restrict__ of)
{
    __shared__ float sbuf[8];
    int row = blockIdx.x, tid = threadIdx.x;
    long o0 = (long)row * DMODEL + tid, o1 = o0 + 256;
    float x0 = hio[o0], x1 = hio[o1];
    if (RES) {
        x0 += yt0[o0] + yt1[o0];
        x1 += yt0[o1] + yt1[o1];
        hio[o0] = x0; hio[o1] = x1;
    }
    float s = warpSum(x0 + x1);
    if ((tid & 31) == 0) sbuf[tid >> 5] = s;
    __syncthreads();
    float mean = 0.f;
    #pragma unroll
    for (int i = 0; i < 8; i++) mean += sbuf[i];
    mean *= (1.f / DMODEL);
    __syncthreads();
    float c0 = x0 - mean, c1 = x1 - mean;
    float ss = warpSum(c0 * c0 + c1 * c1);
    if ((tid & 31) == 0) sbuf[tid >> 5] = ss;
    __syncthreads();
    float var = 0.f;
    #pragma unroll
    for (int i = 0; i < 8; i++) var += sbuf[i];
    var *= (1.f / DMODEL);
    float rs = rsqrtf(var + EPSF);
    float r0 = c0 * rs * w[tid] + b[tid];
    float r1 = c1 * rs * w[tid + 256] + b[tid + 256];
    __nv_bfloat16 h, l;
    cvt_hl(r0, h, l); oh[o0] = h; ol[o0] = l;
    cvt_hl(r1, h, l); oh[o1] = h; ol[o1] = l;
    if (of) { of[o0] = r0; of[o1] = r1; }
}

// ---------------- sliding-window causal conv + SiLU ----------------
__global__ void __launch_bounds__(128) conv2_k(
    const float* __restrict__ convw, const float* __restrict__ convb, int l)
{
    int c = blockIdx.x * 128 + threadIdx.x;
    bool act = (c < CONVDIM);
    int t0 = blockIdx.y * 64;
    int dir = blockIdx.z >> 1;
    int b = blockIdx.z & 1;
    float w[7], bias = 0.f;
    #pragma unroll
    for (int k = 0; k < 7; k++) w[k] = 0.f;
    if (act) {
        const float* wp = convw + ((long)((l * 2 + dir) * CONVDIM) + c) * DCONV;
        #pragma unroll
        for (int k = 0; k < 7; k++) w[k] = wp[k];
        bias = convb[(l * 2 + dir) * CONVDIM + c];
    }
    const float* in = g_zx[dir] + (long)b * SEQ * DINPROJ + DINNER + c;
    float* outp = g_xbc[dir] + (long)b * SEQ * CONVDIM + c;

    float win[7];
    if (dir == 0) {
        #pragma unroll
        for (int j = 1; j < 7; j++) {
            int t = t0 - j;
            win[j] = (act && t >= 0) ? in[(long)t * DINPROJ] : 0.f;
        }
        #pragma unroll 4
        for (int i = 0; i < 64; i++) {
            int o = t0 + i;
            win[0] = act ? in[(long)o * DINPROJ] : 0.f;
            float a = bias;
            #pragma unroll
            for (int j = 0; j < 7; j++) a += w[6 - j] * win[j];
            float sv = a / (1.f + expf(-a));
            if (act) outp[(long)o * CONVDIM] = sv;
            #pragma unroll
            for (int j = 6; j > 0; j--) win[j] = win[j - 1];
        }
    } else {
        #pragma unroll
        for (int j = 0; j < 6; j++) {
            int t = t0 + j;
            win[j] = (act && t < SEQ) ? in[(long)t * DINPROJ] : 0.f;
        }
        #pragma unroll 4
        for (int i = 0; i < 64; i++) {
            int o = t0 + i;
            int t = o + 6;
            win[6] = (act && t < SEQ) ? in[(long)t * DINPROJ] : 0.f;
            float a = bias;
            #pragma unroll
            for (int j = 0; j < 7; j++) a += w[6 - j] * win[j];
            float sv = a / (1.f + expf(-a));
            if (act) outp[(long)o * CONVDIM] = sv;
            #pragma unroll
            for (int j = 0; j < 6; j++) win[j] = win[j + 1];
        }
    }
}

// ---------------- scan phase A: chunk-local scan + inline dt/dA ------------
// grid: 1024 = dir*512 + b*256 + h*16 + chunk; 64 threads (p)
__global__ void __launch_bounds__(64) scanA_k(
    const float* __restrict__ Dp, const float* __restrict__ dt_bias,
    const float* __restrict__ A_log, int l)
{
    int bid = blockIdx.x;
    int chunk = bid & 15;
    int h = (bid >> 4) & 15;
    int b = (bid >> 8) & 1;
    int dir = bid >> 9;
    int p = threadIdx.x;
    const float* xbc = g_xbc[dir];
    const float* zx = g_zx[dir];
    float* yo = g_y[dir];
    float* cAo = g_cA[dir];
    const float Dv = Dp[(l * 2 + dir) * NHEADS + h];
    const float dtb = dt_bias[(l * 2 + dir) * NHEADS + h];
    const float Av = -expf(A_log[(l * 2 + dir) * NHEADS + h]);

    __shared__ float sdt64[64], sdA64[64];
    {
        int t = chunk * CL + p;
        int o = dir ? (SEQ - 1 - t) : t;
        float raw = zx[(long)(b * SEQ + o) * DINPROJ + DINNER + CONVDIM + h];
        float xv = raw + dtb;
        float dt = (xv > 20.f) ? xv : log1pf(expf(xv));
        sdt64[p] = dt;
        sdA64[p] = expf(dt * Av);
    }
    __syncthreads();

    float hs[16];
    #pragma unroll
    for (int n = 0; n < 16; n++) hs[n] = 0.f;
    float cumA = 1.f;
    __shared__ float sB[8][16], sC[8][16];

    for (int t8 = 0; t8 < CL; t8 += 8) {
        int tb = chunk * CL + t8;
        #pragma unroll
        for (int i = p; i < 128; i += 64) {
            int tt = i >> 4, n = i & 15;
            int o = dir ? (SEQ - 1 - (tb + tt)) : (tb + tt);
            long base = (long)(b * SEQ + o) * CONVDIM + DINNER;
            sB[tt][n] = xbc[base + n];
            sC[tt][n] = xbc[base + DSTATE + n];
        }
        __syncthreads();

        float xt[8];
        int oidx[8];
        #pragma unroll
        for (int j = 0; j < 8; j++) {
            int o = dir ? (SEQ - 1 - (tb + j)) : (tb + j);
            oidx[j] = o;
            xt[j] = xbc[(long)(b * SEQ + o) * CONVDIM + h * HEADDIM + p];
        }
        #pragma unroll
        for (int j = 0; j < 8; j++) {
            float dt = sdt64[t8 + j], dA = sdA64[t8 + j];
            float cdt = dt * xt[j];
            float y = 0.f;
            #pragma unroll
            for (int n = 0; n < 16; n++) {
                hs[n] = hs[n] * dA + cdt * sB[j][n];
                y += hs[n] * sC[j][n];
            }
            y += Dv * xt[j];
            yo[(long)(b * SEQ + oidx[j]) * DINNER + h * HEADDIM + p] = y;  // pre-gate
            cumA *= dA;
            if (p == 0) cAo[((long)(b * SEQ) + tb + j) * NHEADS + h] = cumA;
        }
        __syncthreads();
    }
    long sbase = ((((long)(dir * 2 + b) * 16 + h) * CH + chunk) * 64 + p) * 16;
    #pragma unroll
    for (int n = 0; n < 16; n++) g_S[sbase + n] = hs[n];
}

// ---------------- scan phase B: sequential chunk combine -------------------
__global__ void __launch_bounds__(64) scanB_k()
{
    int bid = blockIdx.x;
    int h = bid & 15;
    int b = (bid >> 4) & 1;
    int dir = bid >> 5;
    int p = threadIdx.x;
    const float* cAo = g_cA[dir];
    float H[16];
    #pragma unroll
    for (int n = 0; n < 16; n++) H[n] = 0.f;
    for (int c = 0; c < CH; c++) {
        long base = ((((long)(dir * 2 + b) * 16 + h) * CH + c) * 64 + p) * 16;
        #pragma unroll
        for (int n = 0; n < 16; n++) g_Hc[base + n] = H[n];
        float P = cAo[((long)(b * SEQ) + c * CL + CL - 1) * NHEADS + h];
        #pragma unroll
        for (int n = 0; n < 16; n++) H[n] = P * H[n] + g_S[base + n];
    }
}

// ---------------- scan phase C: fixup + gate ----------------
__global__ void __launch_bounds__(64) scanC_k(int l)
{
    int bid = blockIdx.x;
    int chunk = bid & 15;
    int h = (bid >> 4) & 15;
    int b = (bid >> 8) & 1;
    int dir = bid >> 9;
    int p = threadIdx.x;
    const float* xbc = g_xbc[dir];
    const float* zx = g_zx[dir];
    const float* cAo = g_cA[dir];
    float* yo = g_y[dir];
    float H[16];
    long hbase = ((((long)(dir * 2 + b) * 16 + h) * CH + chunk) * 64 + p) * 16;
    #pragma unroll
    for (int n = 0; n < 16; n++) H[n] = g_Hc[hbase + n];
    __shared__ float sC[8][16], scA[8];

    for (int t8 = 0; t8 < CL; t8 += 8) {
        int tb = chunk * CL + t8;
        #pragma unroll
        for (int i = p; i < 128; i += 64) {
            int tt = i >> 4, n = i & 15;
            int o = dir ? (SEQ - 1 - (tb + tt)) : (tb + tt);
            sC[tt][n] = xbc[(long)(b * SEQ + o) * CONVDIM + DINNER + DSTATE + n];
        }
        if (p < 8)
            scA[p] = cAo[((long)(b * SEQ) + tb + p) * NHEADS + h];
        __syncthreads();

        float yp[8], zt[8];
        int oidx[8];
        #pragma unroll
        for (int j = 0; j < 8; j++) {
            int o = dir ? (SEQ - 1 - (tb + j)) : (tb + j);
            oidx[j] = o;
            yp[j] = yo[(long)(b * SEQ + o) * DINNER + h * HEADDIM + p];
            zt[j] = zx[(long)(b * SEQ + o) * DINPROJ + h * HEADDIM + p];
        }
        #pragma unroll
        for (int j = 0; j < 8; j++) {
            float dot = 0.f;
            #pragma unroll
            for (int n = 0; n < 16; n++) dot += H[n] * sC[j][n];
            float y = yp[j] + scA[j] * dot;
            float z = zt[j];
            float sil = z / (1.f + expf(-z));
            yo[(long)(b * SEQ + oidx[j]) * DINNER + h * HEADDIM + p] = y * sil;
        }
        __syncthreads();
    }
}

// ---------------- RMS norm (1024) -> bf16 hi/lo (per dir) ------------------
__global__ void __launch_bounds__(256) rms_hl_k(const float* __restrict__ normw, int l)
{
    __shared__ float sbuf[8];
    int bid = blockIdx.x;
    int dir = bid >> 11;
    int tok = bid & (NTOK - 1);
    int tid = threadIdx.x;
    const float* v = g_y[dir] + (long)tok * DINNER;
    const float* w = normw + (l * 2 + dir) * DINNER;
    float vals[4];
    float ss = 0.f;
    #pragma unroll
    for (int i = 0; i < 4; i++) {
        vals[i] = v[tid + i * 256];
        ss += vals[i] * vals[i];
    }
    ss = warpSum(ss);
    if ((tid & 31) == 0) sbuf[tid >> 5] = ss;
    __syncthreads();
    float tot = 0.f;
    #pragma unroll
    for (int i = 0; i < 8; i++) tot += sbuf[i];
    float rs = rsqrtf(tot * (1.f / DINNER) + EPSF);
    #pragma unroll
    for (int i = 0; i < 4; i++) {
        float sv = vals[i] * rs * w[tid + i * 256];
        __nv_bfloat16 h, l2;
        cvt_hl(sv, h, l2);
        long o = (long)tok * DINNER + tid + i * 256;
        g_yh[dir][o] = h;
        g_yl[dir][o] = l2;
    }
}

// ---------------- launch ----------------
extern "C" void kernel_launch(void* const* d_in, const int* in_sizes, int n_in,
                              void* d_out, int out_size)
{
    const float* x      = (const float*)d_in[0];
    const float* Wpi    = (const float*)d_in[1];
    const float* bpi    = (const float*)d_in[2];
    const float* ln_w   = (const float*)d_in[3];
    const float* ln_b   = (const float*)d_in[4];
    const float* Win    = (const float*)d_in[5];
    const float* convw  = (const float*)d_in[6];
    const float* convb  = (const float*)d_in[7];
    const float* dt_bias= (const float*)d_in[8];
    const float* A_log  = (const float*)d_in[9];
    const float* Dp     = (const float*)d_in[10];
    const float* normw  = (const float*)d_in[11];
    const float* Wout   = (const float*)d_in[12];
    const float* fn_w   = (const float*)d_in[13];
    const float* fn_b   = (const float*)d_in[14];
    const float* Wpo    = (const float*)d_in[15];
    const float* bpo    = (const float*)d_in[16];
    float* out = (float*)d_out;

    cudaFuncSetAttribute(gemm5<false, true>,  cudaFuncAttributeMaxDynamicSharedMemorySize, GSMEM);
    cudaFuncSetAttribute(gemm5<false, false>, cudaFuncAttributeMaxDynamicSharedMemorySize, GSMEM);

    float *ph, *pzx, *pyt;
    __nv_bfloat16 *pxh, *pxl, *phnh, *phnl, *pyh, *pyl, *phfh, *phfl;
    __nv_bfloat16 *pwinh, *pwinl, *pwouth, *pwoutl, *pwpih, *pwpil, *pwpoh, *pwpol;
    cudaGetSymbolAddress((void**)&ph,     g_h);
    cudaGetSymbolAddress((void**)&pzx,    g_zx);
    cudaGetSymbolAddress((void**)&pyt,    g_ytmp);
    cudaGetSymbolAddress((void**)&pxh,    g_xh);
    cudaGetSymbolAddress((void**)&pxl,    g_xl);
    cudaGetSymbolAddress((void**)&phnh,   g_hnh);
    cudaGetSymbolAddress((void**)&phnl,   g_hnl);
    cudaGetSymbolAddress((void**)&pyh,    g_yh);
    cudaGetSymbolAddress((void**)&pyl,    g_yl);
    cudaGetSymbolAddress((void**)&phfh,   g_hfh);
    cudaGetSymbolAddress((void**)&phfl,   g_hfl);
    cudaGetSymbolAddress((void**)&pwinh,  g_winh);
    cudaGetSymbolAddress((void**)&pwinl,  g_winl);
    cudaGetSymbolAddress((void**)&pwouth, g_wouth);
    cudaGetSymbolAddress((void**)&pwoutl, g_woutl);
    cudaGetSymbolAddress((void**)&pwpih,  g_wpih);
    cudaGetSymbolAddress((void**)&pwpil,  g_wpil);
    cudaGetSymbolAddress((void**)&pwpoh,  g_wpoh);
    cudaGetSymbolAddress((void**)&pwpol,  g_wpol);

    // ---- one mega convert (weights + x) ----
    cvt_all_k<<<(int)((SEG4 + 255) / 256), 256>>>(Wpi, Win, Wout, Wpo, x);

    // ---- input proj: h = x @ Wpi + bpi ----
    gemm5<false, true><<<dim3(4, 16, 1), 256, GSMEM>>>(
        pxh, pxl, pwpih, pwpil, bpi, ph, DMODEL, KPI, 0, 0, 0);

    for (int l = 0; l < 2; l++) {
        if (l == 0)
            layernorm_hl_k<false><<<NTOK, 256>>>(ph, nullptr, nullptr,
                ln_w, ln_b, phnh, phnl, nullptr);
        else
            layernorm_hl_k<true><<<NTOK, 256>>>(ph, pyt, pyt + (long)NTOK*DMODEL,
                ln_w + l*DMODEL, ln_b + l*DMODEL, phnh, phnl, nullptr);
        gemm5<false, false><<<dim3(17, 16, 2), 256, GSMEM>>>(
            phnh, phnl,
            pwinh + (long)l*2*DMODEL*DINPROJ, pwinl + (long)l*2*DMODEL*DINPROJ,
            nullptr, pzx, DINPROJ, DMODEL,
            0, (long)DMODEL*DINPROJ, (long)NTOK*DINPROJ);
        conv2_k<<<dim3(9, SEQ/64, 4), 128>>>(convw, convb, l);
        scanA_k<<<1024, 64>>>(Dp, dt_bias, A_log, l);
        scanB_k<<<64, 64>>>();
        scanC_k<<<1024, 64>>>(l);
        rms_hl_k<<<2*NTOK, 256>>>(normw, l);
        // ytmp[dir] = y[dir] @ Wout[l,dir]  (batched z=2)
        gemm5<false, false><<<dim3(4, 16, 2), 256, GSMEM>>>(
            pyh, pyl,
            pwouth + (long)l*2*DINNER*DMODEL, pwoutl + (long)l*2*DINNER*DMODEL,
            nullptr, pyt, DMODEL, DINNER,
            (long)NTOK*DINNER, (long)DINNER*DMODEL, (long)NTOK*DMODEL);
    }

    // final: LN(h + yt0 + yt1) -> bf16 hi/lo + fp32 straight into out tail
    layernorm_hl_k<true><<<NTOK, 256>>>(ph, pyt, pyt + (long)NTOK*DMODEL,
        fn_w, fn_b, phfh, phfl, out + (long)NTOK*FEAT);
    gemm5<false, true><<<dim3(1, 16, 1), 256, GSMEM>>>(
        phfh, phfl, pwpoh, pwpol, bpo, out, FEAT, DMODEL, 0, 0, 0);
}

// round 9
// speedup vs baseline: 1.0885x; 1.0220x over previous
#include <cuda_runtime.h>
#include <cuda_bf16.h>
#include <math.h>
#include <stdint.h>

#define BATCH 2
#define SEQ 1024
#define FEAT 80
#define DMODEL 512
#define DSTATE 16
#define DCONV 7
#define HEADDIM 64
#define DINNER 1024
#define NHEADS 16
#define CONVDIM 1056
#define DINPROJ 2096
#define NTOK (BATCH*SEQ)
#define EPSF 1e-5f
#define KPI 128
#define CH 16            // scan chunks
#define CL 64            // steps per chunk

// ---------------- scratch ----------------
__device__ float g_h[NTOK*DMODEL];
__device__ float g_zx[2][NTOK*DINPROJ];
__device__ float g_xbc[2][NTOK*CONVDIM];
__device__ float g_y[2][NTOK*DINNER];
__device__ float g_ytmp[2][NTOK*DMODEL];

__device__ float g_S[2*2*16*CH*64*16];
__device__ float g_Hc[2*2*16*CH*64*16];
__device__ float g_cA[2][NTOK*NHEADS];

__device__ __nv_bfloat16 g_hnh[NTOK*DMODEL],  g_hnl[NTOK*DMODEL];
__device__ __nv_bfloat16 g_xh[NTOK*KPI],      g_xl[NTOK*KPI];
__device__ __nv_bfloat16 g_yh[2][NTOK*DINNER],g_yl[2][NTOK*DINNER];
__device__ __nv_bfloat16 g_hfh[NTOK*DMODEL],  g_hfl[NTOK*DMODEL];

__device__ __nv_bfloat16 g_winh[4L*DMODEL*DINPROJ], g_winl[4L*DMODEL*DINPROJ];
__device__ __nv_bfloat16 g_wouth[4L*DINNER*DMODEL], g_woutl[4L*DINNER*DMODEL];
__device__ __nv_bfloat16 g_wpih[KPI*DMODEL],        g_wpil[KPI*DMODEL];
__device__ __nv_bfloat16 g_wpoh[DMODEL*FEAT],       g_wpol[DMODEL*FEAT];

// ---------------- helpers ----------------
__device__ __forceinline__ void cvt_hl(float v, __nv_bfloat16& h, __nv_bfloat16& l) {
    h = __float2bfloat16_rn(v);
    l = __float2bfloat16_rn(v - __bfloat162float(h));
}
__device__ __forceinline__ uint32_t smem_u32(const void* p) {
    uint32_t a;
    asm("{ .reg .u64 t; cvta.to.shared.u64 t, %1; cvt.u32.u64 %0, t; }" : "=r"(a) : "l"(p));
    return a;
}
__device__ __forceinline__ void cpa16(uint32_t dst, const void* src) {
    asm volatile("cp.async.cg.shared.global [%0], [%1], 16;" :: "r"(dst), "l"(src));
}
__device__ __forceinline__ void ldsm_x4(unsigned r[4], uint32_t addr) {
    asm volatile("ldmatrix.sync.aligned.m8n8.x4.shared.b16 {%0,%1,%2,%3}, [%4];"
        : "=r"(r[0]), "=r"(r[1]), "=r"(r[2]), "=r"(r[3]) : "r"(addr));
}
__device__ __forceinline__ void ldsm_x2t(unsigned r[2], uint32_t addr) {
    asm volatile("ldmatrix.sync.aligned.m8n8.x2.trans.shared.b16 {%0,%1}, [%2];"
        : "=r"(r[0]), "=r"(r[1]) : "r"(addr));
}
__device__ __forceinline__ void mma16816(float d[4], const unsigned a[4], const unsigned b[2]) {
    asm volatile("mma.sync.aligned.m16n8k16.row.col.f32.bf16.bf16.f32 "
        "{%0,%1,%2,%3}, {%4,%5,%6,%7}, {%8,%9}, {%0,%1,%2,%3};"
        : "+f"(d[0]), "+f"(d[1]), "+f"(d[2]), "+f"(d[3])
        : "r"(a[0]), "r"(a[1]), "r"(a[2]), "r"(a[3]), "r"(b[0]), "r"(b[1]));
}

// ---------------- GEMM: BM=128, BN=128, BK=32, 256 thr, 2 CTAs/SM ----------
// C[M,N](+)= A[M,K]@B[K,N] (+bias), bf16 hi/lo 3-pass.
#define ASTR 80
#define BSTR 272
#define OFF_AL 10240
#define OFF_BH 20480
#define OFF_BL 29184
#define STAGE 37888
#define GSMEM (2*STAGE)

__device__ __forceinline__ void g5_stage(
    uint32_t sb, const __nv_bfloat16* Ah, const __nv_bfloat16* Al,
    const __nv_bfloat16* Bh, const __nv_bfloat16* Bl,
    int m0, int n0, int k0, int N, int K, int tid)
{
    #pragma unroll
    for (int q = 0; q < 2; q++) {
        int idx = q * 256 + tid, row = idx >> 2, seg = idx & 3;
        uint32_t d = sb + row * ASTR + seg * 16;
        const __nv_bfloat16* s = Ah + (size_t)(m0 + row) * K + k0 + seg * 8;
        cpa16(d, s);
        cpa16(d + OFF_AL, Al + (s - Ah));
    }
    #pragma unroll
    for (int q = 0; q < 2; q++) {
        int idx = q * 256 + tid, row = idx >> 4, seg = idx & 15;
        uint32_t d = sb + OFF_BH + row * BSTR + seg * 16;
        if (n0 + seg * 8 < N) {
            const __nv_bfloat16* s = Bh + (size_t)(k0 + row) * N + n0 + seg * 8;
            cpa16(d, s);
            cpa16(d + 8704, Bl + (s - Bh));
        } else {
            asm volatile("st.shared.v4.b32 [%0], {%1,%1,%1,%1};" :: "r"(d), "r"(0) : "memory");
            asm volatile("st.shared.v4.b32 [%0], {%1,%1,%1,%1};" :: "r"(d + 8704), "r"(0) : "memory");
        }
    }
    asm volatile("cp.async.commit_group;" ::: "memory");
}

template<bool ACCUM, bool BIAS>
__global__ void __launch_bounds__(256, 2) gemm5(
    const __nv_bfloat16* __restrict__ Ah, const __nv_bfloat16* __restrict__ Al,
    const __nv_bfloat16* __restrict__ Bh, const __nv_bfloat16* __restrict__ Bl,
    const float* __restrict__ bias, float* __restrict__ C,
    int N, int K, long az, long bz, long cz)
{
    extern __shared__ char dsm[];
    Ah += (long)blockIdx.z * az;  Al += (long)blockIdx.z * az;
    Bh += (long)blockIdx.z * bz;  Bl += (long)blockIdx.z * bz;
    C  += (long)blockIdx.z * cz;
    const int m0 = blockIdx.y * 128, n0 = blockIdx.x * 128;
    const int tid = threadIdx.x, warp = tid >> 5, lane = tid & 31;
    const int wm = (warp & 1) * 64, wn = (warp >> 1) * 32;
    const uint32_t raw = smem_u32(dsm);

    float acc[4][4][4];
    #pragma unroll
    for (int f = 0; f < 4; f++)
        #pragma unroll
        for (int g = 0; g < 4; g++)
            #pragma unroll
            for (int i = 0; i < 4; i++) acc[f][g][i] = 0.f;

    const int nch = K >> 5;
    g5_stage(raw, Ah, Al, Bh, Bl, m0, n0, 0, N, K, tid);

    for (int c = 0; c < nch; c++) {
        if (c + 1 < nch) {
            g5_stage(raw + (uint32_t)((c + 1) & 1) * STAGE,
                     Ah, Al, Bh, Bl, m0, n0, (c + 1) << 5, N, K, tid);
            asm volatile("cp.async.wait_group 1;" ::: "memory");
        } else {
            asm volatile("cp.async.wait_group 0;" ::: "memory");
        }
        __syncthreads();

        const uint32_t sb = raw + (uint32_t)(c & 1) * STAGE;
        #pragma unroll
        for (int ks = 0; ks < 2; ks++) {
            const int kk = ks * 16;
            unsigned ah[4][4], al[4][4], bh[4][2], bl[4][2];
            #pragma unroll
            for (int f = 0; f < 4; f++) {
                int row = wm + f * 16 + (lane & 15);
                int col = kk + ((lane >> 4) << 3);
                uint32_t a = sb + row * ASTR + col * 2;
                ldsm_x4(ah[f], a);
                ldsm_x4(al[f], a + OFF_AL);
            }
            #pragma unroll
            for (int g = 0; g < 4; g++) {
                int row = kk + (lane & 15);
                int col = wn + g * 8;
                uint32_t a = sb + OFF_BH + row * BSTR + col * 2;
                ldsm_x2t(bh[g], a);
                ldsm_x2t(bl[g], a + 8704);
            }
            #pragma unroll
            for (int f = 0; f < 4; f++)
                #pragma unroll
                for (int g = 0; g < 4; g++) {
                    mma16816(acc[f][g], ah[f], bh[g]);
                    mma16816(acc[f][g], al[f], bh[g]);
                    mma16816(acc[f][g], ah[f], bl[g]);
                }
        }
        __syncthreads();
    }

    const int cr = lane >> 2, cc = (lane & 3) * 2;
    #pragma unroll
    for (int f = 0; f < 4; f++) {
        #pragma unroll
        for (int g = 0; g < 4; g++) {
            int mmb = m0 + wm + f * 16 + cr;
            int nn = n0 + wn + g * 8 + cc;
            #pragma unroll
            for (int half = 0; half < 2; half++) {
                int m = mmb + half * 8;
                #pragma unroll
                for (int j = 0; j < 2; j++) {
                    if (nn + j < N) {
                        float v = acc[f][g][half * 2 + j];
                        long o = (long)m * N + nn + j;
                        if (BIAS) v += bias[nn + j];
                        if (ACCUM) v += C[o];
                        C[o] = v;
                    }
                }
            }
        }
    }
}

// ---------------- mega convert: all weights + x -> bf16 hi/lo --------------
#define SEG0 ((long)KPI*DMODEL)
#define SEG1 (SEG0 + 4L*DMODEL*DINPROJ)
#define SEG2 (SEG1 + 4L*DINNER*DMODEL)
#define SEG3 (SEG2 + (long)DMODEL*FEAT)
#define SEG4 (SEG3 + (long)NTOK*KPI)

__global__ void __launch_bounds__(256) cvt_all_k(
    const float* __restrict__ Wpi, const float* __restrict__ Win,
    const float* __restrict__ Wout, const float* __restrict__ Wpo,
    const float* __restrict__ x)
{
    long i = (long)blockIdx.x * 256 + threadIdx.x;
    if (i >= SEG4) return;
    float v;
    __nv_bfloat16 *dh, *dl;
    long o;
    if (i < SEG0) {                    // Wpi padded [KPI][DMODEL]
        long k = i / DMODEL, n = i - k * DMODEL;
        v = (k < FEAT) ? Wpi[k * DMODEL + n] : 0.f;
        dh = g_wpih; dl = g_wpil; o = i;
    } else if (i < SEG1) {             // Win flat
        o = i - SEG0; v = Win[o]; dh = g_winh; dl = g_winl;
    } else if (i < SEG2) {             // Wout flat
        o = i - SEG1; v = Wout[o]; dh = g_wouth; dl = g_woutl;
    } else if (i < SEG3) {             // Wpo flat
        o = i - SEG2; v = Wpo[o]; dh = g_wpoh; dl = g_wpol;
    } else {                           // x padded [NTOK][KPI]
        o = i - SEG3;
        long r = o >> 7, c = o & (KPI - 1);
        v = (c < FEAT) ? x[r * FEAT + c] : 0.f;
        dh = g_xh; dl = g_xl;
    }
    __nv_bfloat16 h, l;
    cvt_hl(v, h, l);
    dh[o] = h; dl[o] = l;
}

// ---------------- reductions ----------------
__device__ __forceinline__ float warpSum(float v) {
    #pragma unroll
    for (int o = 16; o; o >>= 1) v += __shfl_down_sync(0xffffffffu, v, o);
    return v;
}

// ---------------- layernorm (+optional residual add) -> bf16 hi/lo ---------
// RES: x = h + yt0 + yt1, writes summed value back to h (next residual).
template<bool RES>
__global__ void __launch_bounds__(256) layernorm_hl_k(
    float* __restrict__ hio, const float* __restrict__ yt0,
    const float* __restrict__ yt1, const float* __restrict__ w,
    const float* __restrict__ b, __nv_bfloat16* __restrict__ oh,
    __nv_bfloat16* __restrict__ ol, float* __restrict__ of)
{
    __shared__ float sbuf[8];
    int row = blockIdx.x, tid = threadIdx.x;
    long o0 = (long)row * DMODEL + tid, o1 = o0 + 256;
    float x0 = hio[o0], x1 = hio[o1];
    if (RES) {
        x0 += yt0[o0] + yt1[o0];
        x1 += yt0[o1] + yt1[o1];
        hio[o0] = x0; hio[o1] = x1;
    }
    float s = warpSum(x0 + x1);
    if ((tid & 31) == 0) sbuf[tid >> 5] = s;
    __syncthreads();
    float mean = 0.f;
    #pragma unroll
    for (int i = 0; i < 8; i++) mean += sbuf[i];
    mean *= (1.f / DMODEL);
    __syncthreads();
    float c0 = x0 - mean, c1 = x1 - mean;
    float ss = warpSum(c0 * c0 + c1 * c1);
    if ((tid & 31) == 0) sbuf[tid >> 5] = ss;
    __syncthreads();
    float var = 0.f;
    #pragma unroll
    for (int i = 0; i < 8; i++) var += sbuf[i];
    var *= (1.f / DMODEL);
    float rs = rsqrtf(var + EPSF);
    float r0 = c0 * rs * w[tid] + b[tid];
    float r1 = c1 * rs * w[tid + 256] + b[tid + 256];
    __nv_bfloat16 h, l;
    cvt_hl(r0, h, l); oh[o0] = h; ol[o0] = l;
    cvt_hl(r1, h, l); oh[o1] = h; ol[o1] = l;
    if (of) { of[o0] = r0; of[o1] = r1; }
}

// ---------------- sliding-window causal conv + SiLU ----------------
__global__ void __launch_bounds__(128) conv2_k(
    const float* __restrict__ convw, const float* __restrict__ convb, int l)
{
    int c = blockIdx.x * 128 + threadIdx.x;
    bool act = (c < CONVDIM);
    int t0 = blockIdx.y * 64;
    int dir = blockIdx.z >> 1;
    int b = blockIdx.z & 1;
    float w[7], bias = 0.f;
    #pragma unroll
    for (int k = 0; k < 7; k++) w[k] = 0.f;
    if (act) {
        const float* wp = convw + ((long)((l * 2 + dir) * CONVDIM) + c) * DCONV;
        #pragma unroll
        for (int k = 0; k < 7; k++) w[k] = wp[k];
        bias = convb[(l * 2 + dir) * CONVDIM + c];
    }
    const float* in = g_zx[dir] + (long)b * SEQ * DINPROJ + DINNER + c;
    float* outp = g_xbc[dir] + (long)b * SEQ * CONVDIM + c;

    float win[7];
    if (dir == 0) {
        #pragma unroll
        for (int j = 1; j < 7; j++) {
            int t = t0 - j;
            win[j] = (act && t >= 0) ? in[(long)t * DINPROJ] : 0.f;
        }
        #pragma unroll 4
        for (int i = 0; i < 64; i++) {
            int o = t0 + i;
            win[0] = act ? in[(long)o * DINPROJ] : 0.f;
            float a = bias;
            #pragma unroll
            for (int j = 0; j < 7; j++) a += w[6 - j] * win[j];
            float sv = a / (1.f + expf(-a));
            if (act) outp[(long)o * CONVDIM] = sv;
            #pragma unroll
            for (int j = 6; j > 0; j--) win[j] = win[j - 1];
        }
    } else {
        #pragma unroll
        for (int j = 0; j < 6; j++) {
            int t = t0 + j;
            win[j] = (act && t < SEQ) ? in[(long)t * DINPROJ] : 0.f;
        }
        #pragma unroll 4
        for (int i = 0; i < 64; i++) {
            int o = t0 + i;
            int t = o + 6;
            win[6] = (act && t < SEQ) ? in[(long)t * DINPROJ] : 0.f;
            float a = bias;
            #pragma unroll
            for (int j = 0; j < 7; j++) a += w[6 - j] * win[j];
            float sv = a / (1.f + expf(-a));
            if (act) outp[(long)o * CONVDIM] = sv;
            #pragma unroll
            for (int j = 0; j < 6; j++) win[j] = win[j + 1];
        }
    }
}

// ---------------- scan phase A: chunk-local scan + inline dt/dA ------------
// grid: 1024 = dir*512 + b*256 + h*16 + chunk; 64 threads (p)
__global__ void __launch_bounds__(64) scanA_k(
    const float* __restrict__ Dp, const float* __restrict__ dt_bias,
    const float* __restrict__ A_log, int l)
{
    int bid = blockIdx.x;
    int chunk = bid & 15;
    int h = (bid >> 4) & 15;
    int b = (bid >> 8) & 1;
    int dir = bid >> 9;
    int p = threadIdx.x;
    const float* xbc = g_xbc[dir];
    const float* zx = g_zx[dir];
    float* yo = g_y[dir];
    float* cAo = g_cA[dir];
    const float Dv = Dp[(l * 2 + dir) * NHEADS + h];
    const float dtb = dt_bias[(l * 2 + dir) * NHEADS + h];
    const float Av = -expf(A_log[(l * 2 + dir) * NHEADS + h]);

    __shared__ float sdt64[64], sdA64[64];
    {
        int t = chunk * CL + p;
        int o = dir ? (SEQ - 1 - t) : t;
        float raw = zx[(long)(b * SEQ + o) * DINPROJ + DINNER + CONVDIM + h];
        float xv = raw + dtb;
        float dt = (xv > 20.f) ? xv : log1pf(expf(xv));
        sdt64[p] = dt;
        sdA64[p] = expf(dt * Av);
    }
    __syncthreads();

    float hs[16];
    #pragma unroll
    for (int n = 0; n < 16; n++) hs[n] = 0.f;
    float cumA = 1.f;
    __shared__ float sB[8][16], sC[8][16];

    for (int t8 = 0; t8 < CL; t8 += 8) {
        int tb = chunk * CL + t8;
        #pragma unroll
        for (int i = p; i < 128; i += 64) {
            int tt = i >> 4, n = i & 15;
            int o = dir ? (SEQ - 1 - (tb + tt)) : (tb + tt);
            long base = (long)(b * SEQ + o) * CONVDIM + DINNER;
            sB[tt][n] = xbc[base + n];
            sC[tt][n] = xbc[base + DSTATE + n];
        }
        __syncthreads();

        float xt[8];
        int oidx[8];
        #pragma unroll
        for (int j = 0; j < 8; j++) {
            int o = dir ? (SEQ - 1 - (tb + j)) : (tb + j);
            oidx[j] = o;
            xt[j] = xbc[(long)(b * SEQ + o) * CONVDIM + h * HEADDIM + p];
        }
        #pragma unroll
        for (int j = 0; j < 8; j++) {
            float dt = sdt64[t8 + j], dA = sdA64[t8 + j];
            float cdt = dt * xt[j];
            float y = 0.f;
            #pragma unroll
            for (int n = 0; n < 16; n++) {
                hs[n] = hs[n] * dA + cdt * sB[j][n];
                y += hs[n] * sC[j][n];
            }
            y += Dv * xt[j];
            yo[(long)(b * SEQ + oidx[j]) * DINNER + h * HEADDIM + p] = y;  // pre-gate
            cumA *= dA;
            if (p == 0) cAo[((long)(b * SEQ) + tb + j) * NHEADS + h] = cumA;
        }
        __syncthreads();
    }
    long sbase = ((((long)(dir * 2 + b) * 16 + h) * CH + chunk) * 64 + p) * 16;
    #pragma unroll
    for (int n = 0; n < 16; n++) g_S[sbase + n] = hs[n];
}

// ---------------- scan phase B: sequential chunk combine -------------------
__global__ void __launch_bounds__(64) scanB_k()
{
    int bid = blockIdx.x;
    int h = bid & 15;
    int b = (bid >> 4) & 1;
    int dir = bid >> 5;
    int p = threadIdx.x;
    const float* cAo = g_cA[dir];
    float H[16];
    #pragma unroll
    for (int n = 0; n < 16; n++) H[n] = 0.f;
    for (int c = 0; c < CH; c++) {
        long base = ((((long)(dir * 2 + b) * 16 + h) * CH + c) * 64 + p) * 16;
        #pragma unroll
        for (int n = 0; n < 16; n++) g_Hc[base + n] = H[n];
        float P = cAo[((long)(b * SEQ) + c * CL + CL - 1) * NHEADS + h];
        #pragma unroll
        for (int n = 0; n < 16; n++) H[n] = P * H[n] + g_S[base + n];
    }
}

// ---------------- scan phase C: fixup + gate ----------------
__global__ void __launch_bounds__(64) scanC_k(int l)
{
    int bid = blockIdx.x;
    int chunk = bid & 15;
    int h = (bid >> 4) & 15;
    int b = (bid >> 8) & 1;
    int dir = bid >> 9;
    int p = threadIdx.x;
    const float* xbc = g_xbc[dir];
    const float* zx = g_zx[dir];
    const float* cAo = g_cA[dir];
    float* yo = g_y[dir];
    float H[16];
    long hbase = ((((long)(dir * 2 + b) * 16 + h) * CH + chunk) * 64 + p) * 16;
    #pragma unroll
    for (int n = 0; n < 16; n++) H[n] = g_Hc[hbase + n];
    __shared__ float sC[8][16], scA[8];

    for (int t8 = 0; t8 < CL; t8 += 8) {
        int tb = chunk * CL + t8;
        #pragma unroll
        for (int i = p; i < 128; i += 64) {
            int tt = i >> 4, n = i & 15;
            int o = dir ? (SEQ - 1 - (tb + tt)) : (tb + tt);
            sC[tt][n] = xbc[(long)(b * SEQ + o) * CONVDIM + DINNER + DSTATE + n];
        }
        if (p < 8)
            scA[p] = cAo[((long)(b * SEQ) + tb + p) * NHEADS + h];
        __syncthreads();

        float yp[8], zt[8];
        int oidx[8];
        #pragma unroll
        for (int j = 0; j < 8; j++) {
            int o = dir ? (SEQ - 1 - (tb + j)) : (tb + j);
            oidx[j] = o;
            yp[j] = yo[(long)(b * SEQ + o) * DINNER + h * HEADDIM + p];
            zt[j] = zx[(long)(b * SEQ + o) * DINPROJ + h * HEADDIM + p];
        }
        #pragma unroll
        for (int j = 0; j < 8; j++) {
            float dot = 0.f;
            #pragma unroll
            for (int n = 0; n < 16; n++) dot += H[n] * sC[j][n];
            float y = yp[j] + scA[j] * dot;
            float z = zt[j];
            float sil = z / (1.f + expf(-z));
            yo[(long)(b * SEQ + oidx[j]) * DINNER + h * HEADDIM + p] = y * sil;
        }
        __syncthreads();
    }
}

// ---------------- RMS norm (1024) -> bf16 hi/lo (per dir) ------------------
__global__ void __launch_bounds__(256) rms_hl_k(const float* __restrict__ normw, int l)
{
    __shared__ float sbuf[8];
    int bid = blockIdx.x;
    int dir = bid >> 11;
    int tok = bid & (NTOK - 1);
    int tid = threadIdx.x;
    const float* v = g_y[dir] + (long)tok * DINNER;
    const float* w = normw + (l * 2 + dir) * DINNER;
    float vals[4];
    float ss = 0.f;
    #pragma unroll
    for (int i = 0; i < 4; i++) {
        vals[i] = v[tid + i * 256];
        ss += vals[i] * vals[i];
    }
    ss = warpSum(ss);
    if ((tid & 31) == 0) sbuf[tid >> 5] = ss;
    __syncthreads();
    float tot = 0.f;
    #pragma unroll
    for (int i = 0; i < 8; i++) tot += sbuf[i];
    float rs = rsqrtf(tot * (1.f / DINNER) + EPSF);
    #pragma unroll
    for (int i = 0; i < 4; i++) {
        float sv = vals[i] * rs * w[tid + i * 256];
        __nv_bfloat16 h, l2;
        cvt_hl(sv, h, l2);
        long o = (long)tok * DINNER + tid + i * 256;
        g_yh[dir][o] = h;
        g_yl[dir][o] = l2;
    }
}

// ---------------- launch ----------------
extern "C" void kernel_launch(void* const* d_in, const int* in_sizes, int n_in,
                              void* d_out, int out_size)
{
    const float* x      = (const float*)d_in[0];
    const float* Wpi    = (const float*)d_in[1];
    const float* bpi    = (const float*)d_in[2];
    const float* ln_w   = (const float*)d_in[3];
    const float* ln_b   = (const float*)d_in[4];
    const float* Win    = (const float*)d_in[5];
    const float* convw  = (const float*)d_in[6];
    const float* convb  = (const float*)d_in[7];
    const float* dt_bias= (const float*)d_in[8];
    const float* A_log  = (const float*)d_in[9];
    const float* Dp     = (const float*)d_in[10];
    const float* normw  = (const float*)d_in[11];
    const float* Wout   = (const float*)d_in[12];
    const float* fn_w   = (const float*)d_in[13];
    const float* fn_b   = (const float*)d_in[14];
    const float* Wpo    = (const float*)d_in[15];
    const float* bpo    = (const float*)d_in[16];
    float* out = (float*)d_out;

    cudaFuncSetAttribute(gemm5<false, true>,  cudaFuncAttributeMaxDynamicSharedMemorySize, GSMEM);
    cudaFuncSetAttribute(gemm5<false, false>, cudaFuncAttributeMaxDynamicSharedMemorySize, GSMEM);

    float *ph, *pzx, *pyt;
    __nv_bfloat16 *pxh, *pxl, *phnh, *phnl, *pyh, *pyl, *phfh, *phfl;
    __nv_bfloat16 *pwinh, *pwinl, *pwouth, *pwoutl, *pwpih, *pwpil, *pwpoh, *pwpol;
    cudaGetSymbolAddress((void**)&ph,     g_h);
    cudaGetSymbolAddress((void**)&pzx,    g_zx);
    cudaGetSymbolAddress((void**)&pyt,    g_ytmp);
    cudaGetSymbolAddress((void**)&pxh,    g_xh);
    cudaGetSymbolAddress((void**)&pxl,    g_xl);
    cudaGetSymbolAddress((void**)&phnh,   g_hnh);
    cudaGetSymbolAddress((void**)&phnl,   g_hnl);
    cudaGetSymbolAddress((void**)&pyh,    g_yh);
    cudaGetSymbolAddress((void**)&pyl,    g_yl);
    cudaGetSymbolAddress((void**)&phfh,   g_hfh);
    cudaGetSymbolAddress((void**)&phfl,   g_hfl);
    cudaGetSymbolAddress((void**)&pwinh,  g_winh);
    cudaGetSymbolAddress((void**)&pwinl,  g_winl);
    cudaGetSymbolAddress((void**)&pwouth, g_wouth);
    cudaGetSymbolAddress((void**)&pwoutl, g_woutl);
    cudaGetSymbolAddress((void**)&pwpih,  g_wpih);
    cudaGetSymbolAddress((void**)&pwpil,  g_wpil);
    cudaGetSymbolAddress((void**)&pwpoh,  g_wpoh);
    cudaGetSymbolAddress((void**)&pwpol,  g_wpol);

    // ---- one mega convert (weights + x) ----
    cvt_all_k<<<(int)((SEG4 + 255) / 256), 256>>>(Wpi, Win, Wout, Wpo, x);

    // ---- input proj: h = x @ Wpi + bpi ----
    gemm5<false, true><<<dim3(4, 16, 1), 256, GSMEM>>>(
        pxh, pxl, pwpih, pwpil, bpi, ph, DMODEL, KPI, 0, 0, 0);

    for (int l = 0; l < 2; l++) {
        if (l == 0)
            layernorm_hl_k<false><<<NTOK, 256>>>(ph, nullptr, nullptr,
                ln_w, ln_b, phnh, phnl, nullptr);
        else
            layernorm_hl_k<true><<<NTOK, 256>>>(ph, pyt, pyt + (long)NTOK*DMODEL,
                ln_w + l*DMODEL, ln_b + l*DMODEL, phnh, phnl, nullptr);
        gemm5<false, false><<<dim3(17, 16, 2), 256, GSMEM>>>(
            phnh, phnl,
            pwinh + (long)l*2*DMODEL*DINPROJ, pwinl + (long)l*2*DMODEL*DINPROJ,
            nullptr, pzx, DINPROJ, DMODEL,
            0, (long)DMODEL*DINPROJ, (long)NTOK*DINPROJ);
        conv2_k<<<dim3(9, SEQ/64, 4), 128>>>(convw, convb, l);
        scanA_k<<<1024, 64>>>(Dp, dt_bias, A_log, l);
        scanB_k<<<64, 64>>>();
        scanC_k<<<1024, 64>>>(l);
        rms_hl_k<<<2*NTOK, 256>>>(normw, l);
        // ytmp[dir] = y[dir] @ Wout[l,dir]  (batched z=2)
        gemm5<false, false><<<dim3(4, 16, 2), 256, GSMEM>>>(
            pyh, pyl,
            pwouth + (long)l*2*DINNER*DMODEL, pwoutl + (long)l*2*DINNER*DMODEL,
            nullptr, pyt, DMODEL, DINNER,
            (long)NTOK*DINNER, (long)DINNER*DMODEL, (long)NTOK*DMODEL);
    }

    // final: LN(h + yt0 + yt1) -> bf16 hi/lo + fp32 straight into out tail
    layernorm_hl_k<true><<<NTOK, 256>>>(ph, pyt, pyt + (long)NTOK*DMODEL,
        fn_w, fn_b, phfh, phfl, out + (long)NTOK*FEAT);
    gemm5<false, true><<<dim3(1, 16, 1), 256, GSMEM>>>(
        phfh, phfl, pwpoh, pwpol, bpo, out, FEAT, DMODEL, 0, 0, 0);
}

// round 10
// speedup vs baseline: 1.1088x; 1.0187x over previous
#include <cuda_runtime.h>
#include <cuda_bf16.h>
#include <math.h>
#include <stdint.h>

#define BATCH 2
#define SEQ 1024
#define FEAT 80
#define DMODEL 512
#define DSTATE 16
#define DCONV 7
#define HEADDIM 64
#define DINNER 1024
#define NHEADS 16
#define CONVDIM 1056
#define DINPROJ 2096
#define NTOK (BATCH*SEQ)
#define EPSF 1e-5f
#define KPI 128
#define CH 16            // scan chunks
#define CL 64            // steps per chunk

// ---------------- scratch ----------------
__device__ float g_h[NTOK*DMODEL];
__device__ float g_zx[2][NTOK*DINPROJ];
__device__ float g_xbc[2][NTOK*CONVDIM];
__device__ float g_y[2][NTOK*DINNER];
__device__ float g_ytmp[4][NTOK*DMODEL];    // [dir*2 + khalf]

__device__ float g_S[2*2*16*CH*64*16];
__device__ float g_Hc[2*2*16*CH*64*16];
__device__ float g_cA[2][NTOK*NHEADS];

__device__ __nv_bfloat16 g_hnh[NTOK*DMODEL],  g_hnl[NTOK*DMODEL];
__device__ __nv_bfloat16 g_xh[NTOK*KPI],      g_xl[NTOK*KPI];
__device__ __nv_bfloat16 g_yh[2][NTOK*DINNER],g_yl[2][NTOK*DINNER];
__device__ __nv_bfloat16 g_hfh[NTOK*DMODEL],  g_hfl[NTOK*DMODEL];

__device__ __nv_bfloat16 g_winh[4L*DMODEL*DINPROJ], g_winl[4L*DMODEL*DINPROJ];
__device__ __nv_bfloat16 g_wouth[4L*DINNER*DMODEL], g_woutl[4L*DINNER*DMODEL];
__device__ __nv_bfloat16 g_wpih[KPI*DMODEL],        g_wpil[KPI*DMODEL];
__device__ __nv_bfloat16 g_wpoh[DMODEL*FEAT],       g_wpol[DMODEL*FEAT];

// ---------------- helpers ----------------
__device__ __forceinline__ void cvt_hl(float v, __nv_bfloat16& h, __nv_bfloat16& l) {
    h = __float2bfloat16_rn(v);
    l = __float2bfloat16_rn(v - __bfloat162float(h));
}
__device__ __forceinline__ uint32_t smem_u32(const void* p) {
    uint32_t a;
    asm("{ .reg .u64 t; cvta.to.shared.u64 t, %1; cvt.u32.u64 %0, t; }" : "=r"(a) : "l"(p));
    return a;
}
__device__ __forceinline__ void cpa16(uint32_t dst, const void* src) {
    asm volatile("cp.async.cg.shared.global [%0], [%1], 16;" :: "r"(dst), "l"(src));
}
__device__ __forceinline__ void ldsm_x4(unsigned r[4], uint32_t addr) {
    asm volatile("ldmatrix.sync.aligned.m8n8.x4.shared.b16 {%0,%1,%2,%3}, [%4];"
        : "=r"(r[0]), "=r"(r[1]), "=r"(r[2]), "=r"(r[3]) : "r"(addr));
}
__device__ __forceinline__ void ldsm_x2t(unsigned r[2], uint32_t addr) {
    asm volatile("ldmatrix.sync.aligned.m8n8.x2.trans.shared.b16 {%0,%1}, [%2];"
        : "=r"(r[0]), "=r"(r[1]) : "r"(addr));
}
__device__ __forceinline__ void mma16816(float d[4], const unsigned a[4], const unsigned b[2]) {
    asm volatile("mma.sync.aligned.m16n8k16.row.col.f32.bf16.bf16.f32 "
        "{%0,%1,%2,%3}, {%4,%5,%6,%7}, {%8,%9}, {%0,%1,%2,%3};"
        : "+f"(d[0]), "+f"(d[1]), "+f"(d[2]), "+f"(d[3])
        : "r"(a[0]), "r"(a[1]), "r"(a[2]), "r"(a[3]), "r"(b[0]), "r"(b[1]));
}

// ---------------- GEMM: BM=128, BN=128, BK=32, 256 thr, 2 CTAs/SM ----------
// C[M,N](+)= A[M,K]@B[K,N] (+bias), bf16 hi/lo 3-pass.
// A row stride = lda (>= K; supports split-K slices of wider rows).
// z decomposes as zh = z/zdiv, zl = z%zdiv with separate stride pairs.
#define ASTR 80
#define BSTR 272
#define OFF_AL 10240
#define OFF_BH 20480
#define STAGE 37888
#define GSMEM (2*STAGE)

__device__ __forceinline__ void g5_stage(
    uint32_t sb, const __nv_bfloat16* Ah, const __nv_bfloat16* Al,
    const __nv_bfloat16* Bh, const __nv_bfloat16* Bl,
    int m0, int n0, int k0, int N, int lda, int tid)
{
    #pragma unroll
    for (int q = 0; q < 2; q++) {
        int idx = q * 256 + tid, row = idx >> 2, seg = idx & 3;
        uint32_t d = sb + row * ASTR + seg * 16;
        const __nv_bfloat16* s = Ah + (size_t)(m0 + row) * lda + k0 + seg * 8;
        cpa16(d, s);
        cpa16(d + OFF_AL, Al + (s - Ah));
    }
    #pragma unroll
    for (int q = 0; q < 2; q++) {
        int idx = q * 256 + tid, row = idx >> 4, seg = idx & 15;
        uint32_t d = sb + OFF_BH + row * BSTR + seg * 16;
        if (n0 + seg * 8 < N) {
            const __nv_bfloat16* s = Bh + (size_t)(k0 + row) * N + n0 + seg * 8;
            cpa16(d, s);
            cpa16(d + 8704, Bl + (s - Bh));
        } else {
            asm volatile("st.shared.v4.b32 [%0], {%1,%1,%1,%1};" :: "r"(d), "r"(0) : "memory");
            asm volatile("st.shared.v4.b32 [%0], {%1,%1,%1,%1};" :: "r"(d + 8704), "r"(0) : "memory");
        }
    }
    asm volatile("cp.async.commit_group;" ::: "memory");
}

template<bool ACCUM, bool BIAS>
__global__ void __launch_bounds__(256, 2) gemm5(
    const __nv_bfloat16* __restrict__ Ah, const __nv_bfloat16* __restrict__ Al,
    const __nv_bfloat16* __restrict__ Bh, const __nv_bfloat16* __restrict__ Bl,
    const float* __restrict__ bias, float* __restrict__ C,
    int N, int K, int lda,
    long azH, long bzH, long czH,
    long azL, long bzL, long czL, int zdiv)
{
    extern __shared__ char dsm[];
    const int zh = blockIdx.z / zdiv, zl = blockIdx.z % zdiv;
    Ah += (long)zh * azH + (long)zl * azL;
    Al += (long)zh * azH + (long)zl * azL;
    Bh += (long)zh * bzH + (long)zl * bzL;
    Bl += (long)zh * bzH + (long)zl * bzL;
    C  += (long)zh * czH + (long)zl * czL;
    const int m0 = blockIdx.y * 128, n0 = blockIdx.x * 128;
    const int tid = threadIdx.x, warp = tid >> 5, lane = tid & 31;
    const int wm = (warp & 1) * 64, wn = (warp >> 1) * 32;
    const uint32_t raw = smem_u32(dsm);

    float acc[4][4][4];
    #pragma unroll
    for (int f = 0; f < 4; f++)
        #pragma unroll
        for (int g = 0; g < 4; g++)
            #pragma unroll
            for (int i = 0; i < 4; i++) acc[f][g][i] = 0.f;

    const int nch = K >> 5;
    g5_stage(raw, Ah, Al, Bh, Bl, m0, n0, 0, N, lda, tid);

    for (int c = 0; c < nch; c++) {
        if (c + 1 < nch) {
            g5_stage(raw + (uint32_t)((c + 1) & 1) * STAGE,
                     Ah, Al, Bh, Bl, m0, n0, (c + 1) << 5, N, lda, tid);
            asm volatile("cp.async.wait_group 1;" ::: "memory");
        } else {
            asm volatile("cp.async.wait_group 0;" ::: "memory");
        }
        __syncthreads();

        const uint32_t sb = raw + (uint32_t)(c & 1) * STAGE;
        #pragma unroll
        for (int ks = 0; ks < 2; ks++) {
            const int kk = ks * 16;
            unsigned ah[4][4], al[4][4], bh[4][2], bl[4][2];
            #pragma unroll
            for (int f = 0; f < 4; f++) {
                int row = wm + f * 16 + (lane & 15);
                int col = kk + ((lane >> 4) << 3);
                uint32_t a = sb + row * ASTR + col * 2;
                ldsm_x4(ah[f], a);
                ldsm_x4(al[f], a + OFF_AL);
            }
            #pragma unroll
            for (int g = 0; g < 4; g++) {
                int row = kk + (lane & 15);
                int col = wn + g * 8;
                uint32_t a = sb + OFF_BH + row * BSTR + col * 2;
                ldsm_x2t(bh[g], a);
                ldsm_x2t(bl[g], a + 8704);
            }
            #pragma unroll
            for (int f = 0; f < 4; f++)
                #pragma unroll
                for (int g = 0; g < 4; g++) {
                    mma16816(acc[f][g], ah[f], bh[g]);
                    mma16816(acc[f][g], al[f], bh[g]);
                    mma16816(acc[f][g], ah[f], bl[g]);
                }
        }
        __syncthreads();
    }

    const int cr = lane >> 2, cc = (lane & 3) * 2;
    #pragma unroll
    for (int f = 0; f < 4; f++) {
        #pragma unroll
        for (int g = 0; g < 4; g++) {
            int mmb = m0 + wm + f * 16 + cr;
            int nn = n0 + wn + g * 8 + cc;
            #pragma unroll
            for (int half = 0; half < 2; half++) {
                int m = mmb + half * 8;
                #pragma unroll
                for (int j = 0; j < 2; j++) {
                    if (nn + j < N) {
                        float v = acc[f][g][half * 2 + j];
                        long o = (long)m * N + nn + j;
                        if (BIAS) v += bias[nn + j];
                        if (ACCUM) v += C[o];
                        C[o] = v;
                    }
                }
            }
        }
    }
}

// ---------------- mega convert: all weights + x -> bf16 hi/lo --------------
#define SEG0 ((long)KPI*DMODEL)
#define SEG1 (SEG0 + 4L*DMODEL*DINPROJ)
#define SEG2 (SEG1 + 4L*DINNER*DMODEL)
#define SEG3 (SEG2 + (long)DMODEL*FEAT)
#define SEG4 (SEG3 + (long)NTOK*KPI)

__global__ void __launch_bounds__(256) cvt_all_k(
    const float* __restrict__ Wpi, const float* __restrict__ Win,
    const float* __restrict__ Wout, const float* __restrict__ Wpo,
    const float* __restrict__ x)
{
    long i = (long)blockIdx.x * 256 + threadIdx.x;
    if (i >= SEG4) return;
    float v;
    __nv_bfloat16 *dh, *dl;
    long o;
    if (i < SEG0) {                    // Wpi padded [KPI][DMODEL]
        long k = i / DMODEL, n = i - k * DMODEL;
        v = (k < FEAT) ? Wpi[k * DMODEL + n] : 0.f;
        dh = g_wpih; dl = g_wpil; o = i;
    } else if (i < SEG1) {             // Win flat
        o = i - SEG0; v = Win[o]; dh = g_winh; dl = g_winl;
    } else if (i < SEG2) {             // Wout flat
        o = i - SEG1; v = Wout[o]; dh = g_wouth; dl = g_woutl;
    } else if (i < SEG3) {             // Wpo flat
        o = i - SEG2; v = Wpo[o]; dh = g_wpoh; dl = g_wpol;
    } else {                           // x padded [NTOK][KPI]
        o = i - SEG3;
        long r = o >> 7, c = o & (KPI - 1);
        v = (c < FEAT) ? x[r * FEAT + c] : 0.f;
        dh = g_xh; dl = g_xl;
    }
    __nv_bfloat16 h, l;
    cvt_hl(v, h, l);
    dh[o] = h; dl[o] = l;
}

// ---------------- reductions ----------------
__device__ __forceinline__ float warpSum(float v) {
    #pragma unroll
    for (int o = 16; o; o >>= 1) v += __shfl_down_sync(0xffffffffu, v, o);
    return v;
}

// ---------------- layernorm (+optional 4-way residual add) -> bf16 hi/lo ---
// RES: x = h + yt[0] + yt[1] + yt[2] + yt[3]; writes summed value back to h.
template<bool RES>
__global__ void __launch_bounds__(256) layernorm_hl_k(
    float* __restrict__ hio, const float* __restrict__ ytbase,
    const float* __restrict__ w, const float* __restrict__ b,
    __nv_bfloat16* __restrict__ oh, __nv_bfloat16* __restrict__ ol,
    float* __restrict__ of)
{
    __shared__ float sbuf[8];
    int row = blockIdx.x, tid = threadIdx.x;
    long o0 = (long)row * DMODEL + tid, o1 = o0 + 256;
    float x0 = hio[o0], x1 = hio[o1];
    if (RES) {
        #pragma unroll
        for (int r = 0; r < 4; r++) {
            x0 += ytbase[(long)r * NTOK * DMODEL + o0];
            x1 += ytbase[(long)r * NTOK * DMODEL + o1];
        }
        hio[o0] = x0; hio[o1] = x1;
    }
    float s = warpSum(x0 + x1);
    if ((tid & 31) == 0) sbuf[tid >> 5] = s;
    __syncthreads();
    float mean = 0.f;
    #pragma unroll
    for (int i = 0; i < 8; i++) mean += sbuf[i];
    mean *= (1.f / DMODEL);
    __syncthreads();
    float c0 = x0 - mean, c1 = x1 - mean;
    float ss = warpSum(c0 * c0 + c1 * c1);
    if ((tid & 31) == 0) sbuf[tid >> 5] = ss;
    __syncthreads();
    float var = 0.f;
    #pragma unroll
    for (int i = 0; i < 8; i++) var += sbuf[i];
    var *= (1.f / DMODEL);
    float rs = rsqrtf(var + EPSF);
    float r0 = c0 * rs * w[tid] + b[tid];
    float r1 = c1 * rs * w[tid + 256] + b[tid + 256];
    __nv_bfloat16 h, l;
    cvt_hl(r0, h, l); oh[o0] = h; ol[o0] = l;
    cvt_hl(r1, h, l); oh[o1] = h; ol[o1] = l;
    if (of) { of[o0] = r0; of[o1] = r1; }
}

// ---------------- sliding-window causal conv + SiLU ----------------
__global__ void __launch_bounds__(128) conv2_k(
    const float* __restrict__ convw, const float* __restrict__ convb, int l)
{
    int c = blockIdx.x * 128 + threadIdx.x;
    bool act = (c < CONVDIM);
    int t0 = blockIdx.y * 64;
    int dir = blockIdx.z >> 1;
    int b = blockIdx.z & 1;
    float w[7], bias = 0.f;
    #pragma unroll
    for (int k = 0; k < 7; k++) w[k] = 0.f;
    if (act) {
        const float* wp = convw + ((long)((l * 2 + dir) * CONVDIM) + c) * DCONV;
        #pragma unroll
        for (int k = 0; k < 7; k++) w[k] = wp[k];
        bias = convb[(l * 2 + dir) * CONVDIM + c];
    }
    const float* in = g_zx[dir] + (long)b * SEQ * DINPROJ + DINNER + c;
    float* outp = g_xbc[dir] + (long)b * SEQ * CONVDIM + c;

    float win[7];
    if (dir == 0) {
        #pragma unroll
        for (int j = 1; j < 7; j++) {
            int t = t0 - j;
            win[j] = (act && t >= 0) ? in[(long)t * DINPROJ] : 0.f;
        }
        #pragma unroll 4
        for (int i = 0; i < 64; i++) {
            int o = t0 + i;
            win[0] = act ? in[(long)o * DINPROJ] : 0.f;
            float a = bias;
            #pragma unroll
            for (int j = 0; j < 7; j++) a += w[6 - j] * win[j];
            float sv = a / (1.f + expf(-a));
            if (act) outp[(long)o * CONVDIM] = sv;
            #pragma unroll
            for (int j = 6; j > 0; j--) win[j] = win[j - 1];
        }
    } else {
        #pragma unroll
        for (int j = 0; j < 6; j++) {
            int t = t0 + j;
            win[j] = (act && t < SEQ) ? in[(long)t * DINPROJ] : 0.f;
        }
        #pragma unroll 4
        for (int i = 0; i < 64; i++) {
            int o = t0 + i;
            int t = o + 6;
            win[6] = (act && t < SEQ) ? in[(long)t * DINPROJ] : 0.f;
            float a = bias;
            #pragma unroll
            for (int j = 0; j < 7; j++) a += w[6 - j] * win[j];
            float sv = a / (1.f + expf(-a));
            if (act) outp[(long)o * CONVDIM] = sv;
            #pragma unroll
            for (int j = 0; j < 6; j++) win[j] = win[j + 1];
        }
    }
}

// ---------------- scan phase A: chunk-local scan + inline dt/dA ------------
// grid: 1024 = dir*512 + b*256 + h*16 + chunk; 64 threads (p)
__global__ void __launch_bounds__(64) scanA_k(
    const float* __restrict__ Dp, const float* __restrict__ dt_bias,
    const float* __restrict__ A_log, int l)
{
    int bid = blockIdx.x;
    int chunk = bid & 15;
    int h = (bid >> 4) & 15;
    int b = (bid >> 8) & 1;
    int dir = bid >> 9;
    int p = threadIdx.x;
    const float* xbc = g_xbc[dir];
    const float* zx = g_zx[dir];
    float* yo = g_y[dir];
    float* cAo = g_cA[dir];
    const float Dv = Dp[(l * 2 + dir) * NHEADS + h];
    const float dtb = dt_bias[(l * 2 + dir) * NHEADS + h];
    const float Av = -expf(A_log[(l * 2 + dir) * NHEADS + h]);

    __shared__ float sdt64[64], sdA64[64];
    {
        int t = chunk * CL + p;
        int o = dir ? (SEQ - 1 - t) : t;
        float raw = zx[(long)(b * SEQ + o) * DINPROJ + DINNER + CONVDIM + h];
        float xv = raw + dtb;
        float dt = (xv > 20.f) ? xv : log1pf(expf(xv));
        sdt64[p] = dt;
        sdA64[p] = expf(dt * Av);
    }
    __syncthreads();

    float hs[16];
    #pragma unroll
    for (int n = 0; n < 16; n++) hs[n] = 0.f;
    float cumA = 1.f;
    __shared__ float sB[8][16], sC[8][16];

    for (int t8 = 0; t8 < CL; t8 += 8) {
        int tb = chunk * CL + t8;
        #pragma unroll
        for (int i = p; i < 128; i += 64) {
            int tt = i >> 4, n = i & 15;
            int o = dir ? (SEQ - 1 - (tb + tt)) : (tb + tt);
            long base = (long)(b * SEQ + o) * CONVDIM + DINNER;
            sB[tt][n] = xbc[base + n];
            sC[tt][n] = xbc[base + DSTATE + n];
        }
        __syncthreads();

        float xt[8];
        int oidx[8];
        #pragma unroll
        for (int j = 0; j < 8; j++) {
            int o = dir ? (SEQ - 1 - (tb + j)) : (tb + j);
            oidx[j] = o;
            xt[j] = xbc[(long)(b * SEQ + o) * CONVDIM + h * HEADDIM + p];
        }
        #pragma unroll
        for (int j = 0; j < 8; j++) {
            float dt = sdt64[t8 + j], dA = sdA64[t8 + j];
            float cdt = dt * xt[j];
            float y = 0.f;
            #pragma unroll
            for (int n = 0; n < 16; n++) {
                hs[n] = hs[n] * dA + cdt * sB[j][n];
                y += hs[n] * sC[j][n];
            }
            y += Dv * xt[j];
            yo[(long)(b * SEQ + oidx[j]) * DINNER + h * HEADDIM + p] = y;  // pre-gate
            cumA *= dA;
            if (p == 0) cAo[((long)(b * SEQ) + tb + j) * NHEADS + h] = cumA;
        }
        __syncthreads();
    }
    long sbase = ((((long)(dir * 2 + b) * 16 + h) * CH + chunk) * 64 + p) * 16;
    #pragma unroll
    for (int n = 0; n < 16; n++) g_S[sbase + n] = hs[n];
}

// ---------------- scan phase B: sequential chunk combine -------------------
__global__ void __launch_bounds__(64) scanB_k()
{
    int bid = blockIdx.x;
    int h = bid & 15;
    int b = (bid >> 4) & 1;
    int dir = bid >> 5;
    int p = threadIdx.x;
    const float* cAo = g_cA[dir];
    float H[16];
    #pragma unroll
    for (int n = 0; n < 16; n++) H[n] = 0.f;
    for (int c = 0; c < CH; c++) {
        long base = ((((long)(dir * 2 + b) * 16 + h) * CH + c) * 64 + p) * 16;
        #pragma unroll
        for (int n = 0; n < 16; n++) g_Hc[base + n] = H[n];
        float P = cAo[((long)(b * SEQ) + c * CL + CL - 1) * NHEADS + h];
        #pragma unroll
        for (int n = 0; n < 16; n++) H[n] = P * H[n] + g_S[base + n];
    }
}

// ---------------- scan phase C: fixup + gate ----------------
__global__ void __launch_bounds__(64) scanC_k(int l)
{
    int bid = blockIdx.x;
    int chunk = bid & 15;
    int h = (bid >> 4) & 15;
    int b = (bid >> 8) & 1;
    int dir = bid >> 9;
    int p = threadIdx.x;
    const float* xbc = g_xbc[dir];
    const float* zx = g_zx[dir];
    const float* cAo = g_cA[dir];
    float* yo = g_y[dir];
    float H[16];
    long hbase = ((((long)(dir * 2 + b) * 16 + h) * CH + chunk) * 64 + p) * 16;
    #pragma unroll
    for (int n = 0; n < 16; n++) H[n] = g_Hc[hbase + n];
    __shared__ float sC[8][16], scA[8];

    for (int t8 = 0; t8 < CL; t8 += 8) {
        int tb = chunk * CL + t8;
        #pragma unroll
        for (int i = p; i < 128; i += 64) {
            int tt = i >> 4, n = i & 15;
            int o = dir ? (SEQ - 1 - (tb + tt)) : (tb + tt);
            sC[tt][n] = xbc[(long)(b * SEQ + o) * CONVDIM + DINNER + DSTATE + n];
        }
        if (p < 8)
            scA[p] = cAo[((long)(b * SEQ) + tb + p) * NHEADS + h];
        __syncthreads();

        float yp[8], zt[8];
        int oidx[8];
        #pragma unroll
        for (int j = 0; j < 8; j++) {
            int o = dir ? (SEQ - 1 - (tb + j)) : (tb + j);
            oidx[j] = o;
            yp[j] = yo[(long)(b * SEQ + o) * DINNER + h * HEADDIM + p];
            zt[j] = zx[(long)(b * SEQ + o) * DINPROJ + h * HEADDIM + p];
        }
        #pragma unroll
        for (int j = 0; j < 8; j++) {
            float dot = 0.f;
            #pragma unroll
            for (int n = 0; n < 16; n++) dot += H[n] * sC[j][n];
            float y = yp[j] + scA[j] * dot;
            float z = zt[j];
            float sil = z / (1.f + expf(-z));
            yo[(long)(b * SEQ + oidx[j]) * DINNER + h * HEADDIM + p] = y * sil;
        }
        __syncthreads();
    }
}

// ---------------- RMS norm (1024) -> bf16 hi/lo (per dir) ------------------
__global__ void __launch_bounds__(256) rms_hl_k(const float* __restrict__ normw, int l)
{
    __shared__ float sbuf[8];
    int bid = blockIdx.x;
    int dir = bid >> 11;
    int tok = bid & (NTOK - 1);
    int tid = threadIdx.x;
    const float* v = g_y[dir] + (long)tok * DINNER;
    const float* w = normw + (l * 2 + dir) * DINNER;
    float vals[4];
    float ss = 0.f;
    #pragma unroll
    for (int i = 0; i < 4; i++) {
        vals[i] = v[tid + i * 256];
        ss += vals[i] * vals[i];
    }
    ss = warpSum(ss);
    if ((tid & 31) == 0) sbuf[tid >> 5] = ss;
    __syncthreads();
    float tot = 0.f;
    #pragma unroll
    for (int i = 0; i < 8; i++) tot += sbuf[i];
    float rs = rsqrtf(tot * (1.f / DINNER) + EPSF);
    #pragma unroll
    for (int i = 0; i < 4; i++) {
        float sv = vals[i] * rs * w[tid + i * 256];
        __nv_bfloat16 h, l2;
        cvt_hl(sv, h, l2);
        long o = (long)tok * DINNER + tid + i * 256;
        g_yh[dir][o] = h;
        g_yl[dir][o] = l2;
    }
}

// ---------------- launch ----------------
extern "C" void kernel_launch(void* const* d_in, const int* in_sizes, int n_in,
                              void* d_out, int out_size)
{
    const float* x      = (const float*)d_in[0];
    const float* Wpi    = (const float*)d_in[1];
    const float* bpi    = (const float*)d_in[2];
    const float* ln_w   = (const float*)d_in[3];
    const float* ln_b   = (const float*)d_in[4];
    const float* Win    = (const float*)d_in[5];
    const float* convw  = (const float*)d_in[6];
    const float* convb  = (const float*)d_in[7];
    const float* dt_bias= (const float*)d_in[8];
    const float* A_log  = (const float*)d_in[9];
    const float* Dp     = (const float*)d_in[10];
    const float* normw  = (const float*)d_in[11];
    const float* Wout   = (const float*)d_in[12];
    const float* fn_w   = (const float*)d_in[13];
    const float* fn_b   = (const float*)d_in[14];
    const float* Wpo    = (const float*)d_in[15];
    const float* bpo    = (const float*)d_in[16];
    float* out = (float*)d_out;

    cudaFuncSetAttribute(gemm5<false, true>,  cudaFuncAttributeMaxDynamicSharedMemorySize, GSMEM);
    cudaFuncSetAttribute(gemm5<false, false>, cudaFuncAttributeMaxDynamicSharedMemorySize, GSMEM);

    float *ph, *pzx, *pyt;
    __nv_bfloat16 *pxh, *pxl, *phnh, *phnl, *pyh, *pyl, *phfh, *phfl;
    __nv_bfloat16 *pwinh, *pwinl, *pwouth, *pwoutl, *pwpih, *pwpil, *pwpoh, *pwpol;
    cudaGetSymbolAddress((void**)&ph,     g_h);
    cudaGetSymbolAddress((void**)&pzx,    g_zx);
    cudaGetSymbolAddress((void**)&pyt,    g_ytmp);
    cudaGetSymbolAddress((void**)&pxh,    g_xh);
    cudaGetSymbolAddress((void**)&pxl,    g_xl);
    cudaGetSymbolAddress((void**)&phnh,   g_hnh);
    cudaGetSymbolAddress((void**)&phnl,   g_hnl);
    cudaGetSymbolAddress((void**)&pyh,    g_yh);
    cudaGetSymbolAddress((void**)&pyl,    g_yl);
    cudaGetSymbolAddress((void**)&phfh,   g_hfh);
    cudaGetSymbolAddress((void**)&phfl,   g_hfl);
    cudaGetSymbolAddress((void**)&pwinh,  g_winh);
    cudaGetSymbolAddress((void**)&pwinl,  g_winl);
    cudaGetSymbolAddress((void**)&pwouth, g_wouth);
    cudaGetSymbolAddress((void**)&pwoutl, g_woutl);
    cudaGetSymbolAddress((void**)&pwpih,  g_wpih);
    cudaGetSymbolAddress((void**)&pwpil,  g_wpil);
    cudaGetSymbolAddress((void**)&pwpoh,  g_wpoh);
    cudaGetSymbolAddress((void**)&pwpol,  g_wpol);

    // ---- one mega convert (weights + x) ----
    cvt_all_k<<<(int)((SEG4 + 255) / 256), 256>>>(Wpi, Win, Wout, Wpo, x);

    // ---- input proj: h = x @ Wpi + bpi ----
    gemm5<false, true><<<dim3(4, 16, 1), 256, GSMEM>>>(
        pxh, pxl, pwpih, pwpil, bpi, ph, DMODEL, KPI, KPI,
        0, 0, 0, 0, 0, 0, 1);

    for (int l = 0; l < 2; l++) {
        if (l == 0)
            layernorm_hl_k<false><<<NTOK, 256>>>(ph, nullptr,
                ln_w, ln_b, phnh, phnl, nullptr);
        else
            layernorm_hl_k<true><<<NTOK, 256>>>(ph, pyt,
                ln_w + l*DMODEL, ln_b + l*DMODEL, phnh, phnl, nullptr);
        // in-proj: z = dir
        gemm5<false, false><<<dim3(17, 16, 2), 256, GSMEM>>>(
            phnh, phnl,
            pwinh + (long)l*2*DMODEL*DINPROJ, pwinl + (long)l*2*DMODEL*DINPROJ,
            nullptr, pzx, DINPROJ, DMODEL, DMODEL,
            0, (long)DMODEL*DINPROJ, (long)NTOK*DINPROJ,
            0, 0, 0, 1);
        conv2_k<<<dim3(9, SEQ/64, 4), 128>>>(convw, convb, l);
        scanA_k<<<1024, 64>>>(Dp, dt_bias, A_log, l);
        scanB_k<<<64, 64>>>();
        scanC_k<<<1024, 64>>>(l);
        rms_hl_k<<<2*NTOK, 256>>>(normw, l);
        // out-proj split-K: z = dir*2 + khalf; K=512 per CTA, lda=DINNER
        gemm5<false, false><<<dim3(4, 16, 4), 256, GSMEM>>>(
            pyh, pyl,
            pwouth + (long)l*2*DINNER*DMODEL, pwoutl + (long)l*2*DINNER*DMODEL,
            nullptr, pyt, DMODEL, 512, DINNER,
            (long)NTOK*DINNER, (long)DINNER*DMODEL, 2L*NTOK*DMODEL,
            512, 512L*DMODEL, (long)NTOK*DMODEL, 2);
    }

    // final: LN(h + yt0..3) -> bf16 hi/lo + fp32 straight into out tail
    layernorm_hl_k<true><<<NTOK, 256>>>(ph, pyt,
        fn_w, fn_b, phfh, phfl, out + (long)NTOK*FEAT);
    gemm5<false, true><<<dim3(1, 16, 1), 256, GSMEM>>>(
        phfh, phfl, pwpoh, pwpol, bpo, out, FEAT, DMODEL, DMODEL,
        0, 0, 0, 0, 0, 0, 1);
}

// round 11
// speedup vs baseline: 1.2808x; 1.1552x over previous
#include <cuda_runtime.h>
#include <cuda_fp16.h>
#include <math.h>
#include <stdint.h>

#define BATCH 2
#define SEQ 1024
#define FEAT 80
#define DMODEL 512
#define DSTATE 16
#define DCONV 7
#define HEADDIM 64
#define DINNER 1024
#define NHEADS 16
#define CONVDIM 1056
#define DINPROJ 2096
#define NTOK (BATCH*SEQ)
#define EPSF 1e-5f
#define KPI 128
#define CH 16            // scan chunks
#define CL 64            // steps per chunk

// ---------------- scratch ----------------
__device__ float g_h[NTOK*DMODEL];
__device__ float g_zx[2][NTOK*DINPROJ];
__device__ float g_xbc[2][NTOK*CONVDIM];
__device__ float g_y[2][NTOK*DINNER];
__device__ float g_ytmp[4][NTOK*DMODEL];    // [dir*2 + khalf]

__device__ float g_S[2*2*16*CH*64*16];
__device__ float g_Hc[2*2*16*CH*64*16];
__device__ float g_cA[2][NTOK*NHEADS];

__device__ __half g_hnh[NTOK*DMODEL],  g_hnl[NTOK*DMODEL];
__device__ __half g_xh[NTOK*KPI],      g_xl[NTOK*KPI];
__device__ __half g_yh[2][NTOK*DINNER],g_yl[2][NTOK*DINNER];
__device__ __half g_hfh[NTOK*DMODEL],  g_hfl[NTOK*DMODEL];

// weights: hi-only fp16, [K][N] layout, K padded where needed
__device__ __half g_winh[4L*DMODEL*DINPROJ];
__device__ __half g_wouth[4L*DINNER*DMODEL];
__device__ __half g_wpih[KPI*DMODEL];
__device__ __half g_wpoh[DMODEL*FEAT];

// ---------------- helpers ----------------
__device__ __forceinline__ void cvt_hl(float v, __half& h, __half& l) {
    h = __float2half_rn(v);
    l = __float2half_rn(v - __half2float(h));
}
__device__ __forceinline__ uint32_t smem_u32(const void* p) {
    uint32_t a;
    asm("{ .reg .u64 t; cvta.to.shared.u64 t, %1; cvt.u32.u64 %0, t; }" : "=r"(a) : "l"(p));
    return a;
}
__device__ __forceinline__ void cpa16(uint32_t dst, const void* src) {
    asm volatile("cp.async.cg.shared.global [%0], [%1], 16;" :: "r"(dst), "l"(src));
}
__device__ __forceinline__ void ldsm_x4(unsigned r[4], uint32_t addr) {
    asm volatile("ldmatrix.sync.aligned.m8n8.x4.shared.b16 {%0,%1,%2,%3}, [%4];"
        : "=r"(r[0]), "=r"(r[1]), "=r"(r[2]), "=r"(r[3]) : "r"(addr));
}
__device__ __forceinline__ void ldsm_x2t(unsigned r[2], uint32_t addr) {
    asm volatile("ldmatrix.sync.aligned.m8n8.x2.trans.shared.b16 {%0,%1}, [%2];"
        : "=r"(r[0]), "=r"(r[1]) : "r"(addr));
}
__device__ __forceinline__ void mma16816h(float d[4], const unsigned a[4], const unsigned b[2]) {
    asm volatile("mma.sync.aligned.m16n8k16.row.col.f32.f16.f16.f32 "
        "{%0,%1,%2,%3}, {%4,%5,%6,%7}, {%8,%9}, {%0,%1,%2,%3};"
        : "+f"(d[0]), "+f"(d[1]), "+f"(d[2]), "+f"(d[3])
        : "r"(a[0]), "r"(a[1]), "r"(a[2]), "r"(a[3]), "r"(b[0]), "r"(b[1]));
}

// ---------------- GEMM: BM=128, BN=128, BK=32, 256 thr, 2 CTAs/SM ----------
// C[M,N](+)= A[M,K]@B[K,N] (+bias), fp16 2-pass: A hi/lo, B hi only.
// A row stride = lda (>= K; supports split-K slices of wider rows).
// z decomposes as zh = z/zdiv, zl = z%zdiv with separate stride pairs.
#define ASTR 80
#define BSTR 272
#define OFF_AL 10240
#define OFF_BH 20480
#define STAGE 29184
#define GSMEM (2*STAGE)

__device__ __forceinline__ void g5_stage(
    uint32_t sb, const __half* Ah, const __half* Al, const __half* Bh,
    int m0, int n0, int k0, int N, int lda, int tid)
{
    #pragma unroll
    for (int q = 0; q < 2; q++) {
        int idx = q * 256 + tid, row = idx >> 2, seg = idx & 3;
        uint32_t d = sb + row * ASTR + seg * 16;
        const __half* s = Ah + (size_t)(m0 + row) * lda + k0 + seg * 8;
        cpa16(d, s);
        cpa16(d + OFF_AL, Al + (s - Ah));
    }
    #pragma unroll
    for (int q = 0; q < 2; q++) {
        int idx = q * 256 + tid, row = idx >> 4, seg = idx & 15;
        uint32_t d = sb + OFF_BH + row * BSTR + seg * 16;
        if (n0 + seg * 8 < N) {
            cpa16(d, Bh + (size_t)(k0 + row) * N + n0 + seg * 8);
        } else {
            asm volatile("st.shared.v4.b32 [%0], {%1,%1,%1,%1};" :: "r"(d), "r"(0) : "memory");
        }
    }
    asm volatile("cp.async.commit_group;" ::: "memory");
}

template<bool ACCUM, bool BIAS>
__global__ void __launch_bounds__(256, 2) gemm5(
    const __half* __restrict__ Ah, const __half* __restrict__ Al,
    const __half* __restrict__ Bh,
    const float* __restrict__ bias, float* __restrict__ C,
    int N, int K, int lda,
    long azH, long bzH, long czH,
    long azL, long bzL, long czL, int zdiv)
{
    extern __shared__ char dsm[];
    const int zh = blockIdx.z / zdiv, zl = blockIdx.z % zdiv;
    Ah += (long)zh * azH + (long)zl * azL;
    Al += (long)zh * azH + (long)zl * azL;
    Bh += (long)zh * bzH + (long)zl * bzL;
    C  += (long)zh * czH + (long)zl * czL;
    const int m0 = blockIdx.y * 128, n0 = blockIdx.x * 128;
    const int tid = threadIdx.x, warp = tid >> 5, lane = tid & 31;
    const int wm = (warp & 1) * 64, wn = (warp >> 1) * 32;
    const uint32_t raw = smem_u32(dsm);

    float acc[4][4][4];
    #pragma unroll
    for (int f = 0; f < 4; f++)
        #pragma unroll
        for (int g = 0; g < 4; g++)
            #pragma unroll
            for (int i = 0; i < 4; i++) acc[f][g][i] = 0.f;

    const int nch = K >> 5;
    g5_stage(raw, Ah, Al, Bh, m0, n0, 0, N, lda, tid);

    for (int c = 0; c < nch; c++) {
        if (c + 1 < nch) {
            g5_stage(raw + (uint32_t)((c + 1) & 1) * STAGE,
                     Ah, Al, Bh, m0, n0, (c + 1) << 5, N, lda, tid);
            asm volatile("cp.async.wait_group 1;" ::: "memory");
        } else {
            asm volatile("cp.async.wait_group 0;" ::: "memory");
        }
        __syncthreads();

        const uint32_t sb = raw + (uint32_t)(c & 1) * STAGE;
        #pragma unroll
        for (int ks = 0; ks < 2; ks++) {
            const int kk = ks * 16;
            unsigned ah[4][4], al[4][4], bh[4][2];
            #pragma unroll
            for (int f = 0; f < 4; f++) {
                int row = wm + f * 16 + (lane & 15);
                int col = kk + ((lane >> 4) << 3);
                uint32_t a = sb + row * ASTR + col * 2;
                ldsm_x4(ah[f], a);
                ldsm_x4(al[f], a + OFF_AL);
            }
            #pragma unroll
            for (int g = 0; g < 4; g++) {
                int row = kk + (lane & 15);
                int col = wn + g * 8;
                ldsm_x2t(bh[g], sb + OFF_BH + row * BSTR + col * 2);
            }
            #pragma unroll
            for (int f = 0; f < 4; f++)
                #pragma unroll
                for (int g = 0; g < 4; g++) {
                    mma16816h(acc[f][g], ah[f], bh[g]);
                    mma16816h(acc[f][g], al[f], bh[g]);
                }
        }
        __syncthreads();
    }

    const int cr = lane >> 2, cc = (lane & 3) * 2;
    #pragma unroll
    for (int f = 0; f < 4; f++) {
        #pragma unroll
        for (int g = 0; g < 4; g++) {
            int mmb = m0 + wm + f * 16 + cr;
            int nn = n0 + wn + g * 8 + cc;
            #pragma unroll
            for (int half = 0; half < 2; half++) {
                int m = mmb + half * 8;
                #pragma unroll
                for (int j = 0; j < 2; j++) {
                    if (nn + j < N) {
                        float v = acc[f][g][half * 2 + j];
                        long o = (long)m * N + nn + j;
                        if (BIAS) v += bias[nn + j];
                        if (ACCUM) v += C[o];
                        C[o] = v;
                    }
                }
            }
        }
    }
}

// ---------------- mega convert: weights (hi) + x (hi/lo) -> fp16 -----------
#define SEG0 ((long)KPI*DMODEL)
#define SEG1 (SEG0 + 4L*DMODEL*DINPROJ)
#define SEG2 (SEG1 + 4L*DINNER*DMODEL)
#define SEG3 (SEG2 + (long)DMODEL*FEAT)
#define SEG4 (SEG3 + (long)NTOK*KPI)

__global__ void __launch_bounds__(256) cvt_all_k(
    const float* __restrict__ Wpi, const float* __restrict__ Win,
    const float* __restrict__ Wout, const float* __restrict__ Wpo,
    const float* __restrict__ x)
{
    long i = (long)blockIdx.x * 256 + threadIdx.x;
    if (i >= SEG4) return;
    if (i < SEG0) {                    // Wpi padded [KPI][DMODEL]
        long k = i / DMODEL, n = i - k * DMODEL;
        float v = (k < FEAT) ? Wpi[k * DMODEL + n] : 0.f;
        g_wpih[i] = __float2half_rn(v);
    } else if (i < SEG1) {             // Win flat
        long o = i - SEG0;
        g_winh[o] = __float2half_rn(Win[o]);
    } else if (i < SEG2) {             // Wout flat
        long o = i - SEG1;
        g_wouth[o] = __float2half_rn(Wout[o]);
    } else if (i < SEG3) {             // Wpo flat
        long o = i - SEG2;
        g_wpoh[o] = __float2half_rn(Wpo[o]);
    } else {                           // x padded [NTOK][KPI], hi/lo
        long o = i - SEG3;
        long r = o >> 7, c = o & (KPI - 1);
        float v = (c < FEAT) ? x[r * FEAT + c] : 0.f;
        __half h, l;
        cvt_hl(v, h, l);
        g_xh[o] = h; g_xl[o] = l;
    }
}

// ---------------- reductions ----------------
__device__ __forceinline__ float warpSum(float v) {
    #pragma unroll
    for (int o = 16; o; o >>= 1) v += __shfl_down_sync(0xffffffffu, v, o);
    return v;
}

// ---------------- layernorm (+optional 4-way residual add) -> fp16 hi/lo ---
// RES: x = h + yt[0..3]; writes summed value back to h (next residual).
template<bool RES>
__global__ void __launch_bounds__(256) layernorm_hl_k(
    float* __restrict__ hio, const float* __restrict__ ytbase,
    const float* __restrict__ w, const float* __restrict__ b,
    __half* __restrict__ oh, __half* __restrict__ ol,
    float* __restrict__ of)
{
    __shared__ float sbuf[8];
    int row = blockIdx.x, tid = threadIdx.x;
    long o0 = (long)row * DMODEL + tid, o1 = o0 + 256;
    float x0 = hio[o0], x1 = hio[o1];
    if (RES) {
        #pragma unroll
        for (int r = 0; r < 4; r++) {
            x0 += ytbase[(long)r * NTOK * DMODEL + o0];
            x1 += ytbase[(long)r * NTOK * DMODEL + o1];
        }
        hio[o0] = x0; hio[o1] = x1;
    }
    float s = warpSum(x0 + x1);
    if ((tid & 31) == 0) sbuf[tid >> 5] = s;
    __syncthreads();
    float mean = 0.f;
    #pragma unroll
    for (int i = 0; i < 8; i++) mean += sbuf[i];
    mean *= (1.f / DMODEL);
    __syncthreads();
    float c0 = x0 - mean, c1 = x1 - mean;
    float ss = warpSum(c0 * c0 + c1 * c1);
    if ((tid & 31) == 0) sbuf[tid >> 5] = ss;
    __syncthreads();
    float var = 0.f;
    #pragma unroll
    for (int i = 0; i < 8; i++) var += sbuf[i];
    var *= (1.f / DMODEL);
    float rs = rsqrtf(var + EPSF);
    float r0 = c0 * rs * w[tid] + b[tid];
    float r1 = c1 * rs * w[tid + 256] + b[tid + 256];
    __half h, l;
    cvt_hl(r0, h, l); oh[o0] = h; ol[o0] = l;
    cvt_hl(r1, h, l); oh[o1] = h; ol[o1] = l;
    if (of) { of[o0] = r0; of[o1] = r1; }
}

// ---------------- sliding-window causal conv + SiLU ----------------
__global__ void __launch_bounds__(128) conv2_k(
    const float* __restrict__ convw, const float* __restrict__ convb, int l)
{
    int c = blockIdx.x * 128 + threadIdx.x;
    bool act = (c < CONVDIM);
    int t0 = blockIdx.y * 64;
    int dir = blockIdx.z >> 1;
    int b = blockIdx.z & 1;
    float w[7], bias = 0.f;
    #pragma unroll
    for (int k = 0; k < 7; k++) w[k] = 0.f;
    if (act) {
        const float* wp = convw + ((long)((l * 2 + dir) * CONVDIM) + c) * DCONV;
        #pragma unroll
        for (int k = 0; k < 7; k++) w[k] = wp[k];
        bias = convb[(l * 2 + dir) * CONVDIM + c];
    }
    const float* in = g_zx[dir] + (long)b * SEQ * DINPROJ + DINNER + c;
    float* outp = g_xbc[dir] + (long)b * SEQ * CONVDIM + c;

    float win[7];
    if (dir == 0) {
        #pragma unroll
        for (int j = 1; j < 7; j++) {
            int t = t0 - j;
            win[j] = (act && t >= 0) ? in[(long)t * DINPROJ] : 0.f;
        }
        #pragma unroll 4
        for (int i = 0; i < 64; i++) {
            int o = t0 + i;
            win[0] = act ? in[(long)o * DINPROJ] : 0.f;
            float a = bias;
            #pragma unroll
            for (int j = 0; j < 7; j++) a += w[6 - j] * win[j];
            float sv = a / (1.f + expf(-a));
            if (act) outp[(long)o * CONVDIM] = sv;
            #pragma unroll
            for (int j = 6; j > 0; j--) win[j] = win[j - 1];
        }
    } else {
        #pragma unroll
        for (int j = 0; j < 6; j++) {
            int t = t0 + j;
            win[j] = (act && t < SEQ) ? in[(long)t * DINPROJ] : 0.f;
        }
        #pragma unroll 4
        for (int i = 0; i < 64; i++) {
            int o = t0 + i;
            int t = o + 6;
            win[6] = (act && t < SEQ) ? in[(long)t * DINPROJ] : 0.f;
            float a = bias;
            #pragma unroll
            for (int j = 0; j < 7; j++) a += w[6 - j] * win[j];
            float sv = a / (1.f + expf(-a));
            if (act) outp[(long)o * CONVDIM] = sv;
            #pragma unroll
            for (int j = 0; j < 6; j++) win[j] = win[j + 1];
        }
    }
}

// ---------------- scan phase A: chunk-local scan + inline dt/dA ------------
// grid: 1024 = dir*512 + b*256 + h*16 + chunk; 64 threads (p)
__global__ void __launch_bounds__(64) scanA_k(
    const float* __restrict__ Dp, const float* __restrict__ dt_bias,
    const float* __restrict__ A_log, int l)
{
    int bid = blockIdx.x;
    int chunk = bid & 15;
    int h = (bid >> 4) & 15;
    int b = (bid >> 8) & 1;
    int dir = bid >> 9;
    int p = threadIdx.x;
    const float* xbc = g_xbc[dir];
    const float* zx = g_zx[dir];
    float* yo = g_y[dir];
    float* cAo = g_cA[dir];
    const float Dv = Dp[(l * 2 + dir) * NHEADS + h];
    const float dtb = dt_bias[(l * 2 + dir) * NHEADS + h];
    const float Av = -expf(A_log[(l * 2 + dir) * NHEADS + h]);

    __shared__ float sdt64[64], sdA64[64];
    {
        int t = chunk * CL + p;
        int o = dir ? (SEQ - 1 - t) : t;
        float raw = zx[(long)(b * SEQ + o) * DINPROJ + DINNER + CONVDIM + h];
        float xv = raw + dtb;
        float dt = (xv > 20.f) ? xv : log1pf(expf(xv));
        sdt64[p] = dt;
        sdA64[p] = expf(dt * Av);
    }
    __syncthreads();

    float hs[16];
    #pragma unroll
    for (int n = 0; n < 16; n++) hs[n] = 0.f;
    float cumA = 1.f;
    __shared__ float sB[8][16], sC[8][16];

    for (int t8 = 0; t8 < CL; t8 += 8) {
        int tb = chunk * CL + t8;
        #pragma unroll
        for (int i = p; i < 128; i += 64) {
            int tt = i >> 4, n = i & 15;
            int o = dir ? (SEQ - 1 - (tb + tt)) : (tb + tt);
            long base = (long)(b * SEQ + o) * CONVDIM + DINNER;
            sB[tt][n] = xbc[base + n];
            sC[tt][n] = xbc[base + DSTATE + n];
        }
        __syncthreads();

        float xt[8];
        int oidx[8];
        #pragma unroll
        for (int j = 0; j < 8; j++) {
            int o = dir ? (SEQ - 1 - (tb + j)) : (tb + j);
            oidx[j] = o;
            xt[j] = xbc[(long)(b * SEQ + o) * CONVDIM + h * HEADDIM + p];
        }
        #pragma unroll
        for (int j = 0; j < 8; j++) {
            float dt = sdt64[t8 + j], dA = sdA64[t8 + j];
            float cdt = dt * xt[j];
            float y = 0.f;
            #pragma unroll
            for (int n = 0; n < 16; n++) {
                hs[n] = hs[n] * dA + cdt * sB[j][n];
                y += hs[n] * sC[j][n];
            }
            y += Dv * xt[j];
            yo[(long)(b * SEQ + oidx[j]) * DINNER + h * HEADDIM + p] = y;  // pre-gate
            cumA *= dA;
            if (p == 0) cAo[((long)(b * SEQ) + tb + j) * NHEADS + h] = cumA;
        }
        __syncthreads();
    }
    long sbase = ((((long)(dir * 2 + b) * 16 + h) * CH + chunk) * 64 + p) * 16;
    #pragma unroll
    for (int n = 0; n < 16; n++) g_S[sbase + n] = hs[n];
}

// ---------------- scan phase B: sequential chunk combine -------------------
__global__ void __launch_bounds__(64) scanB_k()
{
    int bid = blockIdx.x;
    int h = bid & 15;
    int b = (bid >> 4) & 1;
    int dir = bid >> 5;
    int p = threadIdx.x;
    const float* cAo = g_cA[dir];
    float H[16];
    #pragma unroll
    for (int n = 0; n < 16; n++) H[n] = 0.f;
    for (int c = 0; c < CH; c++) {
        long base = ((((long)(dir * 2 + b) * 16 + h) * CH + c) * 64 + p) * 16;
        #pragma unroll
        for (int n = 0; n < 16; n++) g_Hc[base + n] = H[n];
        float P = cAo[((long)(b * SEQ) + c * CL + CL - 1) * NHEADS + h];
        #pragma unroll
        for (int n = 0; n < 16; n++) H[n] = P * H[n] + g_S[base + n];
    }
}

// ---------------- scan phase C: fixup + gate ----------------
__global__ void __launch_bounds__(64) scanC_k(int l)
{
    int bid = blockIdx.x;
    int chunk = bid & 15;
    int h = (bid >> 4) & 15;
    int b = (bid >> 8) & 1;
    int dir = bid >> 9;
    int p = threadIdx.x;
    const float* xbc = g_xbc[dir];
    const float* zx = g_zx[dir];
    const float* cAo = g_cA[dir];
    float* yo = g_y[dir];
    float H[16];
    long hbase = ((((long)(dir * 2 + b) * 16 + h) * CH + chunk) * 64 + p) * 16;
    #pragma unroll
    for (int n = 0; n < 16; n++) H[n] = g_Hc[hbase + n];
    __shared__ float sC[8][16], scA[8];

    for (int t8 = 0; t8 < CL; t8 += 8) {
        int tb = chunk * CL + t8;
        #pragma unroll
        for (int i = p; i < 128; i += 64) {
            int tt = i >> 4, n = i & 15;
            int o = dir ? (SEQ - 1 - (tb + tt)) : (tb + tt);
            sC[tt][n] = xbc[(long)(b * SEQ + o) * CONVDIM + DINNER + DSTATE + n];
        }
        if (p < 8)
            scA[p] = cAo[((long)(b * SEQ) + tb + p) * NHEADS + h];
        __syncthreads();

        float yp[8], zt[8];
        int oidx[8];
        #pragma unroll
        for (int j = 0; j < 8; j++) {
            int o = dir ? (SEQ - 1 - (tb + j)) : (tb + j);
            oidx[j] = o;
            yp[j] = yo[(long)(b * SEQ + o) * DINNER + h * HEADDIM + p];
            zt[j] = zx[(long)(b * SEQ + o) * DINPROJ + h * HEADDIM + p];
        }
        #pragma unroll
        for (int j = 0; j < 8; j++) {
            float dot = 0.f;
            #pragma unroll
            for (int n = 0; n < 16; n++) dot += H[n] * sC[j][n];
            float y = yp[j] + scA[j] * dot;
            float z = zt[j];
            float sil = z / (1.f + expf(-z));
            yo[(long)(b * SEQ + oidx[j]) * DINNER + h * HEADDIM + p] = y * sil;
        }
        __syncthreads();
    }
}

// ---------------- RMS norm (1024) -> fp16 hi/lo (per dir) ------------------
__global__ void __launch_bounds__(256) rms_hl_k(const float* __restrict__ normw, int l)
{
    __shared__ float sbuf[8];
    int bid = blockIdx.x;
    int dir = bid >> 11;
    int tok = bid & (NTOK - 1);
    int tid = threadIdx.x;
    const float* v = g_y[dir] + (long)tok * DINNER;
    const float* w = normw + (l * 2 + dir) * DINNER;
    float vals[4];
    float ss = 0.f;
    #pragma unroll
    for (int i = 0; i < 4; i++) {
        vals[i] = v[tid + i * 256];
        ss += vals[i] * vals[i];
    }
    ss = warpSum(ss);
    if ((tid & 31) == 0) sbuf[tid >> 5] = ss;
    __syncthreads();
    float tot = 0.f;
    #pragma unroll
    for (int i = 0; i < 8; i++) tot += sbuf[i];
    float rs = rsqrtf(tot * (1.f / DINNER) + EPSF);
    #pragma unroll
    for (int i = 0; i < 4; i++) {
        float sv = vals[i] * rs * w[tid + i * 256];
        __half h, l2;
        cvt_hl(sv, h, l2);
        long o = (long)tok * DINNER + tid + i * 256;
        g_yh[dir][o] = h;
        g_yl[dir][o] = l2;
    }
}

// ---------------- launch ----------------
extern "C" void kernel_launch(void* const* d_in, const int* in_sizes, int n_in,
                              void* d_out, int out_size)
{
    const float* x      = (const float*)d_in[0];
    const float* Wpi    = (const float*)d_in[1];
    const float* bpi    = (const float*)d_in[2];
    const float* ln_w   = (const float*)d_in[3];
    const float* ln_b   = (const float*)d_in[4];
    const float* Win    = (const float*)d_in[5];
    const float* convw  = (const float*)d_in[6];
    const float* convb  = (const float*)d_in[7];
    const float* dt_bias= (const float*)d_in[8];
    const float* A_log  = (const float*)d_in[9];
    const float* Dp     = (const float*)d_in[10];
    const float* normw  = (const float*)d_in[11];
    const float* Wout   = (const float*)d_in[12];
    const float* fn_w   = (const float*)d_in[13];
    const float* fn_b   = (const float*)d_in[14];
    const float* Wpo    = (const float*)d_in[15];
    const float* bpo    = (const float*)d_in[16];
    float* out = (float*)d_out;

    cudaFuncSetAttribute(gemm5<false, true>,  cudaFuncAttributeMaxDynamicSharedMemorySize, GSMEM);
    cudaFuncSetAttribute(gemm5<false, false>, cudaFuncAttributeMaxDynamicSharedMemorySize, GSMEM);

    float *ph, *pzx, *pyt;
    __half *pxh, *pxl, *phnh, *phnl, *pyh, *pyl, *phfh, *phfl;
    __half *pwinh, *pwouth, *pwpih, *pwpoh;
    cudaGetSymbolAddress((void**)&ph,     g_h);
    cudaGetSymbolAddress((void**)&pzx,    g_zx);
    cudaGetSymbolAddress((void**)&pyt,    g_ytmp);
    cudaGetSymbolAddress((void**)&pxh,    g_xh);
    cudaGetSymbolAddress((void**)&pxl,    g_xl);
    cudaGetSymbolAddress((void**)&phnh,   g_hnh);
    cudaGetSymbolAddress((void**)&phnl,   g_hnl);
    cudaGetSymbolAddress((void**)&pyh,    g_yh);
    cudaGetSymbolAddress((void**)&pyl,    g_yl);
    cudaGetSymbolAddress((void**)&phfh,   g_hfh);
    cudaGetSymbolAddress((void**)&phfl,   g_hfl);
    cudaGetSymbolAddress((void**)&pwinh,  g_winh);
    cudaGetSymbolAddress((void**)&pwouth, g_wouth);
    cudaGetSymbolAddress((void**)&pwpih,  g_wpih);
    cudaGetSymbolAddress((void**)&pwpoh,  g_wpoh);

    // ---- one mega convert (weights hi + x hi/lo) ----
    cvt_all_k<<<(int)((SEG4 + 255) / 256), 256>>>(Wpi, Win, Wout, Wpo, x);

    // ---- input proj: h = x @ Wpi + bpi ----
    gemm5<false, true><<<dim3(4, 16, 1), 256, GSMEM>>>(
        pxh, pxl, pwpih, bpi, ph, DMODEL, KPI, KPI,
        0, 0, 0, 0, 0, 0, 1);

    for (int l = 0; l < 2; l++) {
        if (l == 0)
            layernorm_hl_k<false><<<NTOK, 256>>>(ph, nullptr,
                ln_w, ln_b, phnh, phnl, nullptr);
        else
            layernorm_hl_k<true><<<NTOK, 256>>>(ph, pyt,
                ln_w + l*DMODEL, ln_b + l*DMODEL, phnh, phnl, nullptr);
        // in-proj: z = dir
        gemm5<false, false><<<dim3(17, 16, 2), 256, GSMEM>>>(
            phnh, phnl,
            pwinh + (long)l*2*DMODEL*DINPROJ,
            nullptr, pzx, DINPROJ, DMODEL, DMODEL,
            0, (long)DMODEL*DINPROJ, (long)NTOK*DINPROJ,
            0, 0, 0, 1);
        conv2_k<<<dim3(9, SEQ/64, 4), 128>>>(convw, convb, l);
        scanA_k<<<1024, 64>>>(Dp, dt_bias, A_log, l);
        scanB_k<<<64, 64>>>();
        scanC_k<<<1024, 64>>>(l);
        rms_hl_k<<<2*NTOK, 256>>>(normw, l);
        // out-proj split-K: z = dir*2 + khalf; K=512 per CTA, lda=DINNER
        gemm5<false, false><<<dim3(4, 16, 4), 256, GSMEM>>>(
            pyh, pyl,
            pwouth + (long)l*2*DINNER*DMODEL,
            nullptr, pyt, DMODEL, 512, DINNER,
            (long)NTOK*DINNER, (long)DINNER*DMODEL, 2L*NTOK*DMODEL,
            512, 512L*DMODEL, (long)NTOK*DMODEL, 2);
    }

    // final: LN(h + yt0..3) -> fp16 hi/lo + fp32 straight into out tail
    layernorm_hl_k<true><<<NTOK, 256>>>(ph, pyt,
        fn_w, fn_b, phfh, phfl, out + (long)NTOK*FEAT);
    gemm5<false, true><<<dim3(1, 16, 1), 256, GSMEM>>>(
        phfh, phfl, pwpoh, bpo, out, FEAT, DMODEL, DMODEL,
        0, 0, 0, 0, 0, 0, 1);
}

// round 12
// speedup vs baseline: 1.3087x; 1.0217x over previous
#include <cuda_runtime.h>
#include <cuda_fp16.h>
#include <math.h>
#include <stdint.h>

#define BATCH 2
#define SEQ 1024
#define FEAT 80
#define DMODEL 512
#define DSTATE 16
#define DCONV 7
#define HEADDIM 64
#define DINNER 1024
#define NHEADS 16
#define CONVDIM 1056
#define DINPROJ 2096
#define NTOK (BATCH*SEQ)
#define EPSF 1e-5f
#define KPI 128
#define CH 16            // scan chunks
#define CL 64            // steps per chunk

// ---------------- scratch ----------------
__device__ float g_h[NTOK*DMODEL];
__device__ float g_zx[2][NTOK*DINPROJ];
__device__ float g_xbc[2][NTOK*CONVDIM];
__device__ float g_y[2][NTOK*DINNER];
__device__ float g_ytmp[4][NTOK*DMODEL];    // [dir*2 + khalf]

__device__ float g_S[2*2*16*CH*64*16];
__device__ float g_Hc[2*2*16*CH*64*16];
__device__ float g_cA[2][NTOK*NHEADS];

__device__ __half g_hnh[NTOK*DMODEL],  g_hnl[NTOK*DMODEL];
__device__ __half g_xh[NTOK*KPI],      g_xl[NTOK*KPI];
__device__ __half g_yh[2][NTOK*DINNER],g_yl[2][NTOK*DINNER];
__device__ __half g_hfh[NTOK*DMODEL],  g_hfl[NTOK*DMODEL];

// weights: hi-only fp16, [K][N] layout, K padded where needed
__device__ __half g_winh[4L*DMODEL*DINPROJ];
__device__ __half g_wouth[4L*DINNER*DMODEL];
__device__ __half g_wpih[KPI*DMODEL];
__device__ __half g_wpoh[DMODEL*FEAT];

// ---------------- helpers ----------------
__device__ __forceinline__ void cvt_hl(float v, __half& h, __half& l) {
    h = __float2half_rn(v);
    l = __float2half_rn(v - __half2float(h));
}
__device__ __forceinline__ uint32_t smem_u32(const void* p) {
    uint32_t a;
    asm("{ .reg .u64 t; cvta.to.shared.u64 t, %1; cvt.u32.u64 %0, t; }" : "=r"(a) : "l"(p));
    return a;
}
__device__ __forceinline__ void cpa16(uint32_t dst, const void* src) {
    asm volatile("cp.async.cg.shared.global [%0], [%1], 16;" :: "r"(dst), "l"(src));
}
__device__ __forceinline__ void ldsm_x4(unsigned r[4], uint32_t addr) {
    asm volatile("ldmatrix.sync.aligned.m8n8.x4.shared.b16 {%0,%1,%2,%3}, [%4];"
        : "=r"(r[0]), "=r"(r[1]), "=r"(r[2]), "=r"(r[3]) : "r"(addr));
}
__device__ __forceinline__ void ldsm_x2t(unsigned r[2], uint32_t addr) {
    asm volatile("ldmatrix.sync.aligned.m8n8.x2.trans.shared.b16 {%0,%1}, [%2];"
        : "=r"(r[0]), "=r"(r[1]) : "r"(addr));
}
__device__ __forceinline__ void mma16816h(float d[4], const unsigned a[4], const unsigned b[2]) {
    asm volatile("mma.sync.aligned.m16n8k16.row.col.f32.f16.f16.f32 "
        "{%0,%1,%2,%3}, {%4,%5,%6,%7}, {%8,%9}, {%0,%1,%2,%3};"
        : "+f"(d[0]), "+f"(d[1]), "+f"(d[2]), "+f"(d[3])
        : "r"(a[0]), "r"(a[1]), "r"(a[2]), "r"(a[3]), "r"(b[0]), "r"(b[1]));
}

// ---------------- GEMM: BM=128, BN=128, BK=32, 256 thr, 2 CTAs/SM ----------
// C[M,N](+)= A[M,K]@B[K,N] (+bias), fp16 2-pass: A hi/lo, B hi only.
// 3-stage cp.async pipeline, ONE __syncthreads per chunk.
// A row stride = lda (>= K; supports split-K slices of wider rows).
// z decomposes as zh = z/zdiv, zl = z%zdiv with separate stride pairs.
#define ASTR 80
#define BSTR 272
#define OFF_AL 10240
#define OFF_BH 20480
#define STAGE 29184
#define GSMEM (3*STAGE)

__device__ __forceinline__ void g5_stage(
    uint32_t sb, const __half* Ah, const __half* Al, const __half* Bh,
    int m0, int n0, int k0, int N, int lda, int tid)
{
    #pragma unroll
    for (int q = 0; q < 2; q++) {
        int idx = q * 256 + tid, row = idx >> 2, seg = idx & 3;
        uint32_t d = sb + row * ASTR + seg * 16;
        const __half* s = Ah + (size_t)(m0 + row) * lda + k0 + seg * 8;
        cpa16(d, s);
        cpa16(d + OFF_AL, Al + (s - Ah));
    }
    #pragma unroll
    for (int q = 0; q < 2; q++) {
        int idx = q * 256 + tid, row = idx >> 4, seg = idx & 15;
        uint32_t d = sb + OFF_BH + row * BSTR + seg * 16;
        if (n0 + seg * 8 < N) {
            cpa16(d, Bh + (size_t)(k0 + row) * N + n0 + seg * 8);
        } else {
            asm volatile("st.shared.v4.b32 [%0], {%1,%1,%1,%1};" :: "r"(d), "r"(0) : "memory");
        }
    }
    asm volatile("cp.async.commit_group;" ::: "memory");
}

template<bool ACCUM, bool BIAS>
__global__ void __launch_bounds__(256, 2) gemm5(
    const __half* __restrict__ Ah, const __half* __restrict__ Al,
    const __half* __restrict__ Bh,
    const float* __restrict__ bias, float* __restrict__ C,
    int N, int K, int lda,
    long azH, long bzH, long czH,
    long azL, long bzL, long czL, int zdiv)
{
    extern __shared__ char dsm[];
    const int zh = blockIdx.z / zdiv, zl = blockIdx.z % zdiv;
    Ah += (long)zh * azH + (long)zl * azL;
    Al += (long)zh * azH + (long)zl * azL;
    Bh += (long)zh * bzH + (long)zl * bzL;
    C  += (long)zh * czH + (long)zl * czL;
    const int m0 = blockIdx.y * 128, n0 = blockIdx.x * 128;
    const int tid = threadIdx.x, warp = tid >> 5, lane = tid & 31;
    const int wm = (warp & 1) * 64, wn = (warp >> 1) * 32;
    const uint32_t raw = smem_u32(dsm);

    float acc[4][4][4];
    #pragma unroll
    for (int f = 0; f < 4; f++)
        #pragma unroll
        for (int g = 0; g < 4; g++)
            #pragma unroll
            for (int i = 0; i < 4; i++) acc[f][g][i] = 0.f;

    const int nch = K >> 5;
    g5_stage(raw, Ah, Al, Bh, m0, n0, 0, N, lda, tid);
    if (nch > 1)
        g5_stage(raw + STAGE, Ah, Al, Bh, m0, n0, 32, N, lda, tid);

    int sidx = 0;                 // stage index of chunk c
    for (int c = 0; c < nch; c++) {
        if (c + 1 < nch) {
            asm volatile("cp.async.wait_group 1;" ::: "memory");
        } else {
            asm volatile("cp.async.wait_group 0;" ::: "memory");
        }
        __syncthreads();
        if (c + 2 < nch) {
            int nidx = sidx + 2; if (nidx >= 3) nidx -= 3;
            g5_stage(raw + (uint32_t)nidx * STAGE,
                     Ah, Al, Bh, m0, n0, (c + 2) << 5, N, lda, tid);
        }

        const uint32_t sb = raw + (uint32_t)sidx * STAGE;
        #pragma unroll
        for (int ks = 0; ks < 2; ks++) {
            const int kk = ks * 16;
            unsigned ah[4][4], al[4][4], bh[4][2];
            #pragma unroll
            for (int f = 0; f < 4; f++) {
                int row = wm + f * 16 + (lane & 15);
                int col = kk + ((lane >> 4) << 3);
                uint32_t a = sb + row * ASTR + col * 2;
                ldsm_x4(ah[f], a);
                ldsm_x4(al[f], a + OFF_AL);
            }
            #pragma unroll
            for (int g = 0; g < 4; g++) {
                int row = kk + (lane & 15);
                int col = wn + g * 8;
                ldsm_x2t(bh[g], sb + OFF_BH + row * BSTR + col * 2);
            }
            #pragma unroll
            for (int f = 0; f < 4; f++)
                #pragma unroll
                for (int g = 0; g < 4; g++) {
                    mma16816h(acc[f][g], ah[f], bh[g]);
                    mma16816h(acc[f][g], al[f], bh[g]);
                }
        }
        sidx++; if (sidx >= 3) sidx -= 3;
    }

    const int cr = lane >> 2, cc = (lane & 3) * 2;
    #pragma unroll
    for (int f = 0; f < 4; f++) {
        #pragma unroll
        for (int g = 0; g < 4; g++) {
            int mmb = m0 + wm + f * 16 + cr;
            int nn = n0 + wn + g * 8 + cc;
            #pragma unroll
            for (int half = 0; half < 2; half++) {
                int m = mmb + half * 8;
                #pragma unroll
                for (int j = 0; j < 2; j++) {
                    if (nn + j < N) {
                        float v = acc[f][g][half * 2 + j];
                        long o = (long)m * N + nn + j;
                        if (BIAS) v += bias[nn + j];
                        if (ACCUM) v += C[o];
                        C[o] = v;
                    }
                }
            }
        }
    }
}

// ---------------- mega convert: weights (hi) + x (hi/lo) -> fp16 -----------
#define SEG0 ((long)KPI*DMODEL)
#define SEG1 (SEG0 + 4L*DMODEL*DINPROJ)
#define SEG2 (SEG1 + 4L*DINNER*DMODEL)
#define SEG3 (SEG2 + (long)DMODEL*FEAT)
#define SEG4 (SEG3 + (long)NTOK*KPI)

__global__ void __launch_bounds__(256) cvt_all_k(
    const float* __restrict__ Wpi, const float* __restrict__ Win,
    const float* __restrict__ Wout, const float* __restrict__ Wpo,
    const float* __restrict__ x)
{
    long i = (long)blockIdx.x * 256 + threadIdx.x;
    if (i >= SEG4) return;
    if (i < SEG0) {                    // Wpi padded [KPI][DMODEL]
        long k = i / DMODEL, n = i - k * DMODEL;
        float v = (k < FEAT) ? Wpi[k * DMODEL + n] : 0.f;
        g_wpih[i] = __float2half_rn(v);
    } else if (i < SEG1) {             // Win flat
        long o = i - SEG0;
        g_winh[o] = __float2half_rn(Win[o]);
    } else if (i < SEG2) {             // Wout flat
        long o = i - SEG1;
        g_wouth[o] = __float2half_rn(Wout[o]);
    } else if (i < SEG3) {             // Wpo flat
        long o = i - SEG2;
        g_wpoh[o] = __float2half_rn(Wpo[o]);
    } else {                           // x padded [NTOK][KPI], hi/lo
        long o = i - SEG3;
        long r = o >> 7, c = o & (KPI - 1);
        float v = (c < FEAT) ? x[r * FEAT + c] : 0.f;
        __half h, l;
        cvt_hl(v, h, l);
        g_xh[o] = h; g_xl[o] = l;
    }
}

// ---------------- reductions ----------------
__device__ __forceinline__ float warpSum(float v) {
    #pragma unroll
    for (int o = 16; o; o >>= 1) v += __shfl_down_sync(0xffffffffu, v, o);
    return v;
}

// ---------------- layernorm (+optional 4-way residual add) -> fp16 hi/lo ---
// RES: x = h + yt[0..3]; writes summed value back to h (next residual).
template<bool RES>
__global__ void __launch_bounds__(256) layernorm_hl_k(
    float* __restrict__ hio, const float* __restrict__ ytbase,
    const float* __restrict__ w, const float* __restrict__ b,
    __half* __restrict__ oh, __half* __restrict__ ol,
    float* __restrict__ of)
{
    __shared__ float sbuf[8];
    int row = blockIdx.x, tid = threadIdx.x;
    long o0 = (long)row * DMODEL + tid, o1 = o0 + 256;
    float x0 = hio[o0], x1 = hio[o1];
    if (RES) {
        #pragma unroll
        for (int r = 0; r < 4; r++) {
            x0 += ytbase[(long)r * NTOK * DMODEL + o0];
            x1 += ytbase[(long)r * NTOK * DMODEL + o1];
        }
        hio[o0] = x0; hio[o1] = x1;
    }
    float s = warpSum(x0 + x1);
    if ((tid & 31) == 0) sbuf[tid >> 5] = s;
    __syncthreads();
    float mean = 0.f;
    #pragma unroll
    for (int i = 0; i < 8; i++) mean += sbuf[i];
    mean *= (1.f / DMODEL);
    __syncthreads();
    float c0 = x0 - mean, c1 = x1 - mean;
    float ss = warpSum(c0 * c0 + c1 * c1);
    if ((tid & 31) == 0) sbuf[tid >> 5] = ss;
    __syncthreads();
    float var = 0.f;
    #pragma unroll
    for (int i = 0; i < 8; i++) var += sbuf[i];
    var *= (1.f / DMODEL);
    float rs = rsqrtf(var + EPSF);
    float r0 = c0 * rs * w[tid] + b[tid];
    float r1 = c1 * rs * w[tid + 256] + b[tid + 256];
    __half h, l;
    cvt_hl(r0, h, l); oh[o0] = h; ol[o0] = l;
    cvt_hl(r1, h, l); oh[o1] = h; ol[o1] = l;
    if (of) { of[o0] = r0; of[o1] = r1; }
}

// ---------------- sliding-window causal conv + SiLU ----------------
__global__ void __launch_bounds__(128) conv2_k(
    const float* __restrict__ convw, const float* __restrict__ convb, int l)
{
    int c = blockIdx.x * 128 + threadIdx.x;
    bool act = (c < CONVDIM);
    int t0 = blockIdx.y * 64;
    int dir = blockIdx.z >> 1;
    int b = blockIdx.z & 1;
    float w[7], bias = 0.f;
    #pragma unroll
    for (int k = 0; k < 7; k++) w[k] = 0.f;
    if (act) {
        const float* wp = convw + ((long)((l * 2 + dir) * CONVDIM) + c) * DCONV;
        #pragma unroll
        for (int k = 0; k < 7; k++) w[k] = wp[k];
        bias = convb[(l * 2 + dir) * CONVDIM + c];
    }
    const float* in = g_zx[dir] + (long)b * SEQ * DINPROJ + DINNER + c;
    float* outp = g_xbc[dir] + (long)b * SEQ * CONVDIM + c;

    float win[7];
    if (dir == 0) {
        #pragma unroll
        for (int j = 1; j < 7; j++) {
            int t = t0 - j;
            win[j] = (act && t >= 0) ? in[(long)t * DINPROJ] : 0.f;
        }
        #pragma unroll 4
        for (int i = 0; i < 64; i++) {
            int o = t0 + i;
            win[0] = act ? in[(long)o * DINPROJ] : 0.f;
            float a = bias;
            #pragma unroll
            for (int j = 0; j < 7; j++) a += w[6 - j] * win[j];
            float sv = a / (1.f + expf(-a));
            if (act) outp[(long)o * CONVDIM] = sv;
            #pragma unroll
            for (int j = 6; j > 0; j--) win[j] = win[j - 1];
        }
    } else {
        #pragma unroll
        for (int j = 0; j < 6; j++) {
            int t = t0 + j;
            win[j] = (act && t < SEQ) ? in[(long)t * DINPROJ] : 0.f;
        }
        #pragma unroll 4
        for (int i = 0; i < 64; i++) {
            int o = t0 + i;
            int t = o + 6;
            win[6] = (act && t < SEQ) ? in[(long)t * DINPROJ] : 0.f;
            float a = bias;
            #pragma unroll
            for (int j = 0; j < 7; j++) a += w[6 - j] * win[j];
            float sv = a / (1.f + expf(-a));
            if (act) outp[(long)o * CONVDIM] = sv;
            #pragma unroll
            for (int j = 0; j < 6; j++) win[j] = win[j + 1];
        }
    }
}

// ---------------- scan phase A: chunk-local scan + inline dt/dA ------------
// grid: 1024 = dir*512 + b*256 + h*16 + chunk; 64 threads (p)
__global__ void __launch_bounds__(64) scanA_k(
    const float* __restrict__ Dp, const float* __restrict__ dt_bias,
    const float* __restrict__ A_log, int l)
{
    int bid = blockIdx.x;
    int chunk = bid & 15;
    int h = (bid >> 4) & 15;
    int b = (bid >> 8) & 1;
    int dir = bid >> 9;
    int p = threadIdx.x;
    const float* xbc = g_xbc[dir];
    const float* zx = g_zx[dir];
    float* yo = g_y[dir];
    float* cAo = g_cA[dir];
    const float Dv = Dp[(l * 2 + dir) * NHEADS + h];
    const float dtb = dt_bias[(l * 2 + dir) * NHEADS + h];
    const float Av = -expf(A_log[(l * 2 + dir) * NHEADS + h]);

    __shared__ float sdt64[64], sdA64[64];
    {
        int t = chunk * CL + p;
        int o = dir ? (SEQ - 1 - t) : t;
        float raw = zx[(long)(b * SEQ + o) * DINPROJ + DINNER + CONVDIM + h];
        float xv = raw + dtb;
        float dt = (xv > 20.f) ? xv : log1pf(expf(xv));
        sdt64[p] = dt;
        sdA64[p] = expf(dt * Av);
    }
    __syncthreads();

    float hs[16];
    #pragma unroll
    for (int n = 0; n < 16; n++) hs[n] = 0.f;
    float cumA = 1.f;
    __shared__ float sB[8][16], sC[8][16];

    for (int t8 = 0; t8 < CL; t8 += 8) {
        int tb = chunk * CL + t8;
        #pragma unroll
        for (int i = p; i < 128; i += 64) {
            int tt = i >> 4, n = i & 15;
            int o = dir ? (SEQ - 1 - (tb + tt)) : (tb + tt);
            long base = (long)(b * SEQ + o) * CONVDIM + DINNER;
            sB[tt][n] = xbc[base + n];
            sC[tt][n] = xbc[base + DSTATE + n];
        }
        __syncthreads();

        float xt[8];
        int oidx[8];
        #pragma unroll
        for (int j = 0; j < 8; j++) {
            int o = dir ? (SEQ - 1 - (tb + j)) : (tb + j);
            oidx[j] = o;
            xt[j] = xbc[(long)(b * SEQ + o) * CONVDIM + h * HEADDIM + p];
        }
        #pragma unroll
        for (int j = 0; j < 8; j++) {
            float dt = sdt64[t8 + j], dA = sdA64[t8 + j];
            float cdt = dt * xt[j];
            float y = 0.f;
            #pragma unroll
            for (int n = 0; n < 16; n++) {
                hs[n] = hs[n] * dA + cdt * sB[j][n];
                y += hs[n] * sC[j][n];
            }
            y += Dv * xt[j];
            yo[(long)(b * SEQ + oidx[j]) * DINNER + h * HEADDIM + p] = y;  // pre-gate
            cumA *= dA;
            if (p == 0) cAo[((long)(b * SEQ) + tb + j) * NHEADS + h] = cumA;
        }
        __syncthreads();
    }
    long sbase = ((((long)(dir * 2 + b) * 16 + h) * CH + chunk) * 64 + p) * 16;
    #pragma unroll
    for (int n = 0; n < 16; n++) g_S[sbase + n] = hs[n];
}

// ---------------- scan phase B: sequential chunk combine -------------------
__global__ void __launch_bounds__(64) scanB_k()
{
    int bid = blockIdx.x;
    int h = bid & 15;
    int b = (bid >> 4) & 1;
    int dir = bid >> 5;
    int p = threadIdx.x;
    const float* cAo = g_cA[dir];
    float H[16];
    #pragma unroll
    for (int n = 0; n < 16; n++) H[n] = 0.f;
    for (int c = 0; c < CH; c++) {
        long base = ((((long)(dir * 2 + b) * 16 + h) * CH + c) * 64 + p) * 16;
        #pragma unroll
        for (int n = 0; n < 16; n++) g_Hc[base + n] = H[n];
        float P = cAo[((long)(b * SEQ) + c * CL + CL - 1) * NHEADS + h];
        #pragma unroll
        for (int n = 0; n < 16; n++) H[n] = P * H[n] + g_S[base + n];
    }
}

// ---------------- scan phase C: fixup + gate ----------------
__global__ void __launch_bounds__(64) scanC_k(int l)
{
    int bid = blockIdx.x;
    int chunk = bid & 15;
    int h = (bid >> 4) & 15;
    int b = (bid >> 8) & 1;
    int dir = bid >> 9;
    int p = threadIdx.x;
    const float* xbc = g_xbc[dir];
    const float* zx = g_zx[dir];
    const float* cAo = g_cA[dir];
    float* yo = g_y[dir];
    float H[16];
    long hbase = ((((long)(dir * 2 + b) * 16 + h) * CH + chunk) * 64 + p) * 16;
    #pragma unroll
    for (int n = 0; n < 16; n++) H[n] = g_Hc[hbase + n];
    __shared__ float sC[8][16], scA[8];

    for (int t8 = 0; t8 < CL; t8 += 8) {
        int tb = chunk * CL + t8;
        #pragma unroll
        for (int i = p; i < 128; i += 64) {
            int tt = i >> 4, n = i & 15;
            int o = dir ? (SEQ - 1 - (tb + tt)) : (tb + tt);
            sC[tt][n] = xbc[(long)(b * SEQ + o) * CONVDIM + DINNER + DSTATE + n];
        }
        if (p < 8)
            scA[p] = cAo[((long)(b * SEQ) + tb + p) * NHEADS + h];
        __syncthreads();

        float yp[8], zt[8];
        int oidx[8];
        #pragma unroll
        for (int j = 0; j < 8; j++) {
            int o = dir ? (SEQ - 1 - (tb + j)) : (tb + j);
            oidx[j] = o;
            yp[j] = yo[(long)(b * SEQ + o) * DINNER + h * HEADDIM + p];
            zt[j] = zx[(long)(b * SEQ + o) * DINPROJ + h * HEADDIM + p];
        }
        #pragma unroll
        for (int j = 0; j < 8; j++) {
            float dot = 0.f;
            #pragma unroll
            for (int n = 0; n < 16; n++) dot += H[n] * sC[j][n];
            float y = yp[j] + scA[j] * dot;
            float z = zt[j];
            float sil = z / (1.f + expf(-z));
            yo[(long)(b * SEQ + oidx[j]) * DINNER + h * HEADDIM + p] = y * sil;
        }
        __syncthreads();
    }
}

// ---------------- RMS norm (1024) -> fp16 hi/lo (per dir) ------------------
__global__ void __launch_bounds__(256) rms_hl_k(const float* __restrict__ normw, int l)
{
    __shared__ float sbuf[8];
    int bid = blockIdx.x;
    int dir = bid >> 11;
    int tok = bid & (NTOK - 1);
    int tid = threadIdx.x;
    const float* v = g_y[dir] + (long)tok * DINNER;
    const float* w = normw + (l * 2 + dir) * DINNER;
    float vals[4];
    float ss = 0.f;
    #pragma unroll
    for (int i = 0; i < 4; i++) {
        vals[i] = v[tid + i * 256];
        ss += vals[i] * vals[i];
    }
    ss = warpSum(ss);
    if ((tid & 31) == 0) sbuf[tid >> 5] = ss;
    __syncthreads();
    float tot = 0.f;
    #pragma unroll
    for (int i = 0; i < 8; i++) tot += sbuf[i];
    float rs = rsqrtf(tot * (1.f / DINNER) + EPSF);
    #pragma unroll
    for (int i = 0; i < 4; i++) {
        float sv = vals[i] * rs * w[tid + i * 256];
        __half h, l2;
        cvt_hl(sv, h, l2);
        long o = (long)tok * DINNER + tid + i * 256;
        g_yh[dir][o] = h;
        g_yl[dir][o] = l2;
    }
}

// ---------------- launch ----------------
extern "C" void kernel_launch(void* const* d_in, const int* in_sizes, int n_in,
                              void* d_out, int out_size)
{
    const float* x      = (const float*)d_in[0];
    const float* Wpi    = (const float*)d_in[1];
    const float* bpi    = (const float*)d_in[2];
    const float* ln_w   = (const float*)d_in[3];
    const float* ln_b   = (const float*)d_in[4];
    const float* Win    = (const float*)d_in[5];
    const float* convw  = (const float*)d_in[6];
    const float* convb  = (const float*)d_in[7];
    const float* dt_bias= (const float*)d_in[8];
    const float* A_log  = (const float*)d_in[9];
    const float* Dp     = (const float*)d_in[10];
    const float* normw  = (const float*)d_in[11];
    const float* Wout   = (const float*)d_in[12];
    const float* fn_w   = (const float*)d_in[13];
    const float* fn_b   = (const float*)d_in[14];
    const float* Wpo    = (const float*)d_in[15];
    const float* bpo    = (const float*)d_in[16];
    float* out = (float*)d_out;

    cudaFuncSetAttribute(gemm5<false, true>,  cudaFuncAttributeMaxDynamicSharedMemorySize, GSMEM);
    cudaFuncSetAttribute(gemm5<false, false>, cudaFuncAttributeMaxDynamicSharedMemorySize, GSMEM);

    float *ph, *pzx, *pyt;
    __half *pxh, *pxl, *phnh, *phnl, *pyh, *pyl, *phfh, *phfl;
    __half *pwinh, *pwouth, *pwpih, *pwpoh;
    cudaGetSymbolAddress((void**)&ph,     g_h);
    cudaGetSymbolAddress((void**)&pzx,    g_zx);
    cudaGetSymbolAddress((void**)&pyt,    g_ytmp);
    cudaGetSymbolAddress((void**)&pxh,    g_xh);
    cudaGetSymbolAddress((void**)&pxl,    g_xl);
    cudaGetSymbolAddress((void**)&phnh,   g_hnh);
    cudaGetSymbolAddress((void**)&phnl,   g_hnl);
    cudaGetSymbolAddress((void**)&pyh,    g_yh);
    cudaGetSymbolAddress((void**)&pyl,    g_yl);
    cudaGetSymbolAddress((void**)&phfh,   g_hfh);
    cudaGetSymbolAddress((void**)&phfl,   g_hfl);
    cudaGetSymbolAddress((void**)&pwinh,  g_winh);
    cudaGetSymbolAddress((void**)&pwouth, g_wouth);
    cudaGetSymbolAddress((void**)&pwpih,  g_wpih);
    cudaGetSymbolAddress((void**)&pwpoh,  g_wpoh);

    // ---- one mega convert (weights hi + x hi/lo) ----
    cvt_all_k<<<(int)((SEG4 + 255) / 256), 256>>>(Wpi, Win, Wout, Wpo, x);

    // ---- input proj: h = x @ Wpi + bpi ----
    gemm5<false, true><<<dim3(4, 16, 1), 256, GSMEM>>>(
        pxh, pxl, pwpih, bpi, ph, DMODEL, KPI, KPI,
        0, 0, 0, 0, 0, 0, 1);

    for (int l = 0; l < 2; l++) {
        if (l == 0)
            layernorm_hl_k<false><<<NTOK, 256>>>(ph, nullptr,
                ln_w, ln_b, phnh, phnl, nullptr);
        else
            layernorm_hl_k<true><<<NTOK, 256>>>(ph, pyt,
                ln_w + l*DMODEL, ln_b + l*DMODEL, phnh, phnl, nullptr);
        // in-proj: z = dir
        gemm5<false, false><<<dim3(17, 16, 2), 256, GSMEM>>>(
            phnh, phnl,
            pwinh + (long)l*2*DMODEL*DINPROJ,
            nullptr, pzx, DINPROJ, DMODEL, DMODEL,
            0, (long)DMODEL*DINPROJ, (long)NTOK*DINPROJ,
            0, 0, 0, 1);
        conv2_k<<<dim3(9, SEQ/64, 4), 128>>>(convw, convb, l);
        scanA_k<<<1024, 64>>>(Dp, dt_bias, A_log, l);
        scanB_k<<<64, 64>>>();
        scanC_k<<<1024, 64>>>(l);
        rms_hl_k<<<2*NTOK, 256>>>(normw, l);
        // out-proj split-K: z = dir*2 + khalf; K=512 per CTA, lda=DINNER
        gemm5<false, false><<<dim3(4, 16, 4), 256, GSMEM>>>(
            pyh, pyl,
            pwouth + (long)l*2*DINNER*DMODEL,
            nullptr, pyt, DMODEL, 512, DINNER,
            (long)NTOK*DINNER, (long)DINNER*DMODEL, 2L*NTOK*DMODEL,
            512, 512L*DMODEL, (long)NTOK*DMODEL, 2);
    }

    // final: LN(h + yt0..3) -> fp16 hi/lo + fp32 straight into out tail
    layernorm_hl_k<true><<<NTOK, 256>>>(ph, pyt,
        fn_w, fn_b, phfh, phfl, out + (long)NTOK*FEAT);
    gemm5<false, true><<<dim3(1, 16, 1), 256, GSMEM>>>(
        phfh, phfl, pwpoh, bpo, out, FEAT, DMODEL, DMODEL,
        0, 0, 0, 0, 0, 0, 1);
}

// round 14
// speedup vs baseline: 1.3743x; 1.0502x over previous
#include <cuda_runtime.h>
#include <cuda_fp16.h>
#include <math.h>
#include <stdint.h>

#define BATCH 2
#define SEQ 1024
#define FEAT 80
#define DMODEL 512
#define DSTATE 16
#define DCONV 7
#define HEADDIM 64
#define DINNER 1024
#define NHEADS 16
#define CONVDIM 1056
#define DINPROJ 2096
#define NTOK (BATCH*SEQ)
#define EPSF 1e-5f
#define KPI 128
#define CH 16            // scan chunks
#define CL 64            // steps per chunk

// ---------------- scratch ----------------
__device__ float g_h[NTOK*DMODEL];
__device__ float g_zx[2][NTOK*DINPROJ];
__device__ float g_xbc[2][NTOK*CONVDIM];
__device__ float g_y[2][NTOK*DINNER];
__device__ float g_ytmp[4][NTOK*DMODEL];    // [dir*2 + khalf]

__device__ float g_S[2*2*16*CH*64*16];
__device__ float g_Hc[2*2*16*CH*64*16];
__device__ float g_cA[2][NTOK*NHEADS];

__device__ __half g_hnh[NTOK*DMODEL],  g_hnl[NTOK*DMODEL];
__device__ __half g_xh[NTOK*KPI],      g_xl[NTOK*KPI];
__device__ __half g_yh[2][NTOK*DINNER],g_yl[2][NTOK*DINNER];
__device__ __half g_hfh[NTOK*DMODEL],  g_hfl[NTOK*DMODEL];

// weights: hi-only fp16, [K][N] layout, K padded where needed
__device__ __half g_winh[4L*DMODEL*DINPROJ];
__device__ __half g_wouth[4L*DINNER*DMODEL];
__device__ __half g_wpih[KPI*DMODEL];
__device__ __half g_wpoh[DMODEL*FEAT];

// ---------------- helpers ----------------
__device__ __forceinline__ void cvt_hl(float v, __half& h, __half& l) {
    h = __float2half_rn(v);
    l = __float2half_rn(v - __half2float(h));
}
__device__ __forceinline__ uint32_t smem_u32(const void* p) {
    uint32_t a;
    asm("{ .reg .u64 t; cvta.to.shared.u64 t, %1; cvt.u32.u64 %0, t; }" : "=r"(a) : "l"(p));
    return a;
}
__device__ __forceinline__ void cpa16(uint32_t dst, const void* src) {
    asm volatile("cp.async.cg.shared.global [%0], [%1], 16;" :: "r"(dst), "l"(src));
}
__device__ __forceinline__ void ldsm_x4(unsigned r[4], uint32_t addr) {
    asm volatile("ldmatrix.sync.aligned.m8n8.x4.shared.b16 {%0,%1,%2,%3}, [%4];"
        : "=r"(r[0]), "=r"(r[1]), "=r"(r[2]), "=r"(r[3]) : "r"(addr));
}
__device__ __forceinline__ void ldsm_x2t(unsigned r[2], uint32_t addr) {
    asm volatile("ldmatrix.sync.aligned.m8n8.x2.trans.shared.b16 {%0,%1}, [%2];"
        : "=r"(r[0]), "=r"(r[1]) : "r"(addr));
}
__device__ __forceinline__ void mma16816h(float d[4], const unsigned a[4], const unsigned b[2]) {
    asm volatile("mma.sync.aligned.m16n8k16.row.col.f32.f16.f16.f32 "
        "{%0,%1,%2,%3}, {%4,%5,%6,%7}, {%8,%9}, {%0,%1,%2,%3};"
        : "+f"(d[0]), "+f"(d[1]), "+f"(d[2]), "+f"(d[3])
        : "r"(a[0]), "r"(a[1]), "r"(a[2]), "r"(a[3]), "r"(b[0]), "r"(b[1]));
}

// ---------------- GEMM: BM=128, BN=128, BK=64, 256 thr, 2 CTAs/SM ----------
// C[M,N](+)= A[M,K]@B[K,N] (+bias), fp16 2-pass: A hi/lo, B hi only.
// 2-stage cp.async double-buffer, ONE __syncthreads per 64-K chunk.
// A row stride = lda (>= K, mult of 8); K mult of 64.
// z decomposes as zh = z/zdiv, zl = z%zdiv with separate stride pairs.
#define ASTR 144
#define BSTR 272
#define OFF_AL 18432
#define OFF_BH 36864
#define STAGE 54272
#define GSMEM (2*STAGE)

__device__ __forceinline__ void g5_stage(
    uint32_t sb, const __half* Ah, const __half* Al, const __half* Bh,
    int m0, int n0, int k0, int N, int lda, int tid)
{
    #pragma unroll
    for (int q = 0; q < 4; q++) {
        int idx = q * 256 + tid, row = idx >> 3, seg = idx & 7;
        uint32_t d = sb + row * ASTR + seg * 16;
        const __half* s = Ah + (size_t)(m0 + row) * lda + k0 + seg * 8;
        cpa16(d, s);
        cpa16(d + OFF_AL, Al + (s - Ah));
    }
    #pragma unroll
    for (int q = 0; q < 4; q++) {
        int idx = q * 256 + tid, row = idx >> 4, seg = idx & 15;
        uint32_t d = sb + OFF_BH + row * BSTR + seg * 16;
        if (n0 + seg * 8 < N) {
            cpa16(d, Bh + (size_t)(k0 + row) * N + n0 + seg * 8);
        } else {
            asm volatile("st.shared.v4.b32 [%0], {%1,%1,%1,%1};" :: "r"(d), "r"(0) : "memory");
        }
    }
    asm volatile("cp.async.commit_group;" ::: "memory");
}

template<bool ACCUM, bool BIAS>
__global__ void __launch_bounds__(256, 2) gemm5(
    const __half* __restrict__ Ah, const __half* __restrict__ Al,
    const __half* __restrict__ Bh,
    const float* __restrict__ bias, float* __restrict__ C,
    int N, int K, int lda,
    long azH, long bzH, long czH,
    long azL, long bzL, long czL, int zdiv)
{
    extern __shared__ char dsm[];
    const int zh = blockIdx.z / zdiv, zl = blockIdx.z % zdiv;
    Ah += (long)zh * azH + (long)zl * azL;
    Al += (long)zh * azH + (long)zl * azL;
    Bh += (long)zh * bzH + (long)zl * bzL;
    C  += (long)zh * czH + (long)zl * czL;
    const int m0 = blockIdx.y * 128, n0 = blockIdx.x * 128;
    const int tid = threadIdx.x, warp = tid >> 5, lane = tid & 31;
    const int wm = (warp & 1) * 64, wn = (warp >> 1) * 32;
    const uint32_t raw = smem_u32(dsm);

    float acc[4][4][4];
    #pragma unroll
    for (int f = 0; f < 4; f++)
        #pragma unroll
        for (int g = 0; g < 4; g++)
            #pragma unroll
            for (int i = 0; i < 4; i++) acc[f][g][i] = 0.f;

    const int nch = K >> 6;
    g5_stage(raw, Ah, Al, Bh, m0, n0, 0, N, lda, tid);

    for (int c = 0; c < nch; c++) {
        asm volatile("cp.async.wait_group 0;" ::: "memory");
        __syncthreads();
        if (c + 1 < nch)
            g5_stage(raw + (uint32_t)((c + 1) & 1) * STAGE,
                     Ah, Al, Bh, m0, n0, (c + 1) << 6, N, lda, tid);

        const uint32_t sb = raw + (uint32_t)(c & 1) * STAGE;
        #pragma unroll
        for (int ks = 0; ks < 4; ks++) {
            const int kk = ks * 16;
            unsigned ah[4][4], al[4][4], bh[4][2];
            #pragma unroll
            for (int f = 0; f < 4; f++) {
                int row = wm + f * 16 + (lane & 15);
                int col = kk + ((lane >> 4) << 3);
                uint32_t a = sb + row * ASTR + col * 2;
                ldsm_x4(ah[f], a);
                ldsm_x4(al[f], a + OFF_AL);
            }
            #pragma unroll
            for (int g = 0; g < 4; g++) {
                int row = kk + (lane & 15);
                int col = wn + g * 8;
                ldsm_x2t(bh[g], sb + OFF_BH + row * BSTR + col * 2);
            }
            #pragma unroll
            for (int f = 0; f < 4; f++)
                #pragma unroll
                for (int g = 0; g < 4; g++) {
                    mma16816h(acc[f][g], ah[f], bh[g]);
                    mma16816h(acc[f][g], al[f], bh[g]);
                }
        }
    }

    const int cr = lane >> 2, cc = (lane & 3) * 2;
    #pragma unroll
    for (int f = 0; f < 4; f++) {
        #pragma unroll
        for (int g = 0; g < 4; g++) {
            int mmb = m0 + wm + f * 16 + cr;
            int nn = n0 + wn + g * 8 + cc;
            #pragma unroll
            for (int half = 0; half < 2; half++) {
                int m = mmb + half * 8;
                #pragma unroll
                for (int j = 0; j < 2; j++) {
                    if (nn + j < N) {
                        float v = acc[f][g][half * 2 + j];
                        long o = (long)m * N + nn + j;
                        if (BIAS) v += bias[nn + j];
                        if (ACCUM) v += C[o];
                        C[o] = v;
                    }
                }
            }
        }
    }
}

// ---------------- mega convert: weights (hi) + x (hi/lo) -> fp16 -----------
#define SEG0 ((long)KPI*DMODEL)
#define SEG1 (SEG0 + 4L*DMODEL*DINPROJ)
#define SEG2 (SEG1 + 4L*DINNER*DMODEL)
#define SEG3 (SEG2 + (long)DMODEL*FEAT)
#define SEG4 (SEG3 + (long)NTOK*KPI)

__global__ void __launch_bounds__(256) cvt_all_k(
    const float* __restrict__ Wpi, const float* __restrict__ Win,
    const float* __restrict__ Wout, const float* __restrict__ Wpo,
    const float* __restrict__ x)
{
    long i = (long)blockIdx.x * 256 + threadIdx.x;
    if (i >= SEG4) return;
    if (i < SEG0) {                    // Wpi padded [KPI][DMODEL]
        long k = i / DMODEL, n = i - k * DMODEL;
        float v = (k < FEAT) ? Wpi[k * DMODEL + n] : 0.f;
        g_wpih[i] = __float2half_rn(v);
    } else if (i < SEG1) {             // Win flat
        long o = i - SEG0;
        g_winh[o] = __float2half_rn(Win[o]);
    } else if (i < SEG2) {             // Wout flat
        long o = i - SEG1;
        g_wouth[o] = __float2half_rn(Wout[o]);
    } else if (i < SEG3) {             // Wpo flat
        long o = i - SEG2;
        g_wpoh[o] = __float2half_rn(Wpo[o]);
    } else {                           // x padded [NTOK][KPI], hi/lo
        long o = i - SEG3;
        long r = o >> 7, c = o & (KPI - 1);
        float v = (c < FEAT) ? x[r * FEAT + c] : 0.f;
        __half h, l;
        cvt_hl(v, h, l);
        g_xh[o] = h; g_xl[o] = l;
    }
}

// ---------------- reductions ----------------
__device__ __forceinline__ float warpSum(float v) {
    #pragma unroll
    for (int o = 16; o; o >>= 1) v += __shfl_down_sync(0xffffffffu, v, o);
    return v;
}

// ---------------- layernorm (+optional 4-way residual add) -> fp16 hi/lo ---
// RES: x = h + yt[0..3]; writes summed value back to h (next residual).
template<bool RES>
__global__ void __launch_bounds__(256) layernorm_hl_k(
    float* __restrict__ hio, const float* __restrict__ ytbase,
    const float* __restrict__ w, const float* __restrict__ b,
    __half* __restrict__ oh, __half* __restrict__ ol,
    float* __restrict__ of)
{
    __shared__ float sbuf[8];
    int row = blockIdx.x, tid = threadIdx.x;
    long o0 = (long)row * DMODEL + tid, o1 = o0 + 256;
    float x0 = hio[o0], x1 = hio[o1];
    if (RES) {
        #pragma unroll
        for (int r = 0; r < 4; r++) {
            x0 += ytbase[(long)r * NTOK * DMODEL + o0];
            x1 += ytbase[(long)r * NTOK * DMODEL + o1];
        }
        hio[o0] = x0; hio[o1] = x1;
    }
    float s = warpSum(x0 + x1);
    if ((tid & 31) == 0) sbuf[tid >> 5] = s;
    __syncthreads();
    float mean = 0.f;
    #pragma unroll
    for (int i = 0; i < 8; i++) mean += sbuf[i];
    mean *= (1.f / DMODEL);
    __syncthreads();
    float c0 = x0 - mean, c1 = x1 - mean;
    float ss = warpSum(c0 * c0 + c1 * c1);
    if ((tid & 31) == 0) sbuf[tid >> 5] = ss;
    __syncthreads();
    float var = 0.f;
    #pragma unroll
    for (int i = 0; i < 8; i++) var += sbuf[i];
    var *= (1.f / DMODEL);
    float rs = rsqrtf(var + EPSF);
    float r0 = c0 * rs * w[tid] + b[tid];
    float r1 = c1 * rs * w[tid + 256] + b[tid + 256];
    __half h, l;
    cvt_hl(r0, h, l); oh[o0] = h; ol[o0] = l;
    cvt_hl(r1, h, l); oh[o1] = h; ol[o1] = l;
    if (of) { of[o0] = r0; of[o1] = r1; }
}

// ---------------- sliding-window causal conv + SiLU ----------------
__global__ void __launch_bounds__(128) conv2_k(
    const float* __restrict__ convw, const float* __restrict__ convb, int l)
{
    int c = blockIdx.x * 128 + threadIdx.x;
    bool act = (c < CONVDIM);
    int t0 = blockIdx.y * 64;
    int dir = blockIdx.z >> 1;
    int b = blockIdx.z & 1;
    float w[7], bias = 0.f;
    #pragma unroll
    for (int k = 0; k < 7; k++) w[k] = 0.f;
    if (act) {
        const float* wp = convw + ((long)((l * 2 + dir) * CONVDIM) + c) * DCONV;
        #pragma unroll
        for (int k = 0; k < 7; k++) w[k] = wp[k];
        bias = convb[(l * 2 + dir) * CONVDIM + c];
    }
    const float* in = g_zx[dir] + (long)b * SEQ * DINPROJ + DINNER + c;
    float* outp = g_xbc[dir] + (long)b * SEQ * CONVDIM + c;

    float win[7];
    if (dir == 0) {
        #pragma unroll
        for (int j = 1; j < 7; j++) {
            int t = t0 - j;
            win[j] = (act && t >= 0) ? in[(long)t * DINPROJ] : 0.f;
        }
        #pragma unroll 4
        for (int i = 0; i < 64; i++) {
            int o = t0 + i;
            win[0] = act ? in[(long)o * DINPROJ] : 0.f;
            float a = bias;
            #pragma unroll
            for (int j = 0; j < 7; j++) a += w[6 - j] * win[j];
            float sv = a / (1.f + expf(-a));
            if (act) outp[(long)o * CONVDIM] = sv;
            #pragma unroll
            for (int j = 6; j > 0; j--) win[j] = win[j - 1];
        }
    } else {
        #pragma unroll
        for (int j = 0; j < 6; j++) {
            int t = t0 + j;
            win[j] = (act && t < SEQ) ? in[(long)t * DINPROJ] : 0.f;
        }
        #pragma unroll 4
        for (int i = 0; i < 64; i++) {
            int o = t0 + i;
            int t = o + 6;
            win[6] = (act && t < SEQ) ? in[(long)t * DINPROJ] : 0.f;
            float a = bias;
            #pragma unroll
            for (int j = 0; j < 7; j++) a += w[6 - j] * win[j];
            float sv = a / (1.f + expf(-a));
            if (act) outp[(long)o * CONVDIM] = sv;
            #pragma unroll
            for (int j = 0; j < 6; j++) win[j] = win[j + 1];
        }
    }
}

// ---------------- scan phase A: chunk-local scan + inline dt/dA ------------
// grid: 1024 = dir*512 + b*256 + h*16 + chunk; 64 threads (p)
__global__ void __launch_bounds__(64) scanA_k(
    const float* __restrict__ Dp, const float* __restrict__ dt_bias,
    const float* __restrict__ A_log, int l)
{
    int bid = blockIdx.x;
    int chunk = bid & 15;
    int h = (bid >> 4) & 15;
    int b = (bid >> 8) & 1;
    int dir = bid >> 9;
    int p = threadIdx.x;
    const float* xbc = g_xbc[dir];
    const float* zx = g_zx[dir];
    float* yo = g_y[dir];
    float* cAo = g_cA[dir];
    const float Dv = Dp[(l * 2 + dir) * NHEADS + h];
    const float dtb = dt_bias[(l * 2 + dir) * NHEADS + h];
    const float Av = -expf(A_log[(l * 2 + dir) * NHEADS + h]);

    __shared__ float sdt64[64], sdA64[64];
    {
        int t = chunk * CL + p;
        int o = dir ? (SEQ - 1 - t) : t;
        float raw = zx[(long)(b * SEQ + o) * DINPROJ + DINNER + CONVDIM + h];
        float xv = raw + dtb;
        float dt = (xv > 20.f) ? xv : log1pf(expf(xv));
        sdt64[p] = dt;
        sdA64[p] = expf(dt * Av);
    }
    __syncthreads();

    float hs[16];
    #pragma unroll
    for (int n = 0; n < 16; n++) hs[n] = 0.f;
    float cumA = 1.f;
    __shared__ float sB[8][16], sC[8][16];

    for (int t8 = 0; t8 < CL; t8 += 8) {
        int tb = chunk * CL + t8;
        #pragma unroll
        for (int i = p; i < 128; i += 64) {
            int tt = i >> 4, n = i & 15;
            int o = dir ? (SEQ - 1 - (tb + tt)) : (tb + tt);
            long base = (long)(b * SEQ + o) * CONVDIM + DINNER;
            sB[tt][n] = xbc[base + n];
            sC[tt][n] = xbc[base + DSTATE + n];
        }
        __syncthreads();

        float xt[8];
        int oidx[8];
        #pragma unroll
        for (int j = 0; j < 8; j++) {
            int o = dir ? (SEQ - 1 - (tb + j)) : (tb + j);
            oidx[j] = o;
            xt[j] = xbc[(long)(b * SEQ + o) * CONVDIM + h * HEADDIM + p];
        }
        #pragma unroll
        for (int j = 0; j < 8; j++) {
            float dt = sdt64[t8 + j], dA = sdA64[t8 + j];
            float cdt = dt * xt[j];
            float y = 0.f;
            #pragma unroll
            for (int n = 0; n < 16; n++) {
                hs[n] = hs[n] * dA + cdt * sB[j][n];
                y += hs[n] * sC[j][n];
            }
            y += Dv * xt[j];
            yo[(long)(b * SEQ + oidx[j]) * DINNER + h * HEADDIM + p] = y;  // pre-gate
            cumA *= dA;
            if (p == 0) cAo[((long)(b * SEQ) + tb + j) * NHEADS + h] = cumA;
        }
        __syncthreads();
    }
    long sbase = ((((long)(dir * 2 + b) * 16 + h) * CH + chunk) * 64 + p) * 16;
    #pragma unroll
    for (int n = 0; n < 16; n++) g_S[sbase + n] = hs[n];
}

// ---------------- scan phase B: sequential chunk combine -------------------
__global__ void __launch_bounds__(64) scanB_k()
{
    int bid = blockIdx.x;
    int h = bid & 15;
    int b = (bid >> 4) & 1;
    int dir = bid >> 5;
    int p = threadIdx.x;
    const float* cAo = g_cA[dir];
    float H[16];
    #pragma unroll
    for (int n = 0; n < 16; n++) H[n] = 0.f;
    for (int c = 0; c < CH; c++) {
        long base = ((((long)(dir * 2 + b) * 16 + h) * CH + c) * 64 + p) * 16;
        #pragma unroll
        for (int n = 0; n < 16; n++) g_Hc[base + n] = H[n];
        float P = cAo[((long)(b * SEQ) + c * CL + CL - 1) * NHEADS + h];
        #pragma unroll
        for (int n = 0; n < 16; n++) H[n] = P * H[n] + g_S[base + n];
    }
}

// ---------------- scan phase C: fixup + gate ----------------
__global__ void __launch_bounds__(64) scanC_k(int l)
{
    int bid = blockIdx.x;
    int chunk = bid & 15;
    int h = (bid >> 4) & 15;
    int b = (bid >> 8) & 1;
    int dir = bid >> 9;
    int p = threadIdx.x;
    const float* xbc = g_xbc[dir];
    const float* zx = g_zx[dir];
    const float* cAo = g_cA[dir];
    float* yo = g_y[dir];
    float H[16];
    long hbase = ((((long)(dir * 2 + b) * 16 + h) * CH + chunk) * 64 + p) * 16;
    #pragma unroll
    for (int n = 0; n < 16; n++) H[n] = g_Hc[hbase + n];
    __shared__ float sC[8][16], scA[8];

    for (int t8 = 0; t8 < CL; t8 += 8) {
        int tb = chunk * CL + t8;
        #pragma unroll
        for (int i = p; i < 128; i += 64) {
            int tt = i >> 4, n = i & 15;
            int o = dir ? (SEQ - 1 - (tb + tt)) : (tb + tt);
            sC[tt][n] = xbc[(long)(b * SEQ + o) * CONVDIM + DINNER + DSTATE + n];
        }
        if (p < 8)
            scA[p] = cAo[((long)(b * SEQ) + tb + p) * NHEADS + h];
        __syncthreads();

        float yp[8], zt[8];
        int oidx[8];
        #pragma unroll
        for (int j = 0; j < 8; j++) {
            int o = dir ? (SEQ - 1 - (tb + j)) : (tb + j);
            oidx[j] = o;
            yp[j] = yo[(long)(b * SEQ + o) * DINNER + h * HEADDIM + p];
            zt[j] = zx[(long)(b * SEQ + o) * DINPROJ + h * HEADDIM + p];
        }
        #pragma unroll
        for (int j = 0; j < 8; j++) {
            float dot = 0.f;
            #pragma unroll
            for (int n = 0; n < 16; n++) dot += H[n] * sC[j][n];
            float y = yp[j] + scA[j] * dot;
            float z = zt[j];
            float sil = z / (1.f + expf(-z));
            yo[(long)(b * SEQ + oidx[j]) * DINNER + h * HEADDIM + p] = y * sil;
        }
        __syncthreads();
    }
}

// ---------------- RMS norm (1024) -> fp16 hi/lo (per dir) ------------------
__global__ void __launch_bounds__(256) rms_hl_k(const float* __restrict__ normw, int l)
{
    __shared__ float sbuf[8];
    int bid = blockIdx.x;
    int dir = bid >> 11;
    int tok = bid & (NTOK - 1);
    int tid = threadIdx.x;
    const float* v = g_y[dir] + (long)tok * DINNER;
    const float* w = normw + (l * 2 + dir) * DINNER;
    float vals[4];
    float ss = 0.f;
    #pragma unroll
    for (int i = 0; i < 4; i++) {
        vals[i] = v[tid + i * 256];
        ss += vals[i] * vals[i];
    }
    ss = warpSum(ss);
    if ((tid & 31) == 0) sbuf[tid >> 5] = ss;
    __syncthreads();
    float tot = 0.f;
    #pragma unroll
    for (int i = 0; i < 8; i++) tot += sbuf[i];
    float rs = rsqrtf(tot * (1.f / DINNER) + EPSF);
    #pragma unroll
    for (int i = 0; i < 4; i++) {
        float sv = vals[i] * rs * w[tid + i * 256];
        __half h, l2;
        cvt_hl(sv, h, l2);
        long o = (long)tok * DINNER + tid + i * 256;
        g_yh[dir][o] = h;
        g_yl[dir][o] = l2;
    }
}

// ---------------- launch ----------------
extern "C" void kernel_launch(void* const* d_in, const int* in_sizes, int n_in,
                              void* d_out, int out_size)
{
    const float* x      = (const float*)d_in[0];
    const float* Wpi    = (const float*)d_in[1];
    const float* bpi    = (const float*)d_in[2];
    const float* ln_w   = (const float*)d_in[3];
    const float* ln_b   = (const float*)d_in[4];
    const float* Win    = (const float*)d_in[5];
    const float* convw  = (const float*)d_in[6];
    const float* convb  = (const float*)d_in[7];
    const float* dt_bias= (const float*)d_in[8];
    const float* A_log  = (const float*)d_in[9];
    const float* Dp     = (const float*)d_in[10];
    const float* normw  = (const float*)d_in[11];
    const float* Wout   = (const float*)d_in[12];
    const float* fn_w   = (const float*)d_in[13];
    const float* fn_b   = (const float*)d_in[14];
    const float* Wpo    = (const float*)d_in[15];
    const float* bpo    = (const float*)d_in[16];
    float* out = (float*)d_out;

    cudaFuncSetAttribute(gemm5<false, true>,  cudaFuncAttributeMaxDynamicSharedMemorySize, GSMEM);
    cudaFuncSetAttribute(gemm5<false, false>, cudaFuncAttributeMaxDynamicSharedMemorySize, GSMEM);

    float *ph, *pzx, *pyt;
    __half *pxh, *pxl, *phnh, *phnl, *pyh, *pyl, *phfh, *phfl;
    __half *pwinh, *pwouth, *pwpih, *pwpoh;
    cudaGetSymbolAddress((void**)&ph,     g_h);
    cudaGetSymbolAddress((void**)&pzx,    g_zx);
    cudaGetSymbolAddress((void**)&pyt,    g_ytmp);
    cudaGetSymbolAddress((void**)&pxh,    g_xh);
    cudaGetSymbolAddress((void**)&pxl,    g_xl);
    cudaGetSymbolAddress((void**)&phnh,   g_hnh);
    cudaGetSymbolAddress((void**)&phnl,   g_hnl);
    cudaGetSymbolAddress((void**)&pyh,    g_yh);
    cudaGetSymbolAddress((void**)&pyl,    g_yl);
    cudaGetSymbolAddress((void**)&phfh,   g_hfh);
    cudaGetSymbolAddress((void**)&phfl,   g_hfl);
    cudaGetSymbolAddress((void**)&pwinh,  g_winh);
    cudaGetSymbolAddress((void**)&pwouth, g_wouth);
    cudaGetSymbolAddress((void**)&pwpih,  g_wpih);
    cudaGetSymbolAddress((void**)&pwpoh,  g_wpoh);

    // ---- one mega convert (weights hi + x hi/lo) ----
    cvt_all_k<<<(int)((SEG4 + 255) / 256), 256>>>(Wpi, Win, Wout, Wpo, x);

    // ---- input proj: h = x @ Wpi + bpi ----
    gemm5<false, true><<<dim3(4, 16, 1), 256, GSMEM>>>(
        pxh, pxl, pwpih, bpi, ph, DMODEL, KPI, KPI,
        0, 0, 0, 0, 0, 0, 1);

    for (int l = 0; l < 2; l++) {
        if (l == 0)
            layernorm_hl_k<false><<<NTOK, 256>>>(ph, nullptr,
                ln_w, ln_b, phnh, phnl, nullptr);
        else
            layernorm_hl_k<true><<<NTOK, 256>>>(ph, pyt,
                ln_w + l*DMODEL, ln_b + l*DMODEL, phnh, phnl, nullptr);
        // in-proj: z = dir
        gemm5<false, false><<<dim3(17, 16, 2), 256, GSMEM>>>(
            phnh, phnl,
            pwinh + (long)l*2*DMODEL*DINPROJ,
            nullptr, pzx, DINPROJ, DMODEL, DMODEL,
            0, (long)DMODEL*DINPROJ, (long)NTOK*DINPROJ,
            0, 0, 0, 1);
        conv2_k<<<dim3(9, SEQ/64, 4), 128>>>(convw, convb, l);
        scanA_k<<<1024, 64>>>(Dp, dt_bias, A_log, l);
        scanB_k<<<64, 64>>>();
        scanC_k<<<1024, 64>>>(l);
        rms_hl_k<<<2*NTOK, 256>>>(normw, l);
        // out-proj split-K: z = dir*2 + khalf; K=512 per CTA, lda=DINNER
        gemm5<false, false><<<dim3(4, 16, 4), 256, GSMEM>>>(
            pyh, pyl,
            pwouth + (long)l*2*DINNER*DMODEL,
            nullptr, pyt, DMODEL, 512, DINNER,
            (long)NTOK*DINNER, (long)DINNER*DMODEL, 2L*NTOK*DMODEL,
            512, 512L*DMODEL, (long)NTOK*DMODEL, 2);
    }

    // final: LN(h + yt0..3) -> fp16 hi/lo + fp32 straight into out tail
    layernorm_hl_k<true><<<NTOK, 256>>>(ph, pyt,
        fn_w, fn_b, phfh, phfl, out + (long)NTOK*FEAT);
    gemm5<false, true><<<dim3(1, 16, 1), 256, GSMEM>>>(
        phfh, phfl, pwpoh, bpo, out, FEAT, DMODEL, DMODEL,
        0, 0, 0, 0, 0, 0, 1);
}

// round 16
// speedup vs baseline: 1.3852x; 1.0079x over previous
#include <cuda_runtime.h>
#include <cuda_fp16.h>
#include <math.h>
#include <stdint.h>

#define BATCH 2
#define SEQ 1024
#define FEAT 80
#define DMODEL 512
#define DSTATE 16
#define DCONV 7
#define HEADDIM 64
#define DINNER 1024
#define NHEADS 16
#define CONVDIM 1056
#define DINPROJ 2096
#define NTOK (BATCH*SEQ)
#define EPSF 1e-5f
#define KPI 128
#define CH 16            // scan chunks
#define CL 64            // steps per chunk

// ---------------- scratch ----------------
__device__ float g_h[NTOK*DMODEL];
__device__ float g_zx[2][NTOK*DINPROJ];
__device__ float g_xbc[2][NTOK*CONVDIM];
__device__ float g_y[2][NTOK*DINNER];
__device__ float g_ytmp[4][NTOK*DMODEL];    // [dir*2 + khalf]

__device__ float g_S[2*2*16*CH*64*16];
__device__ float g_Hc[2*2*16*CH*64*16];
__device__ float g_cA[2][NTOK*NHEADS];

__device__ __half g_hnh[NTOK*DMODEL],  g_hnl[NTOK*DMODEL];
__device__ __half g_xh[NTOK*KPI],      g_xl[NTOK*KPI];
__device__ __half g_yh[2][NTOK*DINNER],g_yl[2][NTOK*DINNER];
__device__ __half g_hfh[NTOK*DMODEL],  g_hfl[NTOK*DMODEL];

// weights: hi-only fp16, [K][N] layout, K padded where needed
__device__ __half g_winh[4L*DMODEL*DINPROJ];
__device__ __half g_wouth[4L*DINNER*DMODEL];
__device__ __half g_wpih[KPI*DMODEL];
__device__ __half g_wpoh[DMODEL*FEAT];

// ---------------- helpers ----------------
__device__ __forceinline__ void cvt_hl(float v, __half& h, __half& l) {
    h = __float2half_rn(v);
    l = __float2half_rn(v - __half2float(h));
}
__device__ __forceinline__ uint32_t smem_u32(const void* p) {
    uint32_t a;
    asm("{ .reg .u64 t; cvta.to.shared.u64 t, %1; cvt.u32.u64 %0, t; }" : "=r"(a) : "l"(p));
    return a;
}
__device__ __forceinline__ void cpa16(uint32_t dst, const void* src) {
    asm volatile("cp.async.cg.shared.global [%0], [%1], 16;" :: "r"(dst), "l"(src));
}
__device__ __forceinline__ void ldsm_x4(unsigned r[4], uint32_t addr) {
    asm volatile("ldmatrix.sync.aligned.m8n8.x4.shared.b16 {%0,%1,%2,%3}, [%4];"
        : "=r"(r[0]), "=r"(r[1]), "=r"(r[2]), "=r"(r[3]) : "r"(addr));
}
__device__ __forceinline__ void ldsm_x4t(unsigned r[4], uint32_t addr) {
    asm volatile("ldmatrix.sync.aligned.m8n8.x4.trans.shared.b16 {%0,%1,%2,%3}, [%4];"
        : "=r"(r[0]), "=r"(r[1]), "=r"(r[2]), "=r"(r[3]) : "r"(addr));
}
__device__ __forceinline__ void mma16816h(float d[4], const unsigned a[4], const unsigned b[2]) {
    asm volatile("mma.sync.aligned.m16n8k16.row.col.f32.f16.f16.f32 "
        "{%0,%1,%2,%3}, {%4,%5,%6,%7}, {%8,%9}, {%0,%1,%2,%3};"
        : "+f"(d[0]), "+f"(d[1]), "+f"(d[2]), "+f"(d[3])
        : "r"(a[0]), "r"(a[1]), "r"(a[2]), "r"(a[3]), "r"(b[0]), "r"(b[1]));
}

// ---------------- GEMM: BM=128, BN=128, BK=64, 256 thr, 2 CTAs/SM ----------
// C[M,N](+)= A[M,K]@B[K,N] (+bias), fp16 2-pass: A hi/lo, B hi only.
// Warp grid 4(M) x 2(N): warp tile 32x64. A read by 2 col-groups (hi+lo),
// B by 4 row-groups -> 32KB/ks crossbar traffic (balanced vs MMA pipe).
// 2-stage cp.async double-buffer, ONE __syncthreads per 64-K chunk.
// A row stride = lda (>= K, mult of 8); K mult of 64.
// z decomposes as zh = z/zdiv, zl = z%zdiv with separate stride pairs.
#define ASTR 144
#define BSTR 272
#define OFF_AL 18432
#define OFF_BH 36864
#define STAGE 54272
#define GSMEM (2*STAGE)

__device__ __forceinline__ void g5_stage(
    uint32_t sb, const __half* Ah, const __half* Al, const __half* Bh,
    int m0, int n0, int k0, int N, int lda, int tid)
{
    #pragma unroll
    for (int q = 0; q < 4; q++) {
        int idx = q * 256 + tid, row = idx >> 3, seg = idx & 7;
        uint32_t d = sb + row * ASTR + seg * 16;
        const __half* s = Ah + (size_t)(m0 + row) * lda + k0 + seg * 8;
        cpa16(d, s);
        cpa16(d + OFF_AL, Al + (s - Ah));
    }
    #pragma unroll
    for (int q = 0; q < 4; q++) {
        int idx = q * 256 + tid, row = idx >> 4, seg = idx & 15;
        uint32_t d = sb + OFF_BH + row * BSTR + seg * 16;
        if (n0 + seg * 8 < N) {
            cpa16(d, Bh + (size_t)(k0 + row) * N + n0 + seg * 8);
        } else {
            asm volatile("st.shared.v4.b32 [%0], {%1,%1,%1,%1};" :: "r"(d), "r"(0) : "memory");
        }
    }
    asm volatile("cp.async.commit_group;" ::: "memory");
}

template<bool ACCUM, bool BIAS>
__global__ void __launch_bounds__(256, 2) gemm5(
    const __half* __restrict__ Ah, const __half* __restrict__ Al,
    const __half* __restrict__ Bh,
    const float* __restrict__ bias, float* __restrict__ C,
    int N, int K, int lda,
    long azH, long bzH, long czH,
    long azL, long bzL, long czL, int zdiv)
{
    extern __shared__ char dsm[];
    const int zh = blockIdx.z / zdiv, zl = blockIdx.z % zdiv;
    Ah += (long)zh * azH + (long)zl * azL;
    Al += (long)zh * azH + (long)zl * azL;
    Bh += (long)zh * bzH + (long)zl * bzL;
    C  += (long)zh * czH + (long)zl * czL;
    const int m0 = blockIdx.y * 128, n0 = blockIdx.x * 128;
    const int tid = threadIdx.x, warp = tid >> 5, lane = tid & 31;
    const int wm = (warp & 3) * 32, wn = (warp >> 2) * 64;
    const uint32_t raw = smem_u32(dsm);

    float acc[2][8][4];
    #pragma unroll
    for (int f = 0; f < 2; f++)
        #pragma unroll
        for (int g = 0; g < 8; g++)
            #pragma unroll
            for (int i = 0; i < 4; i++) acc[f][g][i] = 0.f;

    const int nch = K >> 6;
    g5_stage(raw, Ah, Al, Bh, m0, n0, 0, N, lda, tid);

    for (int c = 0; c < nch; c++) {
        asm volatile("cp.async.wait_group 0;" ::: "memory");
        __syncthreads();
        if (c + 1 < nch)
            g5_stage(raw + (uint32_t)((c + 1) & 1) * STAGE,
                     Ah, Al, Bh, m0, n0, (c + 1) << 6, N, lda, tid);

        const uint32_t sb = raw + (uint32_t)(c & 1) * STAGE;
        #pragma unroll
        for (int ks = 0; ks < 4; ks++) {
            const int kk = ks * 16;
            unsigned ah[2][4], al[2][4], bh[8][2];
            #pragma unroll
            for (int f = 0; f < 2; f++) {
                int row = wm + f * 16 + (lane & 15);
                int col = kk + ((lane >> 4) << 3);
                uint32_t a = sb + row * ASTR + col * 2;
                ldsm_x4(ah[f], a);
                ldsm_x4(al[f], a + OFF_AL);
            }
            #pragma unroll
            for (int gp = 0; gp < 4; gp++) {
                int row = kk + (lane & 15);
                int col = wn + gp * 16 + ((lane >> 4) << 3);
                unsigned t4[4];
                ldsm_x4t(t4, sb + OFF_BH + row * BSTR + col * 2);
                bh[gp * 2][0] = t4[0]; bh[gp * 2][1] = t4[1];
                bh[gp * 2 + 1][0] = t4[2]; bh[gp * 2 + 1][1] = t4[3];
            }
            #pragma unroll
            for (int f = 0; f < 2; f++)
                #pragma unroll
                for (int g = 0; g < 8; g++) {
                    mma16816h(acc[f][g], ah[f], bh[g]);
                    mma16816h(acc[f][g], al[f], bh[g]);
                }
        }
    }

    const int cr = lane >> 2, cc = (lane & 3) * 2;
    #pragma unroll
    for (int f = 0; f < 2; f++) {
        #pragma unroll
        for (int g = 0; g < 8; g++) {
            int mmb = m0 + wm + f * 16 + cr;
            int nn = n0 + wn + g * 8 + cc;
            #pragma unroll
            for (int half = 0; half < 2; half++) {
                int m = mmb + half * 8;
                #pragma unroll
                for (int j = 0; j < 2; j++) {
                    if (nn + j < N) {
                        float v = acc[f][g][half * 2 + j];
                        long o = (long)m * N + nn + j;
                        if (BIAS) v += bias[nn + j];
                        if (ACCUM) v += C[o];
                        C[o] = v;
                    }
                }
            }
        }
    }
}

// ---------------- mega convert: weights (hi) + x (hi/lo) -> fp16 -----------
#define SEG0 ((long)KPI*DMODEL)
#define SEG1 (SEG0 + 4L*DMODEL*DINPROJ)
#define SEG2 (SEG1 + 4L*DINNER*DMODEL)
#define SEG3 (SEG2 + (long)DMODEL*FEAT)
#define SEG4 (SEG3 + (long)NTOK*KPI)

__global__ void __launch_bounds__(256) cvt_all_k(
    const float* __restrict__ Wpi, const float* __restrict__ Win,
    const float* __restrict__ Wout, const float* __restrict__ Wpo,
    const float* __restrict__ x)
{
    long i = (long)blockIdx.x * 256 + threadIdx.x;
    if (i >= SEG4) return;
    if (i < SEG0) {                    // Wpi padded [KPI][DMODEL]
        long k = i / DMODEL, n = i - k * DMODEL;
        float v = (k < FEAT) ? Wpi[k * DMODEL + n] : 0.f;
        g_wpih[i] = __float2half_rn(v);
    } else if (i < SEG1) {             // Win flat
        long o = i - SEG0;
        g_winh[o] = __float2half_rn(Win[o]);
    } else if (i < SEG2) {             // Wout flat
        long o = i - SEG1;
        g_wouth[o] = __float2half_rn(Wout[o]);
    } else if (i < SEG3) {             // Wpo flat
        long o = i - SEG2;
        g_wpoh[o] = __float2half_rn(Wpo[o]);
    } else {                           // x padded [NTOK][KPI], hi/lo
        long o = i - SEG3;
        long r = o >> 7, c = o & (KPI - 1);
        float v = (c < FEAT) ? x[r * FEAT + c] : 0.f;
        __half h, l;
        cvt_hl(v, h, l);
        g_xh[o] = h; g_xl[o] = l;
    }
}

// ---------------- reductions ----------------
__device__ __forceinline__ float warpSum(float v) {
    #pragma unroll
    for (int o = 16; o; o >>= 1) v += __shfl_down_sync(0xffffffffu, v, o);
    return v;
}

// ---------------- layernorm (+optional 4-way residual add) -> fp16 hi/lo ---
// RES: x = h + yt[0..3]; writes summed value back to h (next residual).
template<bool RES>
__global__ void __launch_bounds__(256) layernorm_hl_k(
    float* __restrict__ hio, const float* __restrict__ ytbase,
    const float* __restrict__ w, const float* __restrict__ b,
    __half* __restrict__ oh, __half* __restrict__ ol,
    float* __restrict__ of)
{
    __shared__ float sbuf[8];
    int row = blockIdx.x, tid = threadIdx.x;
    long o0 = (long)row * DMODEL + tid, o1 = o0 + 256;
    float x0 = hio[o0], x1 = hio[o1];
    if (RES) {
        #pragma unroll
        for (int r = 0; r < 4; r++) {
            x0 += ytbase[(long)r * NTOK * DMODEL + o0];
            x1 += ytbase[(long)r * NTOK * DMODEL + o1];
        }
        hio[o0] = x0; hio[o1] = x1;
    }
    float s = warpSum(x0 + x1);
    if ((tid & 31) == 0) sbuf[tid >> 5] = s;
    __syncthreads();
    float mean = 0.f;
    #pragma unroll
    for (int i = 0; i < 8; i++) mean += sbuf[i];
    mean *= (1.f / DMODEL);
    __syncthreads();
    float c0 = x0 - mean, c1 = x1 - mean;
    float ss = warpSum(c0 * c0 + c1 * c1);
    if ((tid & 31) == 0) sbuf[tid >> 5] = ss;
    __syncthreads();
    float var = 0.f;
    #pragma unroll
    for (int i = 0; i < 8; i++) var += sbuf[i];
    var *= (1.f / DMODEL);
    float rs = rsqrtf(var + EPSF);
    float r0 = c0 * rs * w[tid] + b[tid];
    float r1 = c1 * rs * w[tid + 256] + b[tid + 256];
    __half h, l;
    cvt_hl(r0, h, l); oh[o0] = h; ol[o0] = l;
    cvt_hl(r1, h, l); oh[o1] = h; ol[o1] = l;
    if (of) { of[o0] = r0; of[o1] = r1; }
}

// ---------------- sliding-window causal conv + SiLU ----------------
__global__ void __launch_bounds__(128) conv2_k(
    const float* __restrict__ convw, const float* __restrict__ convb, int l)
{
    int c = blockIdx.x * 128 + threadIdx.x;
    bool act = (c < CONVDIM);
    int t0 = blockIdx.y * 64;
    int dir = blockIdx.z >> 1;
    int b = blockIdx.z & 1;
    float w[7], bias = 0.f;
    #pragma unroll
    for (int k = 0; k < 7; k++) w[k] = 0.f;
    if (act) {
        const float* wp = convw + ((long)((l * 2 + dir) * CONVDIM) + c) * DCONV;
        #pragma unroll
        for (int k = 0; k < 7; k++) w[k] = wp[k];
        bias = convb[(l * 2 + dir) * CONVDIM + c];
    }
    const float* in = g_zx[dir] + (long)b * SEQ * DINPROJ + DINNER + c;
    float* outp = g_xbc[dir] + (long)b * SEQ * CONVDIM + c;

    float win[7];
    if (dir == 0) {
        #pragma unroll
        for (int j = 1; j < 7; j++) {
            int t = t0 - j;
            win[j] = (act && t >= 0) ? in[(long)t * DINPROJ] : 0.f;
        }
        #pragma unroll 4
        for (int i = 0; i < 64; i++) {
            int o = t0 + i;
            win[0] = act ? in[(long)o * DINPROJ] : 0.f;
            float a = bias;
            #pragma unroll
            for (int j = 0; j < 7; j++) a += w[6 - j] * win[j];
            float sv = a / (1.f + expf(-a));
            if (act) outp[(long)o * CONVDIM] = sv;
            #pragma unroll
            for (int j = 6; j > 0; j--) win[j] = win[j - 1];
        }
    } else {
        #pragma unroll
        for (int j = 0; j < 6; j++) {
            int t = t0 + j;
            win[j] = (act && t < SEQ) ? in[(long)t * DINPROJ] : 0.f;
        }
        #pragma unroll 4
        for (int i = 0; i < 64; i++) {
            int o = t0 + i;
            int t = o + 6;
            win[6] = (act && t < SEQ) ? in[(long)t * DINPROJ] : 0.f;
            float a = bias;
            #pragma unroll
            for (int j = 0; j < 7; j++) a += w[6 - j] * win[j];
            float sv = a / (1.f + expf(-a));
            if (act) outp[(long)o * CONVDIM] = sv;
            #pragma unroll
            for (int j = 0; j < 6; j++) win[j] = win[j + 1];
        }
    }
}

// ---------------- scan phase A: chunk-local scan + inline dt/dA ------------
// grid: 1024 = dir*512 + b*256 + h*16 + chunk; 64 threads (p)
__global__ void __launch_bounds__(64) scanA_k(
    const float* __restrict__ Dp, const float* __restrict__ dt_bias,
    const float* __restrict__ A_log, int l)
{
    int bid = blockIdx.x;
    int chunk = bid & 15;
    int h = (bid >> 4) & 15;
    int b = (bid >> 8) & 1;
    int dir = bid >> 9;
    int p = threadIdx.x;
    const float* xbc = g_xbc[dir];
    const float* zx = g_zx[dir];
    float* yo = g_y[dir];
    float* cAo = g_cA[dir];
    const float Dv = Dp[(l * 2 + dir) * NHEADS + h];
    const float dtb = dt_bias[(l * 2 + dir) * NHEADS + h];
    const float Av = -expf(A_log[(l * 2 + dir) * NHEADS + h]);

    __shared__ float sdt64[64], sdA64[64];
    {
        int t = chunk * CL + p;
        int o = dir ? (SEQ - 1 - t) : t;
        float raw = zx[(long)(b * SEQ + o) * DINPROJ + DINNER + CONVDIM + h];
        float xv = raw + dtb;
        float dt = (xv > 20.f) ? xv : log1pf(expf(xv));
        sdt64[p] = dt;
        sdA64[p] = expf(dt * Av);
    }
    __syncthreads();

    float hs[16];
    #pragma unroll
    for (int n = 0; n < 16; n++) hs[n] = 0.f;
    float cumA = 1.f;
    __shared__ float sB[8][16], sC[8][16];

    for (int t8 = 0; t8 < CL; t8 += 8) {
        int tb = chunk * CL + t8;
        #pragma unroll
        for (int i = p; i < 128; i += 64) {
            int tt = i >> 4, n = i & 15;
            int o = dir ? (SEQ - 1 - (tb + tt)) : (tb + tt);
            long base = (long)(b * SEQ + o) * CONVDIM + DINNER;
            sB[tt][n] = xbc[base + n];
            sC[tt][n] = xbc[base + DSTATE + n];
        }
        __syncthreads();

        float xt[8];
        int oidx[8];
        #pragma unroll
        for (int j = 0; j < 8; j++) {
            int o = dir ? (SEQ - 1 - (tb + j)) : (tb + j);
            oidx[j] = o;
            xt[j] = xbc[(long)(b * SEQ + o) * CONVDIM + h * HEADDIM + p];
        }
        #pragma unroll
        for (int j = 0; j < 8; j++) {
            float dt = sdt64[t8 + j], dA = sdA64[t8 + j];
            float cdt = dt * xt[j];
            float y = 0.f;
            #pragma unroll
            for (int n = 0; n < 16; n++) {
                hs[n] = hs[n] * dA + cdt * sB[j][n];
                y += hs[n] * sC[j][n];
            }
            y += Dv * xt[j];
            yo[(long)(b * SEQ + oidx[j]) * DINNER + h * HEADDIM + p] = y;  // pre-gate
            cumA *= dA;
            if (p == 0) cAo[((long)(b * SEQ) + tb + j) * NHEADS + h] = cumA;
        }
        __syncthreads();
    }
    long sbase = ((((long)(dir * 2 + b) * 16 + h) * CH + chunk) * 64 + p) * 16;
    #pragma unroll
    for (int n = 0; n < 16; n++) g_S[sbase + n] = hs[n];
}

// ---------------- scan phase B: sequential chunk combine -------------------
__global__ void __launch_bounds__(64) scanB_k()
{
    int bid = blockIdx.x;
    int h = bid & 15;
    int b = (bid >> 4) & 1;
    int dir = bid >> 5;
    int p = threadIdx.x;
    const float* cAo = g_cA[dir];
    float H[16];
    #pragma unroll
    for (int n = 0; n < 16; n++) H[n] = 0.f;
    for (int c = 0; c < CH; c++) {
        long base = ((((long)(dir * 2 + b) * 16 + h) * CH + c) * 64 + p) * 16;
        #pragma unroll
        for (int n = 0; n < 16; n++) g_Hc[base + n] = H[n];
        float P = cAo[((long)(b * SEQ) + c * CL + CL - 1) * NHEADS + h];
        #pragma unroll
        for (int n = 0; n < 16; n++) H[n] = P * H[n] + g_S[base + n];
    }
}

// ---------------- scan phase C: fixup + gate ----------------
__global__ void __launch_bounds__(64) scanC_k(int l)
{
    int bid = blockIdx.x;
    int chunk = bid & 15;
    int h = (bid >> 4) & 15;
    int b = (bid >> 8) & 1;
    int dir = bid >> 9;
    int p = threadIdx.x;
    const float* xbc = g_xbc[dir];
    const float* zx = g_zx[dir];
    const float* cAo = g_cA[dir];
    float* yo = g_y[dir];
    float H[16];
    long hbase = ((((long)(dir * 2 + b) * 16 + h) * CH + chunk) * 64 + p) * 16;
    #pragma unroll
    for (int n = 0; n < 16; n++) H[n] = g_Hc[hbase + n];
    __shared__ float sC[8][16], scA[8];

    for (int t8 = 0; t8 < CL; t8 += 8) {
        int tb = chunk * CL + t8;
        #pragma unroll
        for (int i = p; i < 128; i += 64) {
            int tt = i >> 4, n = i & 15;
            int o = dir ? (SEQ - 1 - (tb + tt)) : (tb + tt);
            sC[tt][n] = xbc[(long)(b * SEQ + o) * CONVDIM + DINNER + DSTATE + n];
        }
        if (p < 8)
            scA[p] = cAo[((long)(b * SEQ) + tb + p) * NHEADS + h];
        __syncthreads();

        float yp[8], zt[8];
        int oidx[8];
        #pragma unroll
        for (int j = 0; j < 8; j++) {
            int o = dir ? (SEQ - 1 - (tb + j)) : (tb + j);
            oidx[j] = o;
            yp[j] = yo[(long)(b * SEQ + o) * DINNER + h * HEADDIM + p];
            zt[j] = zx[(long)(b * SEQ + o) * DINPROJ + h * HEADDIM + p];
        }
        #pragma unroll
        for (int j = 0; j < 8; j++) {
            float dot = 0.f;
            #pragma unroll
            for (int n = 0; n < 16; n++) dot += H[n] * sC[j][n];
            float y = yp[j] + scA[j] * dot;
            float z = zt[j];
            float sil = z / (1.f + expf(-z));
            yo[(long)(b * SEQ + oidx[j]) * DINNER + h * HEADDIM + p] = y * sil;
        }
        __syncthreads();
    }
}

// ---------------- RMS norm (1024) -> fp16 hi/lo (per dir) ------------------
__global__ void __launch_bounds__(256) rms_hl_k(const float* __restrict__ normw, int l)
{
    __shared__ float sbuf[8];
    int bid = blockIdx.x;
    int dir = bid >> 11;
    int tok = bid & (NTOK - 1);
    int tid = threadIdx.x;
    const float* v = g_y[dir] + (long)tok * DINNER;
    const float* w = normw + (l * 2 + dir) * DINNER;
    float vals[4];
    float ss = 0.f;
    #pragma unroll
    for (int i = 0; i < 4; i++) {
        vals[i] = v[tid + i * 256];
        ss += vals[i] * vals[i];
    }
    ss = warpSum(ss);
    if ((tid & 31) == 0) sbuf[tid >> 5] = ss;
    __syncthreads();
    float tot = 0.f;
    #pragma unroll
    for (int i = 0; i < 8; i++) tot += sbuf[i];
    float rs = rsqrtf(tot * (1.f / DINNER) + EPSF);
    #pragma unroll
    for (int i = 0; i < 4; i++) {
        float sv = vals[i] * rs * w[tid + i * 256];
        __half h, l2;
        cvt_hl(sv, h, l2);
        long o = (long)tok * DINNER + tid + i * 256;
        g_yh[dir][o] = h;
        g_yl[dir][o] = l2;
    }
}

// ---------------- launch ----------------
extern "C" void kernel_launch(void* const* d_in, const int* in_sizes, int n_in,
                              void* d_out, int out_size)
{
    const float* x      = (const float*)d_in[0];
    const float* Wpi    = (const float*)d_in[1];
    const float* bpi    = (const float*)d_in[2];
    const float* ln_w   = (const float*)d_in[3];
    const float* ln_b   = (const float*)d_in[4];
    const float* Win    = (const float*)d_in[5];
    const float* convw  = (const float*)d_in[6];
    const float* convb  = (const float*)d_in[7];
    const float* dt_bias= (const float*)d_in[8];
    const float* A_log  = (const float*)d_in[9];
    const float* Dp     = (const float*)d_in[10];
    const float* normw  = (const float*)d_in[11];
    const float* Wout   = (const float*)d_in[12];
    const float* fn_w   = (const float*)d_in[13];
    const float* fn_b   = (const float*)d_in[14];
    const float* Wpo    = (const float*)d_in[15];
    const float* bpo    = (const float*)d_in[16];
    float* out = (float*)d_out;

    cudaFuncSetAttribute(gemm5<false, true>,  cudaFuncAttributeMaxDynamicSharedMemorySize, GSMEM);
    cudaFuncSetAttribute(gemm5<false, false>, cudaFuncAttributeMaxDynamicSharedMemorySize, GSMEM);

    float *ph, *pzx, *pyt;
    __half *pxh, *pxl, *phnh, *phnl, *pyh, *pyl, *phfh, *phfl;
    __half *pwinh, *pwouth, *pwpih, *pwpoh;
    cudaGetSymbolAddress((void**)&ph,     g_h);
    cudaGetSymbolAddress((void**)&pzx,    g_zx);
    cudaGetSymbolAddress((void**)&pyt,    g_ytmp);
    cudaGetSymbolAddress((void**)&pxh,    g_xh);
    cudaGetSymbolAddress((void**)&pxl,    g_xl);
    cudaGetSymbolAddress((void**)&phnh,   g_hnh);
    cudaGetSymbolAddress((void**)&phnl,   g_hnl);
    cudaGetSymbolAddress((void**)&pyh,    g_yh);
    cudaGetSymbolAddress((void**)&pyl,    g_yl);
    cudaGetSymbolAddress((void**)&phfh,   g_hfh);
    cudaGetSymbolAddress((void**)&phfl,   g_hfl);
    cudaGetSymbolAddress((void**)&pwinh,  g_winh);
    cudaGetSymbolAddress((void**)&pwouth, g_wouth);
    cudaGetSymbolAddress((void**)&pwpih,  g_wpih);
    cudaGetSymbolAddress((void**)&pwpoh,  g_wpoh);

    // ---- one mega convert (weights hi + x hi/lo) ----
    cvt_all_k<<<(int)((SEG4 + 255) / 256), 256>>>(Wpi, Win, Wout, Wpo, x);

    // ---- input proj: h = x @ Wpi + bpi ----
    gemm5<false, true><<<dim3(4, 16, 1), 256, GSMEM>>>(
        pxh, pxl, pwpih, bpi, ph, DMODEL, KPI, KPI,
        0, 0, 0, 0, 0, 0, 1);

    for (int l = 0; l < 2; l++) {
        if (l == 0)
            layernorm_hl_k<false><<<NTOK, 256>>>(ph, nullptr,
                ln_w, ln_b, phnh, phnl, nullptr);
        else
            layernorm_hl_k<true><<<NTOK, 256>>>(ph, pyt,
                ln_w + l*DMODEL, ln_b + l*DMODEL, phnh, phnl, nullptr);
        // in-proj: z = dir
        gemm5<false, false><<<dim3(17, 16, 2), 256, GSMEM>>>(
            phnh, phnl,
            pwinh + (long)l*2*DMODEL*DINPROJ,
            nullptr, pzx, DINPROJ, DMODEL, DMODEL,
            0, (long)DMODEL*DINPROJ, (long)NTOK*DINPROJ,
            0, 0, 0, 1);
        conv2_k<<<dim3(9, SEQ/64, 4), 128>>>(convw, convb, l);
        scanA_k<<<1024, 64>>>(Dp, dt_bias, A_log, l);
        scanB_k<<<64, 64>>>();
        scanC_k<<<1024, 64>>>(l);
        rms_hl_k<<<2*NTOK, 256>>>(normw, l);
        // out-proj split-K: z = dir*2 + khalf; K=512 per CTA, lda=DINNER
        gemm5<false, false><<<dim3(4, 16, 4), 256, GSMEM>>>(
            pyh, pyl,
            pwouth + (long)l*2*DINNER*DMODEL,
            nullptr, pyt, DMODEL, 512, DINNER,
            (long)NTOK*DINNER, (long)DINNER*DMODEL, 2L*NTOK*DMODEL,
            512, 512L*DMODEL, (long)NTOK*DMODEL, 2);
    }

    // final: LN(h + yt0..3) -> fp16 hi/lo + fp32 straight into out tail
    layernorm_hl_k<true><<<NTOK, 256>>>(ph, pyt,
        fn_w, fn_b, phfh, phfl, out + (long)NTOK*FEAT);
    gemm5<false, true><<<dim3(1, 16, 1), 256, GSMEM>>>(
        phfh, phfl, pwpoh, bpo, out, FEAT, DMODEL, DMODEL,
        0, 0, 0, 0, 0, 0, 1);
}